// round 2
// baseline (speedup 1.0000x reference)
#include <cuda_runtime.h>

#define BZ 64
#define LZ 1024
#define DZ 64
#define C7 7
#define HZ 8
#define EZ 8
#define MZ 64
#define M2 128
#define DFFD 256
#define NROW (BZ*LZ)
#define NHE  (BZ*DZ)

__device__ float g_x[BZ*LZ*C7];
__device__ float g_seas0[BZ*LZ*C7];
__device__ float g_trend0[BZ*LZ*C7];
__device__ float g_mean7[BZ*C7];
__device__ float g_trendbase[BZ*LZ];
__device__ float g_seasinit[BZ*LZ*C7];
__device__ float g_h[NROW*DZ];
__device__ float g_q[NROW*DZ];
__device__ float g_qT[NROW*DZ];
__device__ float g_y[NROW*DZ];
__device__ float g_a[NROW*DZ];
__device__ float g_ffn[NROW*DFFD];
__device__ float g_Xf[NHE*M2];
__device__ float g_Xk[NHE*M2];
__device__ float g_sel[NHE*M2];
__device__ float g_qk[BZ*HZ*MZ*MZ*2];
__device__ float g_xd[NROW*DZ];
__device__ float g_tacc[NROW*DZ];
__device__ float g_cm[BZ*DZ];
__device__ float g_ln[NROW*DZ];
__device__ float g_F[M2*LZ];
__device__ float g_Fi[LZ*M2];

__global__ void build_tables_kernel() {
    int idx = blockIdx.x * blockDim.x + threadIdx.x;
    if (idx >= LZ * M2) return;
    int t = idx >> 7;
    int m2 = idx & 127;
    int m = m2 >> 1;
    int r = (m * t) & (LZ - 1);
    float a = (float)r * (6.28318530717958647692f / (float)LZ);
    float s, c;
    sincosf(a, &s, &c);
    float v = (m2 & 1) ? -s : c;
    g_F[(size_t)m2 * LZ + t] = v;
    float cm = (m == 0) ? 1.f : 2.f;
    g_Fi[(size_t)t * M2 + m2] = v * (cm / (float)LZ);
}

__global__ void transpose_in_kernel(const float* __restrict__ xe) {
    int idx = blockIdx.x * blockDim.x + threadIdx.x;
    if (idx >= BZ * C7 * LZ) return;
    int t = idx & 1023;
    int c = (idx >> 10) % C7;
    int b = idx / (C7 * LZ);
    g_x[((size_t)(b * LZ + t)) * C7 + c] = xe[idx];
}

__global__ void colmean7_kernel(const float* __restrict__ xe) {
    __shared__ float r[256];
    int bc = blockIdx.x;
    float s = 0.f;
    for (int t = threadIdx.x; t < LZ; t += 256) s += xe[(size_t)bc * LZ + t];
    r[threadIdx.x] = s;
    __syncthreads();
    for (int o = 128; o > 0; o >>= 1) {
        if (threadIdx.x < o) r[threadIdx.x] += r[threadIdx.x + o];
        __syncthreads();
    }
    if (threadIdx.x == 0) g_mean7[bc] = r[0] * (1.f / LZ);
}

__global__ void decomp7_kernel(const float* __restrict__ A,
                               const float* __restrict__ w4, const float* __restrict__ b4,
                               float* __restrict__ seas, float* __restrict__ trend) {
    __shared__ float xs[LZ];
    __shared__ float ps[LZ];
    int c = blockIdx.x % C7, b = blockIdx.x / C7;
    int t = threadIdx.x;
    size_t idx = ((size_t)(b * LZ + t)) * C7 + c;
    float x = A[idx];
    xs[t] = x; ps[t] = x;
    __syncthreads();
    for (int off = 1; off < LZ; off <<= 1) {
        float v = ps[t];
        if (t >= off) v += ps[t - off];
        __syncthreads();
        ps[t] = v;
        __syncthreads();
    }
    float x0 = xs[0], xN = xs[LZ - 1];
    const int ks[4] = {10, 50, 100, 500};
    float ma[4];
#pragma unroll
    for (int kk = 0; kk < 4; kk++) {
        int k = ks[kk], f = (k - 1) >> 1, e = k >> 1;
        int lo = t - f, hi = t + e;
        int cl = lo < 0 ? 0 : lo, ch = hi > LZ - 1 ? LZ - 1 : hi;
        float s = ps[ch] - (cl > 0 ? ps[cl - 1] : 0.f)
                + (float)(cl - lo) * x0 + (float)(hi - ch) * xN;
        ma[kk] = s / (float)k;
    }
    float z[4], mx = -1e30f;
#pragma unroll
    for (int kk = 0; kk < 4; kk++) { z[kk] = x * w4[kk] + b4[kk]; mx = fmaxf(mx, z[kk]); }
    float se = 0.f, mean = 0.f;
#pragma unroll
    for (int kk = 0; kk < 4; kk++) { float e2 = expf(z[kk] - mx); se += e2; mean += ma[kk] * e2; }
    mean /= se;
    seas[idx] = x - mean;
    trend[idx] = mean;
}

__global__ void decomp64_kernel(const float* __restrict__ A, const float* __restrict__ Bb,
                                const float* __restrict__ w4, const float* __restrict__ b4,
                                float* __restrict__ seas, float* __restrict__ trend, int accum) {
    __shared__ float4 xs[LZ];
    __shared__ float4 ps[LZ];
    int c4 = blockIdx.x & 15, b = blockIdx.x >> 4;
    int t = threadIdx.x;
    size_t base = ((size_t)(b * LZ + t)) * DZ + c4 * 4;
    float4 x = *reinterpret_cast<const float4*>(A + base);
    if (Bb) {
        float4 y = *reinterpret_cast<const float4*>(Bb + base);
        x.x += y.x; x.y += y.y; x.z += y.z; x.w += y.w;
    }
    xs[t] = x; ps[t] = x;
    __syncthreads();
    for (int off = 1; off < LZ; off <<= 1) {
        float4 v = ps[t];
        if (t >= off) {
            float4 u = ps[t - off];
            v.x += u.x; v.y += u.y; v.z += u.z; v.w += u.w;
        }
        __syncthreads();
        ps[t] = v;
        __syncthreads();
    }
    float4 x0 = xs[0], xN = xs[LZ - 1];
    const int ks[4] = {10, 50, 100, 500};
    float ma[4][4];
#pragma unroll
    for (int kk = 0; kk < 4; kk++) {
        int k = ks[kk], f = (k - 1) >> 1, e = k >> 1;
        int lo = t - f, hi = t + e;
        int cl = lo < 0 ? 0 : lo, ch = hi > LZ - 1 ? LZ - 1 : hi;
        float4 pc = ps[ch];
        float4 pl = make_float4(0.f, 0.f, 0.f, 0.f);
        if (cl > 0) pl = ps[cl - 1];
        float fl = (float)(cl - lo), fr = (float)(hi - ch);
        float inv = 1.f / (float)k;
        ma[kk][0] = (pc.x - pl.x + fl * x0.x + fr * xN.x) * inv;
        ma[kk][1] = (pc.y - pl.y + fl * x0.y + fr * xN.y) * inv;
        ma[kk][2] = (pc.z - pl.z + fl * x0.z + fr * xN.z) * inv;
        ma[kk][3] = (pc.w - pl.w + fl * x0.w + fr * xN.w) * inv;
    }
    float xa[4] = {x.x, x.y, x.z, x.w};
    float so[4], tr[4];
#pragma unroll
    for (int cc = 0; cc < 4; cc++) {
        float z[4], mx = -1e30f;
#pragma unroll
        for (int kk = 0; kk < 4; kk++) { z[kk] = xa[cc] * w4[kk] + b4[kk]; mx = fmaxf(mx, z[kk]); }
        float se = 0.f, mean = 0.f;
#pragma unroll
        for (int kk = 0; kk < 4; kk++) { float e2 = expf(z[kk] - mx); se += e2; mean += ma[kk][cc] * e2; }
        mean /= se;
        so[cc] = xa[cc] - mean;
        tr[cc] = mean;
    }
    *reinterpret_cast<float4*>(seas + base) = make_float4(so[0], so[1], so[2], so[3]);
    if (trend) {
        float4 tv = make_float4(tr[0], tr[1], tr[2], tr[3]);
        if (accum) {
            float4 old = *reinterpret_cast<float4*>(trend + base);
            tv.x += old.x; tv.y += old.y; tv.z += old.z; tv.w += old.w;
        }
        *reinterpret_cast<float4*>(trend + base) = tv;
    }
}

__global__ void trendbase_kernel(const float* __restrict__ dpw, const float* __restrict__ dpb) {
    int idx = blockIdx.x * blockDim.x + threadIdx.x;
    if (idx >= BZ * LZ) return;
    int t = idx & 1023, b = idx >> 10;
    float s = dpb[0];
#pragma unroll
    for (int c = 0; c < C7; c++) {
        float v = (t < 512) ? g_trend0[((size_t)(b * LZ + 512 + t)) * C7 + c]
                            : g_mean7[b * C7 + c];
        s += v * dpw[c];
    }
    g_trendbase[idx] = s;
}

__global__ void seasinit_kernel() {
    int idx = blockIdx.x * blockDim.x + threadIdx.x;
    if (idx >= BZ * LZ * C7) return;
    int c = idx % C7;
    int t = (idx / C7) & 1023;
    int b = idx / (C7 * LZ);
    g_seasinit[idx] = (t < 512) ? g_seas0[((size_t)(b * LZ + 512 + t)) * C7 + c] : 0.f;
}

__global__ void embed_kernel(const float* __restrict__ in, const float* __restrict__ w,
                             float* __restrict__ out) {
    int idx = blockIdx.x * blockDim.x + threadIdx.x;
    if (idx >= BZ * LZ * DZ) return;
    int o = idx & 63;
    int t = (idx >> 6) & 1023;
    int b = idx >> 16;
    float s = 0.f;
#pragma unroll
    for (int j = 0; j < 3; j++) {
        int ts = (t + j - 1 + LZ) & (LZ - 1);
        const float* ip = in + ((size_t)(b * LZ + ts)) * C7;
#pragma unroll
        for (int c = 0; c < C7; c++) s += ip[c] * w[(o * C7 + c) * 3 + j];
    }
    int i2 = o & ~1;
    float div = expf(-(float)i2 * 0.14391156831212793f);
    float arg = (float)t * div;
    float pe = (o & 1) ? cosf(arg) : sinf(arg);
    out[idx] = s + pe;
}

template <int ACT>
__global__ void gemm_kernel(const float* __restrict__ A, const float* __restrict__ W,
                            const float* __restrict__ bias, float* __restrict__ C,
                            int N, int K, int O) {
    __shared__ float As[16][65];
    __shared__ float Ws[16][65];
    const int rb = blockIdx.x * 64;
    const int cb = blockIdx.y * 64;
    const int tid = threadIdx.x;
    const int tx = tid & 15, ty = tid >> 4;
    const int lk = tid & 15, lr = tid >> 4;
    float acc[4][4];
#pragma unroll
    for (int i = 0; i < 4; i++)
#pragma unroll
        for (int j = 0; j < 4; j++) acc[i][j] = 0.f;
    for (int k0 = 0; k0 < K; k0 += 16) {
#pragma unroll
        for (int r = 0; r < 4; r++) {
            As[lk][lr + 16 * r] = A[(size_t)(rb + lr + 16 * r) * K + k0 + lk];
            Ws[lk][lr + 16 * r] = W[(size_t)(cb + lr + 16 * r) * K + k0 + lk];
        }
        __syncthreads();
#pragma unroll
        for (int k = 0; k < 16; k++) {
            float a0 = As[k][ty * 4 + 0], a1 = As[k][ty * 4 + 1];
            float a2 = As[k][ty * 4 + 2], a3 = As[k][ty * 4 + 3];
            float b0 = Ws[k][tx * 4 + 0], b1 = Ws[k][tx * 4 + 1];
            float b2 = Ws[k][tx * 4 + 2], b3 = Ws[k][tx * 4 + 3];
            acc[0][0] += a0 * b0; acc[0][1] += a0 * b1; acc[0][2] += a0 * b2; acc[0][3] += a0 * b3;
            acc[1][0] += a1 * b0; acc[1][1] += a1 * b1; acc[1][2] += a1 * b2; acc[1][3] += a1 * b3;
            acc[2][0] += a2 * b0; acc[2][1] += a2 * b1; acc[2][2] += a2 * b2; acc[2][3] += a2 * b3;
            acc[3][0] += a3 * b0; acc[3][1] += a3 * b1; acc[3][2] += a3 * b2; acc[3][3] += a3 * b3;
        }
        __syncthreads();
    }
#pragma unroll
    for (int i = 0; i < 4; i++) {
        int row = rb + ty * 4 + i;
#pragma unroll
        for (int j = 0; j < 4; j++) {
            int col = cb + tx * 4 + j;
            float v = acc[i][j];
            if (bias) v += bias[col];
            if (ACT == 1) v = 0.5f * v * (1.f + erff(v * 0.70710678118654752f));
            C[(size_t)row * O + col] = v;
        }
    }
}

__global__ void transpose_bld_kernel(const float* __restrict__ in, float* __restrict__ out) {
    __shared__ float tile[32][33];
    int b = blockIdx.z;
    int t0 = blockIdx.x * 32;
    int d0 = blockIdx.y * 32;
    int tx = threadIdx.x, ty = threadIdx.y;
#pragma unroll
    for (int i = 0; i < 32; i += 8)
        tile[ty + i][tx] = in[((size_t)b * LZ + t0 + ty + i) * DZ + d0 + tx];
    __syncthreads();
#pragma unroll
    for (int i = 0; i < 32; i += 8)
        out[((size_t)b * DZ + d0 + ty + i) * LZ + t0 + tx] = tile[tx][ty + i];
}

__global__ void mode_mix_kernel(const float* __restrict__ X, const float* __restrict__ wr,
                                const float* __restrict__ wi, float* __restrict__ sel,
                                float scale) {
    int idx = blockIdx.x * blockDim.x + threadIdx.x;
    if (idx >= BZ * HZ * EZ * MZ) return;
    int m = idx & 63;
    int o = (idx >> 6) & 7;
    int h = (idx >> 9) & 7;
    int b = idx >> 12;
    float ar = 0.f, ai = 0.f;
#pragma unroll
    for (int e = 0; e < 8; e++) {
        int rx = (b * 64 + h * 8 + e) * M2 + 2 * m;
        float xr = X[rx], xi = X[rx + 1];
        int wix = ((h * 8 + e) * 8 + o) * MZ + m;
        float wrv = wr[wix], wiv = wi[wix];
        ar += xr * wrv - xi * wiv;
        ai += xr * wiv + xi * wrv;
    }
    int ro = (b * 64 + h * 8 + o) * M2 + 2 * m;
    sel[ro] = ar * scale;
    sel[ro + 1] = ai * scale;
}

__global__ void qk_kernel(const float* __restrict__ Qf, const float* __restrict__ Kf,
                          float* __restrict__ qk) {
    int idx = blockIdx.x * blockDim.x + threadIdx.x;
    if (idx >= BZ * HZ * MZ * MZ) return;
    int y = idx & 63;
    int x = (idx >> 6) & 63;
    int h = (idx >> 12) & 7;
    int b = idx >> 15;
    float ar = 0.f, ai = 0.f;
#pragma unroll
    for (int e = 0; e < 8; e++) {
        int rq = (b * 64 + h * 8 + e) * M2;
        float qr = Qf[rq + 2 * x], qi = Qf[rq + 2 * x + 1];
        float kr = Kf[rq + 2 * y], ki = Kf[rq + 2 * y + 1];
        ar += qr * kr - qi * ki;
        ai += qr * ki + qi * kr;
    }
    float a2 = 2.f * ar, b2 = 2.f * ai;
    float tr, ti;
    if (fabsf(a2) > 30.f) {
        tr = copysignf(1.f, ar);
        ti = 0.f;
    } else {
        float sn, cs;
        sincosf(b2, &sn, &cs);
        float den = coshf(a2) + cs;
        tr = sinhf(a2) / den;
        ti = sn / den;
    }
    size_t o = ((size_t)((b * 8 + h) * 64 + x) * 64 + y) * 2;
    qk[o] = tr;
    qk[o + 1] = ti;
}

__global__ void qkv_kernel(const float* __restrict__ qk, const float* __restrict__ Kf,
                           float* __restrict__ out) {
    int idx = blockIdx.x * blockDim.x + threadIdx.x;
    if (idx >= BZ * HZ * EZ * MZ) return;
    int x = idx & 63;
    int e = (idx >> 6) & 7;
    int h = (idx >> 9) & 7;
    int b = idx >> 12;
    const float* qrow = qk + ((size_t)((b * 8 + h) * 64 + x) * 64) * 2;
    const float* krow = Kf + (size_t)(b * 64 + h * 8 + e) * M2;
    float ar = 0.f, ai = 0.f;
    for (int y = 0; y < 64; y++) {
        float qr = qrow[2 * y], qi = qrow[2 * y + 1];
        float kr = krow[2 * y], ki = krow[2 * y + 1];
        ar += qr * kr - qi * ki;
        ai += qr * ki + qi * kr;
    }
    int ro = (b * 64 + h * 8 + e) * M2 + 2 * x;
    out[ro] = ar;
    out[ro + 1] = ai;
}

__global__ void ln_row_kernel(const float* __restrict__ X, const float* __restrict__ g,
                              const float* __restrict__ be, float* __restrict__ out) {
    __shared__ float red[256];
    int tid = threadIdx.x;
    int sub = tid >> 6;
    int d = tid & 63;
    int row = blockIdx.x * 4 + sub;
    float v = X[(size_t)row * DZ + d];
    red[tid] = v;
    __syncthreads();
    for (int s = 32; s > 0; s >>= 1) {
        if (d < s) red[tid] += red[tid + s];
        __syncthreads();
    }
    float mu = red[sub * 64] * (1.f / 64.f);
    __syncthreads();
    float dv = v - mu;
    red[tid] = dv * dv;
    __syncthreads();
    for (int s = 32; s > 0; s >>= 1) {
        if (d < s) red[tid] += red[tid + s];
        __syncthreads();
    }
    float var = red[sub * 64] * (1.f / 64.f);
    out[(size_t)row * DZ + d] = dv * rsqrtf(var + 1e-5f) * g[d] + be[d];
}

__global__ void colmean_kernel(const float* __restrict__ X, float* __restrict__ cm) {
    __shared__ float r[256];
    int b = blockIdx.x / DZ, d = blockIdx.x % DZ;
    float s = 0.f;
    for (int t = threadIdx.x; t < LZ; t += 256) s += X[((size_t)(b * LZ + t)) * DZ + d];
    r[threadIdx.x] = s;
    __syncthreads();
    for (int o = 128; o > 0; o >>= 1) {
        if (threadIdx.x < o) r[threadIdx.x] += r[threadIdx.x + o];
        __syncthreads();
    }
    if (threadIdx.x == 0) cm[b * DZ + d] = r[0] * (1.f / LZ);
}

__global__ void subtract_cm_kernel(const float* __restrict__ X, const float* __restrict__ cm,
                                   float* __restrict__ out) {
    int idx = blockIdx.x * blockDim.x + threadIdx.x;
    if (idx >= NROW * DZ) return;
    int d = idx & 63;
    int b = idx >> 16;
    out[idx] = X[idx] - cm[b * DZ + d];
}

__global__ void final_kernel(const float* __restrict__ xln, const float* __restrict__ tacc,
                             const float* __restrict__ tbase, const float* __restrict__ tw,
                             const float* __restrict__ pw, const float* __restrict__ pb,
                             float* __restrict__ out) {
    int idx = blockIdx.x * blockDim.x + threadIdx.x;
    if (idx >= BZ * 512) return;
    int t = idx & 511, b = idx >> 9;
    int tt = t + 512;
    float cv = 0.f;
#pragma unroll
    for (int j = 0; j < 3; j++) {
        int ts = (tt + j - 1) & (LZ - 1);
        const float* row = tacc + ((size_t)(b * LZ + ts)) * DZ;
        for (int d = 0; d < DZ; d++) cv += row[d] * tw[d * 3 + j];
    }
    float p = pb[0];
    const float* xr = xln + ((size_t)(b * LZ + tt)) * DZ;
    for (int d = 0; d < DZ; d++) p += xr[d] * pw[d];
    out[idx] = p + cv + tbase[b * LZ + tt];
}

static float* symaddr_f(const void* sym) {
    void* p = nullptr;
    cudaGetSymbolAddress(&p, sym);
    return (float*)p;
}

extern "C" void kernel_launch(void* const* d_in, const int* in_sizes, int n_in,
                              void* d_out, int out_size) {
    const float* x_enc       = (const float*)d_in[0];
    const float* dp_w        = (const float*)d_in[1];
    const float* dp_b        = (const float*)d_in[2];
    const float* emb_enc_w   = (const float*)d_in[3];
    const float* emb_dec_w   = (const float*)d_in[4];
    const float* decomp_w    = (const float*)d_in[5];
    const float* decomp_b    = (const float*)d_in[6];
    const float* enc_attn_w  = (const float*)d_in[7];
    const float* enc_attn_b  = (const float*)d_in[8];
    const float* enc_four_wr = (const float*)d_in[9];
    const float* enc_four_wi = (const float*)d_in[10];
    const float* enc_c1      = (const float*)d_in[11];
    const float* enc_c2      = (const float*)d_in[12];
    const float* enc_ln_g    = (const float*)d_in[13];
    const float* enc_ln_b    = (const float*)d_in[14];
    const float* dec_self_w  = (const float*)d_in[15];
    const float* dec_self_b  = (const float*)d_in[16];
    const float* dec_four_wr = (const float*)d_in[17];
    const float* dec_four_wi = (const float*)d_in[18];
    const float* dec_cross_w = (const float*)d_in[19];
    const float* dec_cross_b = (const float*)d_in[20];
    const float* dec_cross_wr= (const float*)d_in[21];
    const float* dec_cross_wi= (const float*)d_in[22];
    const float* dec_c1      = (const float*)d_in[23];
    const float* dec_c2      = (const float*)d_in[24];
    const float* dec_trend_w = (const float*)d_in[25];
    const float* dec_ln_g    = (const float*)d_in[26];
    const float* dec_ln_b    = (const float*)d_in[27];
    const float* dec_proj_w  = (const float*)d_in[28];
    const float* dec_proj_b  = (const float*)d_in[29];
    float* out = (float*)d_out;

    float* px        = symaddr_f(g_x);
    float* pseas0    = symaddr_f(g_seas0);
    float* ptrend0   = symaddr_f(g_trend0);
    float* pseasinit = symaddr_f(g_seasinit);
    float* ph        = symaddr_f(g_h);
    float* pq        = symaddr_f(g_q);
    float* pqT       = symaddr_f(g_qT);
    float* py        = symaddr_f(g_y);
    float* pa        = symaddr_f(g_a);
    float* pffn      = symaddr_f(g_ffn);
    float* pXf       = symaddr_f(g_Xf);
    float* pXk       = symaddr_f(g_Xk);
    float* psel      = symaddr_f(g_sel);
    float* pqk       = symaddr_f(g_qk);
    float* pxd       = symaddr_f(g_xd);
    float* ptacc     = symaddr_f(g_tacc);
    float* pcm       = symaddr_f(g_cm);
    float* pln       = symaddr_f(g_ln);
    float* pF        = symaddr_f(g_F);
    float* pFi       = symaddr_f(g_Fi);
    float* ptbase    = symaddr_f(g_trendbase);

    dim3 tb(32, 8);
    dim3 tg(32, 2, 64);

    build_tables_kernel<<<512, 256>>>();
    transpose_in_kernel<<<1792, 256>>>(x_enc);
    colmean7_kernel<<<BZ * C7, 256>>>(x_enc);
    decomp7_kernel<<<BZ * C7, LZ>>>(px, decomp_w + 0, decomp_b + 0, pseas0, ptrend0);
    trendbase_kernel<<<256, 256>>>(dp_w, dp_b);
    seasinit_kernel<<<1792, 256>>>();

    embed_kernel<<<16384, 256>>>(px, emb_enc_w, ph);
    for (int l = 0; l < 2; l++) {
        const float* wq = enc_attn_w + (size_t)(l * 4 + 0) * 4096;
        const float* bq = enc_attn_b + (size_t)(l * 4 + 0) * 64;
        const float* wo = enc_attn_w + (size_t)(l * 4 + 3) * 4096;
        const float* bo = enc_attn_b + (size_t)(l * 4 + 3) * 64;
        gemm_kernel<0><<<dim3(1024, 1), 256>>>(ph, wq, bq, pq, NROW, 64, 64);
        transpose_bld_kernel<<<tg, tb>>>(pq, pqT);
        gemm_kernel<0><<<dim3(64, 2), 256>>>(pqT, pF, nullptr, pXf, NHE, 1024, 128);
        mode_mix_kernel<<<1024, 256>>>(pXf, enc_four_wr + (size_t)l * 32768,
                                       enc_four_wi + (size_t)l * 32768, psel, 1.0f);
        gemm_kernel<0><<<dim3(64, 16), 256>>>(psel, pFi, nullptr, py, NHE, 128, 1024);
        gemm_kernel<0><<<dim3(1024, 1), 256>>>(py, wo, bo, pa, NROW, 64, 64);
        decomp64_kernel<<<1024, LZ>>>(ph, pa, decomp_w + (1 + 2 * l) * 4,
                                      decomp_b + (1 + 2 * l) * 4, ph, nullptr, 0);
        gemm_kernel<1><<<dim3(1024, 4), 256>>>(ph, enc_c1 + (size_t)l * 16384, nullptr, pffn,
                                               NROW, 64, 256);
        gemm_kernel<0><<<dim3(1024, 1), 256>>>(pffn, enc_c2 + (size_t)l * 16384, nullptr, py,
                                               NROW, 256, 64);
        decomp64_kernel<<<1024, LZ>>>(ph, py, decomp_w + (2 + 2 * l) * 4,
                                      decomp_b + (2 + 2 * l) * 4, ph, nullptr, 0);
    }
    ln_row_kernel<<<16384, 256>>>(ph, enc_ln_g, enc_ln_b, pln);
    colmean_kernel<<<BZ * DZ, 256>>>(pln, pcm);
    subtract_cm_kernel<<<16384, 256>>>(pln, pcm, ph);

    embed_kernel<<<16384, 256>>>(pseasinit, emb_dec_w, pxd);
    gemm_kernel<0><<<dim3(1024, 1), 256>>>(pxd, dec_self_w + 0, dec_self_b + 0, pq, NROW, 64, 64);
    transpose_bld_kernel<<<tg, tb>>>(pq, pqT);
    gemm_kernel<0><<<dim3(64, 2), 256>>>(pqT, pF, nullptr, pXf, NHE, 1024, 128);
    mode_mix_kernel<<<1024, 256>>>(pXf, dec_four_wr, dec_four_wi, psel, 1.0f);
    gemm_kernel<0><<<dim3(64, 16), 256>>>(psel, pFi, nullptr, py, NHE, 128, 1024);
    gemm_kernel<0><<<dim3(1024, 1), 256>>>(py, dec_self_w + 3 * 4096, dec_self_b + 3 * 64, pa,
                                           NROW, 64, 64);
    decomp64_kernel<<<1024, LZ>>>(pxd, pa, decomp_w + 5 * 4, decomp_b + 5 * 4, pxd, ptacc, 0);

    gemm_kernel<0><<<dim3(1024, 1), 256>>>(pxd, dec_cross_w + 0, dec_cross_b + 0, pq, NROW, 64, 64);
    transpose_bld_kernel<<<tg, tb>>>(pq, pqT);
    gemm_kernel<0><<<dim3(64, 2), 256>>>(pqT, pF, nullptr, pXf, NHE, 1024, 128);
    gemm_kernel<0><<<dim3(1024, 1), 256>>>(ph, dec_cross_w + 1 * 4096, dec_cross_b + 1 * 64, pq,
                                           NROW, 64, 64);
    transpose_bld_kernel<<<tg, tb>>>(pq, pqT);
    gemm_kernel<0><<<dim3(64, 2), 256>>>(pqT, pF, nullptr, pXk, NHE, 1024, 128);
    qk_kernel<<<8192, 256>>>(pXf, pXk, pqk);
    qkv_kernel<<<1024, 256>>>(pqk, pXk, pXf);
    mode_mix_kernel<<<1024, 256>>>(pXf, dec_cross_wr, dec_cross_wi, psel, 1.0f / 4096.0f);
    gemm_kernel<0><<<dim3(64, 16), 256>>>(psel, pFi, nullptr, py, NHE, 128, 1024);
    gemm_kernel<0><<<dim3(1024, 1), 256>>>(py, dec_cross_w + 3 * 4096, dec_cross_b + 3 * 64, pa,
                                           NROW, 64, 64);
    decomp64_kernel<<<1024, LZ>>>(pxd, pa, decomp_w + 6 * 4, decomp_b + 6 * 4, pxd, ptacc, 1);

    gemm_kernel<1><<<dim3(1024, 4), 256>>>(pxd, dec_c1, nullptr, pffn, NROW, 64, 256);
    gemm_kernel<0><<<dim3(1024, 1), 256>>>(pffn, dec_c2, nullptr, py, NROW, 256, 64);
    decomp64_kernel<<<1024, LZ>>>(pxd, py, decomp_w + 7 * 4, decomp_b + 7 * 4, pxd, ptacc, 1);

    ln_row_kernel<<<16384, 256>>>(pxd, dec_ln_g, dec_ln_b, pln);
    colmean_kernel<<<BZ * DZ, 256>>>(pln, pcm);
    subtract_cm_kernel<<<16384, 256>>>(pln, pcm, pln);
    final_kernel<<<128, 256>>>(pln, ptacc, ptbase, dec_trend_w, dec_proj_w, dec_proj_b, out);
}

// round 4
// speedup vs baseline: 1.5703x; 1.5703x over previous
#include <cuda_runtime.h>
#include <cstdint>

#define BZ 64
#define LZ 1024
#define DZ 64
#define C7 7
#define HZ 8
#define EZ 8
#define MZ 64
#define M2 128
#define DFFD 256
#define NROW (BZ*LZ)
#define NHE  (BZ*DZ)

__device__ float g_x[BZ*LZ*C7];
__device__ float g_seas0[BZ*LZ*C7];
__device__ float g_trend0[BZ*LZ*C7];
__device__ float g_mean7[BZ*C7];
__device__ float g_trendbase[BZ*LZ];
__device__ float g_seasinit[BZ*LZ*C7];
__device__ float g_h[NROW*DZ];
__device__ float g_q[NROW*DZ];
__device__ float g_qT[NROW*DZ];
__device__ float g_y[NROW*DZ];
__device__ float g_a[NROW*DZ];
__device__ float g_ffn[NROW*DFFD];
__device__ float g_Xf[NHE*M2];
__device__ float g_Xk[NHE*M2];
__device__ float g_sel[NHE*M2];
__device__ float g_qk[BZ*HZ*MZ*MZ*2];
__device__ float g_xd[NROW*DZ];
__device__ float g_tacc[NROW*DZ];
__device__ float g_cm[BZ*DZ];
__device__ float g_ln[NROW*DZ];
__device__ float g_F[M2*LZ];
__device__ float g_Fi[LZ*M2];
__device__ float g_pe[LZ*DZ];

// ------------------------------------------------------------------ tables
__global__ void build_tables_kernel() {
    int idx = blockIdx.x * blockDim.x + threadIdx.x;
    if (idx >= LZ * M2) return;
    int t = idx >> 7;
    int m2 = idx & 127;
    int m = m2 >> 1;
    int r = (m * t) & (LZ - 1);
    float a = (float)r * (6.28318530717958647692f / (float)LZ);
    float s, c;
    sincosf(a, &s, &c);
    float v = (m2 & 1) ? -s : c;
    g_F[(size_t)m2 * LZ + t] = v;
    float cm = (m == 0) ? 1.f : 2.f;
    g_Fi[(size_t)t * M2 + m2] = v * (cm / (float)LZ);
}

__global__ void build_pe_kernel() {
    int idx = blockIdx.x * blockDim.x + threadIdx.x;
    if (idx >= LZ * DZ) return;
    int o = idx & 63;
    int t = idx >> 6;
    int i2 = o & ~1;
    float div = expf(-(float)i2 * 0.14391156831212793f);
    float arg = (float)t * div;
    g_pe[idx] = (o & 1) ? cosf(arg) : sinf(arg);
}

// ------------------------------------------------------------------ input prep
__global__ void transpose_in_kernel(const float* __restrict__ xe) {
    int idx = blockIdx.x * blockDim.x + threadIdx.x;
    if (idx >= BZ * C7 * LZ) return;
    int t = idx & 1023;
    int c = (idx >> 10) % C7;
    int b = idx / (C7 * LZ);
    g_x[((size_t)(b * LZ + t)) * C7 + c] = xe[idx];
}

__global__ void colmean7_kernel(const float* __restrict__ xe) {
    __shared__ float r[256];
    int bc = blockIdx.x;
    float s = 0.f;
    for (int t = threadIdx.x; t < LZ; t += 256) s += xe[(size_t)bc * LZ + t];
    r[threadIdx.x] = s;
    __syncthreads();
    for (int o = 128; o > 0; o >>= 1) {
        if (threadIdx.x < o) r[threadIdx.x] += r[threadIdx.x + o];
        __syncthreads();
    }
    if (threadIdx.x == 0) g_mean7[bc] = r[0] * (1.f / LZ);
}

// ------------------------------------------------------------------ decomps (warp-shuffle scan)
__global__ void decomp7_kernel(const float* __restrict__ A,
                               const float* __restrict__ w4, const float* __restrict__ b4,
                               float* __restrict__ seas, float* __restrict__ trend) {
    __shared__ float ps[LZ];
    __shared__ float wsum[32];
    __shared__ float sx0, sxN;
    int c = blockIdx.x % C7, b = blockIdx.x / C7;
    int t = threadIdx.x, lane = t & 31, wid = t >> 5;
    size_t idx = ((size_t)(b * LZ + t)) * C7 + c;
    float x = A[idx];
    float s = x;
#pragma unroll
    for (int off = 1; off < 32; off <<= 1) {
        float v = __shfl_up_sync(0xffffffffu, s, off);
        if (lane >= off) s += v;
    }
    if (lane == 31) wsum[wid] = s;
    if (t == 0) sx0 = x;
    if (t == LZ - 1) sxN = x;
    __syncthreads();
    if (wid == 0) {
        float v = wsum[lane];
#pragma unroll
        for (int off = 1; off < 32; off <<= 1) {
            float u = __shfl_up_sync(0xffffffffu, v, off);
            if (lane >= off) v += u;
        }
        wsum[lane] = v;
    }
    __syncthreads();
    if (wid > 0) s += wsum[wid - 1];
    ps[t] = s;
    __syncthreads();
    float x0 = sx0, xN = sxN;
    const int ks[4] = {10, 50, 100, 500};
    float ma[4];
#pragma unroll
    for (int kk = 0; kk < 4; kk++) {
        int k = ks[kk], f = (k - 1) >> 1, e = k >> 1;
        int lo = t - f, hi = t + e;
        int cl = lo < 0 ? 0 : lo, ch = hi > LZ - 1 ? LZ - 1 : hi;
        float sw = ps[ch] - (cl > 0 ? ps[cl - 1] : 0.f)
                 + (float)(cl - lo) * x0 + (float)(hi - ch) * xN;
        ma[kk] = sw / (float)k;
    }
    float z[4], mx = -1e30f;
#pragma unroll
    for (int kk = 0; kk < 4; kk++) { z[kk] = x * w4[kk] + b4[kk]; mx = fmaxf(mx, z[kk]); }
    float se = 0.f, mean = 0.f;
#pragma unroll
    for (int kk = 0; kk < 4; kk++) { float e2 = expf(z[kk] - mx); se += e2; mean += ma[kk] * e2; }
    mean /= se;
    seas[idx] = x - mean;
    trend[idx] = mean;
}

__device__ __forceinline__ float4 f4add(float4 a, float4 b) {
    return make_float4(a.x + b.x, a.y + b.y, a.z + b.z, a.w + b.w);
}

__global__ void decomp64_kernel(const float* __restrict__ A, const float* __restrict__ Bb,
                                const float* __restrict__ w4, const float* __restrict__ b4,
                                float* __restrict__ seas, float* __restrict__ trend, int accum) {
    __shared__ float4 ps[LZ];
    __shared__ float4 wsum[32];
    __shared__ float4 sx0, sxN;
    int c4 = blockIdx.x & 15, b = blockIdx.x >> 4;
    int t = threadIdx.x, lane = t & 31, wid = t >> 5;
    size_t base = ((size_t)(b * LZ + t)) * DZ + c4 * 4;
    float4 x = *reinterpret_cast<const float4*>(A + base);
    if (Bb) {
        float4 y = *reinterpret_cast<const float4*>(Bb + base);
        x = f4add(x, y);
    }
    float4 s = x;
#pragma unroll
    for (int off = 1; off < 32; off <<= 1) {
        float4 v;
        v.x = __shfl_up_sync(0xffffffffu, s.x, off);
        v.y = __shfl_up_sync(0xffffffffu, s.y, off);
        v.z = __shfl_up_sync(0xffffffffu, s.z, off);
        v.w = __shfl_up_sync(0xffffffffu, s.w, off);
        if (lane >= off) s = f4add(s, v);
    }
    if (lane == 31) wsum[wid] = s;
    if (t == 0) sx0 = x;
    if (t == LZ - 1) sxN = x;
    __syncthreads();
    if (wid == 0) {
        float4 v = wsum[lane];
#pragma unroll
        for (int off = 1; off < 32; off <<= 1) {
            float4 u;
            u.x = __shfl_up_sync(0xffffffffu, v.x, off);
            u.y = __shfl_up_sync(0xffffffffu, v.y, off);
            u.z = __shfl_up_sync(0xffffffffu, v.z, off);
            u.w = __shfl_up_sync(0xffffffffu, v.w, off);
            if (lane >= off) v = f4add(v, u);
        }
        wsum[lane] = v;
    }
    __syncthreads();
    if (wid > 0) s = f4add(s, wsum[wid - 1]);
    ps[t] = s;
    __syncthreads();
    float4 x0 = sx0, xN = sxN;
    const int ks[4] = {10, 50, 100, 500};
    float ma[4][4];
#pragma unroll
    for (int kk = 0; kk < 4; kk++) {
        int k = ks[kk], f = (k - 1) >> 1, e = k >> 1;
        int lo = t - f, hi = t + e;
        int cl = lo < 0 ? 0 : lo, ch = hi > LZ - 1 ? LZ - 1 : hi;
        float4 pc = ps[ch];
        float4 pl = make_float4(0.f, 0.f, 0.f, 0.f);
        if (cl > 0) pl = ps[cl - 1];
        float fl = (float)(cl - lo), fr = (float)(hi - ch);
        float inv = 1.f / (float)k;
        ma[kk][0] = (pc.x - pl.x + fl * x0.x + fr * xN.x) * inv;
        ma[kk][1] = (pc.y - pl.y + fl * x0.y + fr * xN.y) * inv;
        ma[kk][2] = (pc.z - pl.z + fl * x0.z + fr * xN.z) * inv;
        ma[kk][3] = (pc.w - pl.w + fl * x0.w + fr * xN.w) * inv;
    }
    float xa[4] = {x.x, x.y, x.z, x.w};
    float so[4], tr[4];
#pragma unroll
    for (int cc = 0; cc < 4; cc++) {
        float z[4], mx = -1e30f;
#pragma unroll
        for (int kk = 0; kk < 4; kk++) { z[kk] = xa[cc] * w4[kk] + b4[kk]; mx = fmaxf(mx, z[kk]); }
        float se = 0.f, mean = 0.f;
#pragma unroll
        for (int kk = 0; kk < 4; kk++) { float e2 = expf(z[kk] - mx); se += e2; mean += ma[kk][cc] * e2; }
        mean /= se;
        so[cc] = xa[cc] - mean;
        tr[cc] = mean;
    }
    *reinterpret_cast<float4*>(seas + base) = make_float4(so[0], so[1], so[2], so[3]);
    if (trend) {
        float4 tv = make_float4(tr[0], tr[1], tr[2], tr[3]);
        if (accum) {
            float4 old = *reinterpret_cast<float4*>(trend + base);
            tv = f4add(tv, old);
        }
        *reinterpret_cast<float4*>(trend + base) = tv;
    }
}

// ------------------------------------------------------------------ trend/seasonal init
__global__ void trendbase_kernel(const float* __restrict__ dpw, const float* __restrict__ dpb) {
    int idx = blockIdx.x * blockDim.x + threadIdx.x;
    if (idx >= BZ * LZ) return;
    int t = idx & 1023, b = idx >> 10;
    float s = dpb[0];
#pragma unroll
    for (int c = 0; c < C7; c++) {
        float v = (t < 512) ? g_trend0[((size_t)(b * LZ + 512 + t)) * C7 + c]
                            : g_mean7[b * C7 + c];
        s += v * dpw[c];
    }
    g_trendbase[idx] = s;
}

__global__ void seasinit_kernel() {
    int idx = blockIdx.x * blockDim.x + threadIdx.x;
    if (idx >= BZ * LZ * C7) return;
    int c = idx % C7;
    int t = (idx / C7) & 1023;
    int b = idx / (C7 * LZ);
    g_seasinit[idx] = (t < 512) ? g_seas0[((size_t)(b * LZ + 512 + t)) * C7 + c] : 0.f;
}

// ------------------------------------------------------------------ embedding
__global__ void embed_kernel(const float* __restrict__ in, const float* __restrict__ w,
                             float* __restrict__ out) {
    int idx = blockIdx.x * blockDim.x + threadIdx.x;
    if (idx >= BZ * LZ * DZ) return;
    int o = idx & 63;
    int t = (idx >> 6) & 1023;
    int b = idx >> 16;
    float s = 0.f;
#pragma unroll
    for (int j = 0; j < 3; j++) {
        int ts = (t + j - 1 + LZ) & (LZ - 1);
        const float* ip = in + ((size_t)(b * LZ + ts)) * C7;
#pragma unroll
        for (int c = 0; c < C7; c++) s += ip[c] * w[(o * C7 + c) * 3 + j];
    }
    out[idx] = s + g_pe[(t << 6) + o];
}

// ------------------------------------------------------------------ tf32 tensor-core GEMM
__device__ __forceinline__ uint32_t to_tf32(float x) {
    uint32_t r;
    asm("cvt.rna.tf32.f32 %0, %1;" : "=r"(r) : "f"(x));
    return r;
}

template <int ACT>
__global__ __launch_bounds__(128) void gemm_tc(const float* __restrict__ A,
                                               const float* __restrict__ W,
                                               const float* __restrict__ bias,
                                               float* __restrict__ C,
                                               int N, int K, int O) {
    __shared__ uint32_t As[128][36];
    __shared__ uint32_t Bs[64][36];
    const int rb = blockIdx.x * 128;
    const int cb = blockIdx.y * 64;
    const int tid = threadIdx.x;
    const int lane = tid & 31;
    const int w = tid >> 5;
    const int wm = w & 1, wn = w >> 1;
    const int m0 = wm * 64, n0 = wn * 32;
    const int g = lane >> 2, tg = lane & 3;
    const int lrow = tid >> 3;         // 0..15
    const int lcol = (tid & 7) * 4;    // 0..28

    float acc[4][4][4];
#pragma unroll
    for (int mi = 0; mi < 4; mi++)
#pragma unroll
        for (int ni = 0; ni < 4; ni++)
#pragma unroll
            for (int r = 0; r < 4; r++) acc[mi][ni][r] = 0.f;

    for (int k0 = 0; k0 < K; k0 += 32) {
#pragma unroll
        for (int r = 0; r < 8; r++) {
            int row = lrow + r * 16;
            float4 v = *reinterpret_cast<const float4*>(A + (size_t)(rb + row) * K + k0 + lcol);
            uint4 u;
            u.x = to_tf32(v.x); u.y = to_tf32(v.y); u.z = to_tf32(v.z); u.w = to_tf32(v.w);
            *reinterpret_cast<uint4*>(&As[row][lcol]) = u;
        }
#pragma unroll
        for (int r = 0; r < 4; r++) {
            int row = lrow + r * 16;
            float4 v = *reinterpret_cast<const float4*>(W + (size_t)(cb + row) * K + k0 + lcol);
            uint4 u;
            u.x = to_tf32(v.x); u.y = to_tf32(v.y); u.z = to_tf32(v.z); u.w = to_tf32(v.w);
            *reinterpret_cast<uint4*>(&Bs[row][lcol]) = u;
        }
        __syncthreads();
#pragma unroll
        for (int kk = 0; kk < 32; kk += 8) {
            uint32_t a[4][4], bfr[4][2];
#pragma unroll
            for (int mi = 0; mi < 4; mi++) {
                int r = m0 + mi * 16 + g;
                a[mi][0] = As[r][kk + tg];
                a[mi][1] = As[r + 8][kk + tg];
                a[mi][2] = As[r][kk + tg + 4];
                a[mi][3] = As[r + 8][kk + tg + 4];
            }
#pragma unroll
            for (int ni = 0; ni < 4; ni++) {
                int c = n0 + ni * 8 + g;
                bfr[ni][0] = Bs[c][kk + tg];
                bfr[ni][1] = Bs[c][kk + tg + 4];
            }
#pragma unroll
            for (int mi = 0; mi < 4; mi++)
#pragma unroll
                for (int ni = 0; ni < 4; ni++) {
                    asm volatile(
                        "mma.sync.aligned.m16n8k8.row.col.f32.tf32.tf32.f32 "
                        "{%0,%1,%2,%3}, {%4,%5,%6,%7}, {%8,%9}, {%0,%1,%2,%3};"
                        : "+f"(acc[mi][ni][0]), "+f"(acc[mi][ni][1]),
                          "+f"(acc[mi][ni][2]), "+f"(acc[mi][ni][3])
                        : "r"(a[mi][0]), "r"(a[mi][1]), "r"(a[mi][2]), "r"(a[mi][3]),
                          "r"(bfr[ni][0]), "r"(bfr[ni][1]));
                }
        }
        __syncthreads();
    }
#pragma unroll
    for (int mi = 0; mi < 4; mi++) {
        int row0 = rb + m0 + mi * 16 + g;
#pragma unroll
        for (int ni = 0; ni < 4; ni++) {
            int col = cb + n0 + ni * 8 + 2 * tg;
#pragma unroll
            for (int half = 0; half < 2; half++) {
                int row = row0 + half * 8;
                float v0 = acc[mi][ni][half * 2 + 0];
                float v1 = acc[mi][ni][half * 2 + 1];
                if (bias) { v0 += bias[col]; v1 += bias[col + 1]; }
                if (ACT == 1) {
                    v0 = 0.5f * v0 * (1.f + erff(v0 * 0.70710678118654752f));
                    v1 = 0.5f * v1 * (1.f + erff(v1 * 0.70710678118654752f));
                }
                C[(size_t)row * O + col] = v0;
                C[(size_t)row * O + col + 1] = v1;
            }
        }
    }
}

// ------------------------------------------------------------------ transpose (B,L,64)->(B,64,L)
__global__ void transpose_bld_kernel(const float* __restrict__ in, float* __restrict__ out) {
    __shared__ float tile[32][33];
    int b = blockIdx.z;
    int t0 = blockIdx.x * 32;
    int d0 = blockIdx.y * 32;
    int tx = threadIdx.x, ty = threadIdx.y;
#pragma unroll
    for (int i = 0; i < 32; i += 8)
        tile[ty + i][tx] = in[((size_t)b * LZ + t0 + ty + i) * DZ + d0 + tx];
    __syncthreads();
#pragma unroll
    for (int i = 0; i < 32; i += 8)
        out[((size_t)b * DZ + d0 + ty + i) * LZ + t0 + tx] = tile[tx][ty + i];
}

// ------------------------------------------------------------------ mode mixing / cross attn
__global__ void mode_mix_kernel(const float* __restrict__ X, const float* __restrict__ wr,
                                const float* __restrict__ wi, float* __restrict__ sel,
                                float scale) {
    int idx = blockIdx.x * blockDim.x + threadIdx.x;
    if (idx >= BZ * HZ * EZ * MZ) return;
    int m = idx & 63;
    int o = (idx >> 6) & 7;
    int h = (idx >> 9) & 7;
    int b = idx >> 12;
    float ar = 0.f, ai = 0.f;
#pragma unroll
    for (int e = 0; e < 8; e++) {
        int rx = (b * 64 + h * 8 + e) * M2 + 2 * m;
        float xr = X[rx], xi = X[rx + 1];
        int wix = ((h * 8 + e) * 8 + o) * MZ + m;
        float wrv = wr[wix], wiv = wi[wix];
        ar += xr * wrv - xi * wiv;
        ai += xr * wiv + xi * wrv;
    }
    int ro = (b * 64 + h * 8 + o) * M2 + 2 * m;
    sel[ro] = ar * scale;
    sel[ro + 1] = ai * scale;
}

__global__ void qk_kernel(const float* __restrict__ Qf, const float* __restrict__ Kf,
                          float* __restrict__ qk) {
    int idx = blockIdx.x * blockDim.x + threadIdx.x;
    if (idx >= BZ * HZ * MZ * MZ) return;
    int y = idx & 63;
    int x = (idx >> 6) & 63;
    int h = (idx >> 12) & 7;
    int b = idx >> 15;
    float ar = 0.f, ai = 0.f;
#pragma unroll
    for (int e = 0; e < 8; e++) {
        int rq = (b * 64 + h * 8 + e) * M2;
        float qr = Qf[rq + 2 * x], qi = Qf[rq + 2 * x + 1];
        float kr = Kf[rq + 2 * y], ki = Kf[rq + 2 * y + 1];
        ar += qr * kr - qi * ki;
        ai += qr * ki + qi * kr;
    }
    float a2 = 2.f * ar, b2 = 2.f * ai;
    float tr, ti;
    if (fabsf(a2) > 30.f) {
        tr = copysignf(1.f, ar);
        ti = 0.f;
    } else {
        float sn, cs;
        sincosf(b2, &sn, &cs);
        float ex = expf(a2);
        float exi = 1.f / ex;
        float den = 0.5f * (ex + exi) + cs;
        tr = 0.5f * (ex - exi) / den;
        ti = sn / den;
    }
    size_t o = ((size_t)((b * 8 + h) * 64 + x) * 64 + y) * 2;
    qk[o] = tr;
    qk[o + 1] = ti;
}

__global__ void qkv_kernel(const float* __restrict__ qk, const float* __restrict__ Kf,
                           float* __restrict__ out) {
    int idx = blockIdx.x * blockDim.x + threadIdx.x;
    if (idx >= BZ * HZ * EZ * MZ) return;
    int x = idx & 63;
    int e = (idx >> 6) & 7;
    int h = (idx >> 9) & 7;
    int b = idx >> 12;
    const float* qrow = qk + ((size_t)((b * 8 + h) * 64 + x) * 64) * 2;
    const float* krow = Kf + (size_t)(b * 64 + h * 8 + e) * M2;
    float ar = 0.f, ai = 0.f;
    for (int y = 0; y < 64; y++) {
        float qr = qrow[2 * y], qi = qrow[2 * y + 1];
        float kr = krow[2 * y], ki = krow[2 * y + 1];
        ar += qr * kr - qi * ki;
        ai += qr * ki + qi * kr;
    }
    int ro = (b * 64 + h * 8 + e) * M2 + 2 * x;
    out[ro] = ar;
    out[ro + 1] = ai;
}

// ------------------------------------------------------------------ layernorm family
__global__ void ln_row_kernel(const float* __restrict__ X, const float* __restrict__ g,
                              const float* __restrict__ be, float* __restrict__ out) {
    __shared__ float red[256];
    int tid = threadIdx.x;
    int sub = tid >> 6;
    int d = tid & 63;
    int row = blockIdx.x * 4 + sub;
    float v = X[(size_t)row * DZ + d];
    red[tid] = v;
    __syncthreads();
    for (int s = 32; s > 0; s >>= 1) {
        if (d < s) red[tid] += red[tid + s];
        __syncthreads();
    }
    float mu = red[sub * 64] * (1.f / 64.f);
    __syncthreads();
    float dv = v - mu;
    red[tid] = dv * dv;
    __syncthreads();
    for (int s = 32; s > 0; s >>= 1) {
        if (d < s) red[tid] += red[tid + s];
        __syncthreads();
    }
    float var = red[sub * 64] * (1.f / 64.f);
    out[(size_t)row * DZ + d] = dv * rsqrtf(var + 1e-5f) * g[d] + be[d];
}

__global__ void colmean_kernel(const float* __restrict__ X, float* __restrict__ cm) {
    __shared__ float r[256];
    int b = blockIdx.x / DZ, d = blockIdx.x % DZ;
    float s = 0.f;
    for (int t = threadIdx.x; t < LZ; t += 256) s += X[((size_t)(b * LZ + t)) * DZ + d];
    r[threadIdx.x] = s;
    __syncthreads();
    for (int o = 128; o > 0; o >>= 1) {
        if (threadIdx.x < o) r[threadIdx.x] += r[threadIdx.x + o];
        __syncthreads();
    }
    if (threadIdx.x == 0) cm[b * DZ + d] = r[0] * (1.f / LZ);
}

__global__ void subtract_cm_kernel(const float* __restrict__ X, const float* __restrict__ cm,
                                   float* __restrict__ out) {
    int idx = blockIdx.x * blockDim.x + threadIdx.x;
    if (idx >= NROW * DZ) return;
    int d = idx & 63;
    int b = idx >> 16;
    out[idx] = X[idx] - cm[b * DZ + d];
}

// ------------------------------------------------------------------ final epilogue
__global__ void final_kernel(const float* __restrict__ xln, const float* __restrict__ tacc,
                             const float* __restrict__ tbase, const float* __restrict__ tw,
                             const float* __restrict__ pw, const float* __restrict__ pb,
                             float* __restrict__ out) {
    int idx = blockIdx.x * blockDim.x + threadIdx.x;
    if (idx >= BZ * 512) return;
    int t = idx & 511, b = idx >> 9;
    int tt = t + 512;
    float cv = 0.f;
#pragma unroll
    for (int j = 0; j < 3; j++) {
        int ts = (tt + j - 1) & (LZ - 1);
        const float* row = tacc + ((size_t)(b * LZ + ts)) * DZ;
        for (int d = 0; d < DZ; d++) cv += row[d] * tw[d * 3 + j];
    }
    float p = pb[0];
    const float* xr = xln + ((size_t)(b * LZ + tt)) * DZ;
    for (int d = 0; d < DZ; d++) p += xr[d] * pw[d];
    out[idx] = p + cv + tbase[b * LZ + tt];
}

static float* symaddr_f(const void* sym) {
    void* p = nullptr;
    cudaGetSymbolAddress(&p, sym);
    return (float*)p;
}

extern "C" void kernel_launch(void* const* d_in, const int* in_sizes, int n_in,
                              void* d_out, int out_size) {
    const float* x_enc       = (const float*)d_in[0];
    const float* dp_w        = (const float*)d_in[1];
    const float* dp_b        = (const float*)d_in[2];
    const float* emb_enc_w   = (const float*)d_in[3];
    const float* emb_dec_w   = (const float*)d_in[4];
    const float* decomp_w    = (const float*)d_in[5];
    const float* decomp_b    = (const float*)d_in[6];
    const float* enc_attn_w  = (const float*)d_in[7];
    const float* enc_attn_b  = (const float*)d_in[8];
    const float* enc_four_wr = (const float*)d_in[9];
    const float* enc_four_wi = (const float*)d_in[10];
    const float* enc_c1      = (const float*)d_in[11];
    const float* enc_c2      = (const float*)d_in[12];
    const float* enc_ln_g    = (const float*)d_in[13];
    const float* enc_ln_b    = (const float*)d_in[14];
    const float* dec_self_w  = (const float*)d_in[15];
    const float* dec_self_b  = (const float*)d_in[16];
    const float* dec_four_wr = (const float*)d_in[17];
    const float* dec_four_wi = (const float*)d_in[18];
    const float* dec_cross_w = (const float*)d_in[19];
    const float* dec_cross_b = (const float*)d_in[20];
    const float* dec_cross_wr= (const float*)d_in[21];
    const float* dec_cross_wi= (const float*)d_in[22];
    const float* dec_c1      = (const float*)d_in[23];
    const float* dec_c2      = (const float*)d_in[24];
    const float* dec_trend_w = (const float*)d_in[25];
    const float* dec_ln_g    = (const float*)d_in[26];
    const float* dec_ln_b    = (const float*)d_in[27];
    const float* dec_proj_w  = (const float*)d_in[28];
    const float* dec_proj_b  = (const float*)d_in[29];
    float* out = (float*)d_out;

    float* px        = symaddr_f(g_x);
    float* pseas0    = symaddr_f(g_seas0);
    float* ptrend0   = symaddr_f(g_trend0);
    float* pseasinit = symaddr_f(g_seasinit);
    float* ph        = symaddr_f(g_h);
    float* pq        = symaddr_f(g_q);
    float* pqT       = symaddr_f(g_qT);
    float* py        = symaddr_f(g_y);
    float* pa        = symaddr_f(g_a);
    float* pffn      = symaddr_f(g_ffn);
    float* pXf       = symaddr_f(g_Xf);
    float* pXk       = symaddr_f(g_Xk);
    float* psel      = symaddr_f(g_sel);
    float* pqk       = symaddr_f(g_qk);
    float* pxd       = symaddr_f(g_xd);
    float* ptacc     = symaddr_f(g_tacc);
    float* pcm       = symaddr_f(g_cm);
    float* pln       = symaddr_f(g_ln);
    float* pF        = symaddr_f(g_F);
    float* pFi       = symaddr_f(g_Fi);
    float* ptbase    = symaddr_f(g_trendbase);

    dim3 tb(32, 8);
    dim3 tg(32, 2, 64);

    build_tables_kernel<<<512, 256>>>();
    build_pe_kernel<<<256, 256>>>();
    transpose_in_kernel<<<1792, 256>>>(x_enc);
    colmean7_kernel<<<BZ * C7, 256>>>(x_enc);
    decomp7_kernel<<<BZ * C7, LZ>>>(px, decomp_w + 0, decomp_b + 0, pseas0, ptrend0);
    trendbase_kernel<<<256, 256>>>(dp_w, dp_b);
    seasinit_kernel<<<1792, 256>>>();

    embed_kernel<<<16384, 256>>>(px, emb_enc_w, ph);
    for (int l = 0; l < 2; l++) {
        const float* wq = enc_attn_w + (size_t)(l * 4 + 0) * 4096;
        const float* bq = enc_attn_b + (size_t)(l * 4 + 0) * 64;
        const float* wo = enc_attn_w + (size_t)(l * 4 + 3) * 4096;
        const float* bo = enc_attn_b + (size_t)(l * 4 + 3) * 64;
        gemm_tc<0><<<dim3(512, 1), 128>>>(ph, wq, bq, pq, NROW, 64, 64);
        transpose_bld_kernel<<<tg, tb>>>(pq, pqT);
        gemm_tc<0><<<dim3(32, 2), 128>>>(pqT, pF, nullptr, pXf, NHE, 1024, 128);
        mode_mix_kernel<<<1024, 256>>>(pXf, enc_four_wr + (size_t)l * 32768,
                                       enc_four_wi + (size_t)l * 32768, psel, 1.0f);
        gemm_tc<0><<<dim3(32, 16), 128>>>(psel, pFi, nullptr, py, NHE, 128, 1024);
        gemm_tc<0><<<dim3(512, 1), 128>>>(py, wo, bo, pa, NROW, 64, 64);
        decomp64_kernel<<<1024, LZ>>>(ph, pa, decomp_w + (1 + 2 * l) * 4,
                                      decomp_b + (1 + 2 * l) * 4, ph, nullptr, 0);
        gemm_tc<1><<<dim3(512, 4), 128>>>(ph, enc_c1 + (size_t)l * 16384, nullptr, pffn,
                                          NROW, 64, 256);
        gemm_tc<0><<<dim3(512, 1), 128>>>(pffn, enc_c2 + (size_t)l * 16384, nullptr, py,
                                          NROW, 256, 64);
        decomp64_kernel<<<1024, LZ>>>(ph, py, decomp_w + (2 + 2 * l) * 4,
                                      decomp_b + (2 + 2 * l) * 4, ph, nullptr, 0);
    }
    ln_row_kernel<<<16384, 256>>>(ph, enc_ln_g, enc_ln_b, pln);
    colmean_kernel<<<BZ * DZ, 256>>>(pln, pcm);
    subtract_cm_kernel<<<16384, 256>>>(pln, pcm, ph);

    embed_kernel<<<16384, 256>>>(pseasinit, emb_dec_w, pxd);
    gemm_tc<0><<<dim3(512, 1), 128>>>(pxd, dec_self_w + 0, dec_self_b + 0, pq, NROW, 64, 64);
    transpose_bld_kernel<<<tg, tb>>>(pq, pqT);
    gemm_tc<0><<<dim3(32, 2), 128>>>(pqT, pF, nullptr, pXf, NHE, 1024, 128);
    mode_mix_kernel<<<1024, 256>>>(pXf, dec_four_wr, dec_four_wi, psel, 1.0f);
    gemm_tc<0><<<dim3(32, 16), 128>>>(psel, pFi, nullptr, py, NHE, 128, 1024);
    gemm_tc<0><<<dim3(512, 1), 128>>>(py, dec_self_w + 3 * 4096, dec_self_b + 3 * 64, pa,
                                      NROW, 64, 64);
    decomp64_kernel<<<1024, LZ>>>(pxd, pa, decomp_w + 5 * 4, decomp_b + 5 * 4, pxd, ptacc, 0);

    gemm_tc<0><<<dim3(512, 1), 128>>>(pxd, dec_cross_w + 0, dec_cross_b + 0, pq, NROW, 64, 64);
    transpose_bld_kernel<<<tg, tb>>>(pq, pqT);
    gemm_tc<0><<<dim3(32, 2), 128>>>(pqT, pF, nullptr, pXf, NHE, 1024, 128);
    gemm_tc<0><<<dim3(512, 1), 128>>>(ph, dec_cross_w + 1 * 4096, dec_cross_b + 1 * 64, pq,
                                      NROW, 64, 64);
    transpose_bld_kernel<<<tg, tb>>>(pq, pqT);
    gemm_tc<0><<<dim3(32, 2), 128>>>(pqT, pF, nullptr, pXk, NHE, 1024, 128);
    qk_kernel<<<8192, 256>>>(pXf, pXk, pqk);
    qkv_kernel<<<1024, 256>>>(pqk, pXk, pXf);
    mode_mix_kernel<<<1024, 256>>>(pXf, dec_cross_wr, dec_cross_wi, psel, 1.0f / 4096.0f);
    gemm_tc<0><<<dim3(32, 16), 128>>>(psel, pFi, nullptr, py, NHE, 128, 1024);
    gemm_tc<0><<<dim3(512, 1), 128>>>(py, dec_cross_w + 3 * 4096, dec_cross_b + 3 * 64, pa,
                                      NROW, 64, 64);
    decomp64_kernel<<<1024, LZ>>>(pxd, pa, decomp_w + 6 * 4, decomp_b + 6 * 4, pxd, ptacc, 1);

    gemm_tc<1><<<dim3(512, 4), 128>>>(pxd, dec_c1, nullptr, pffn, NROW, 64, 256);
    gemm_tc<0><<<dim3(512, 1), 128>>>(pffn, dec_c2, nullptr, py, NROW, 256, 64);
    decomp64_kernel<<<1024, LZ>>>(pxd, py, decomp_w + 7 * 4, decomp_b + 7 * 4, pxd, ptacc, 1);

    ln_row_kernel<<<16384, 256>>>(pxd, dec_ln_g, dec_ln_b, pln);
    colmean_kernel<<<BZ * DZ, 256>>>(pln, pcm);
    subtract_cm_kernel<<<16384, 256>>>(pln, pcm, pln);
    final_kernel<<<128, 256>>>(pln, ptacc, ptbase, dec_trend_w, dec_proj_w, dec_proj_b, out);
}

// round 6
// speedup vs baseline: 1.8750x; 1.1940x over previous
#include <cuda_runtime.h>
#include <cstdint>

#define BZ 64
#define LZ 1024
#define DZ 64
#define C7 7
#define HZ 8
#define EZ 8
#define MZ 64
#define M2 128
#define DFFD 256
#define NROW (BZ*LZ)
#define NHE  (BZ*DZ)

__device__ float g_x[BZ*LZ*C7];
__device__ float g_seas0[BZ*LZ*C7];
__device__ float g_trend0[BZ*LZ*C7];
__device__ float g_mean7[BZ*C7];
__device__ float g_trendbase[BZ*LZ];
__device__ float g_seasinit[BZ*LZ*C7];
__device__ float g_h[NROW*DZ];
__device__ float g_q[NROW*DZ];
__device__ float g_y[NROW*DZ];
__device__ float g_a[NROW*DZ];
__device__ float g_ffn[NROW*DFFD];
__device__ float g_Xf[NHE*M2];
__device__ float g_Xk[NHE*M2];
__device__ float g_sel[NHE*M2];
__device__ float g_qk[BZ*HZ*MZ*MZ*2];
__device__ float g_xd[NROW*DZ];
__device__ float g_tacc[NROW*DZ];
__device__ float g_cm[BZ*DZ];
__device__ float g_ln[NROW*DZ];
__device__ float g_F[M2*LZ];
__device__ float g_Fi[LZ*M2];
__device__ float g_pe[LZ*DZ];

// ------------------------------------------------------------------ tables
__global__ void build_tables_kernel() {
    int idx = blockIdx.x * blockDim.x + threadIdx.x;
    if (idx >= LZ * M2) return;
    int t = idx >> 7;
    int m2 = idx & 127;
    int m = m2 >> 1;
    int r = (m * t) & (LZ - 1);
    float a = (float)r * (6.28318530717958647692f / (float)LZ);
    float s, c;
    sincosf(a, &s, &c);
    float v = (m2 & 1) ? -s : c;
    g_F[(size_t)m2 * LZ + t] = v;
    float cm = (m == 0) ? 1.f : 2.f;
    g_Fi[(size_t)t * M2 + m2] = v * (cm / (float)LZ);
}

__global__ void build_pe_kernel() {
    int idx = blockIdx.x * blockDim.x + threadIdx.x;
    if (idx >= LZ * DZ) return;
    int o = idx & 63;
    int t = idx >> 6;
    int i2 = o & ~1;
    float div = expf(-(float)i2 * 0.14391156831212793f);
    float arg = (float)t * div;
    g_pe[idx] = (o & 1) ? cosf(arg) : sinf(arg);
}

// ------------------------------------------------------------------ input prep
__global__ void transpose_in_kernel(const float* __restrict__ xe) {
    int idx = blockIdx.x * blockDim.x + threadIdx.x;
    if (idx >= BZ * C7 * LZ) return;
    int t = idx & 1023;
    int c = (idx >> 10) % C7;
    int b = idx / (C7 * LZ);
    g_x[((size_t)(b * LZ + t)) * C7 + c] = xe[idx];
}

__global__ void colmean7_kernel(const float* __restrict__ xe) {
    __shared__ float r[256];
    int bc = blockIdx.x;
    float s = 0.f;
    for (int t = threadIdx.x; t < LZ; t += 256) s += xe[(size_t)bc * LZ + t];
    r[threadIdx.x] = s;
    __syncthreads();
    for (int o = 128; o > 0; o >>= 1) {
        if (threadIdx.x < o) r[threadIdx.x] += r[threadIdx.x + o];
        __syncthreads();
    }
    if (threadIdx.x == 0) g_mean7[bc] = r[0] * (1.f / LZ);
}

// ------------------------------------------------------------------ decomps (warp-shuffle scan)
__global__ void decomp7_kernel(const float* __restrict__ A,
                               const float* __restrict__ w4, const float* __restrict__ b4,
                               float* __restrict__ seas, float* __restrict__ trend) {
    __shared__ float ps[LZ];
    __shared__ float wsum[32];
    __shared__ float sx0, sxN;
    int c = blockIdx.x % C7, b = blockIdx.x / C7;
    int t = threadIdx.x, lane = t & 31, wid = t >> 5;
    size_t idx = ((size_t)(b * LZ + t)) * C7 + c;
    float x = A[idx];
    float s = x;
#pragma unroll
    for (int off = 1; off < 32; off <<= 1) {
        float v = __shfl_up_sync(0xffffffffu, s, off);
        if (lane >= off) s += v;
    }
    if (lane == 31) wsum[wid] = s;
    if (t == 0) sx0 = x;
    if (t == LZ - 1) sxN = x;
    __syncthreads();
    if (wid == 0) {
        float v = wsum[lane];
#pragma unroll
        for (int off = 1; off < 32; off <<= 1) {
            float u = __shfl_up_sync(0xffffffffu, v, off);
            if (lane >= off) v += u;
        }
        wsum[lane] = v;
    }
    __syncthreads();
    if (wid > 0) s += wsum[wid - 1];
    ps[t] = s;
    __syncthreads();
    float x0 = sx0, xN = sxN;
    const int ks[4] = {10, 50, 100, 500};
    float ma[4];
#pragma unroll
    for (int kk = 0; kk < 4; kk++) {
        int k = ks[kk], f = (k - 1) >> 1, e = k >> 1;
        int lo = t - f, hi = t + e;
        int cl = lo < 0 ? 0 : lo, ch = hi > LZ - 1 ? LZ - 1 : hi;
        float sw = ps[ch] - (cl > 0 ? ps[cl - 1] : 0.f)
                 + (float)(cl - lo) * x0 + (float)(hi - ch) * xN;
        ma[kk] = sw / (float)k;
    }
    float z[4], mx = -1e30f;
#pragma unroll
    for (int kk = 0; kk < 4; kk++) { z[kk] = x * w4[kk] + b4[kk]; mx = fmaxf(mx, z[kk]); }
    float se = 0.f, mean = 0.f;
#pragma unroll
    for (int kk = 0; kk < 4; kk++) { float e2 = expf(z[kk] - mx); se += e2; mean += ma[kk] * e2; }
    mean /= se;
    seas[idx] = x - mean;
    trend[idx] = mean;
}

__device__ __forceinline__ float4 f4add(float4 a, float4 b) {
    return make_float4(a.x + b.x, a.y + b.y, a.z + b.z, a.w + b.w);
}

__global__ void decomp64_kernel(const float* __restrict__ A, const float* __restrict__ Bb,
                                const float* __restrict__ w4, const float* __restrict__ b4,
                                float* __restrict__ seas, float* __restrict__ trend, int accum) {
    __shared__ float4 ps[LZ];
    __shared__ float4 wsum[32];
    __shared__ float4 sx0, sxN;
    int c4 = blockIdx.x & 15, b = blockIdx.x >> 4;
    int t = threadIdx.x, lane = t & 31, wid = t >> 5;
    size_t base = ((size_t)(b * LZ + t)) * DZ + c4 * 4;
    float4 x = *reinterpret_cast<const float4*>(A + base);
    if (Bb) {
        float4 y = *reinterpret_cast<const float4*>(Bb + base);
        x = f4add(x, y);
    }
    float4 s = x;
#pragma unroll
    for (int off = 1; off < 32; off <<= 1) {
        float4 v;
        v.x = __shfl_up_sync(0xffffffffu, s.x, off);
        v.y = __shfl_up_sync(0xffffffffu, s.y, off);
        v.z = __shfl_up_sync(0xffffffffu, s.z, off);
        v.w = __shfl_up_sync(0xffffffffu, s.w, off);
        if (lane >= off) s = f4add(s, v);
    }
    if (lane == 31) wsum[wid] = s;
    if (t == 0) sx0 = x;
    if (t == LZ - 1) sxN = x;
    __syncthreads();
    if (wid == 0) {
        float4 v = wsum[lane];
#pragma unroll
        for (int off = 1; off < 32; off <<= 1) {
            float4 u;
            u.x = __shfl_up_sync(0xffffffffu, v.x, off);
            u.y = __shfl_up_sync(0xffffffffu, v.y, off);
            u.z = __shfl_up_sync(0xffffffffu, v.z, off);
            u.w = __shfl_up_sync(0xffffffffu, v.w, off);
            if (lane >= off) v = f4add(v, u);
        }
        wsum[lane] = v;
    }
    __syncthreads();
    if (wid > 0) s = f4add(s, wsum[wid - 1]);
    ps[t] = s;
    __syncthreads();
    float4 x0 = sx0, xN = sxN;
    const int ks[4] = {10, 50, 100, 500};
    float ma[4][4];
#pragma unroll
    for (int kk = 0; kk < 4; kk++) {
        int k = ks[kk], f = (k - 1) >> 1, e = k >> 1;
        int lo = t - f, hi = t + e;
        int cl = lo < 0 ? 0 : lo, ch = hi > LZ - 1 ? LZ - 1 : hi;
        float4 pc = ps[ch];
        float4 pl = make_float4(0.f, 0.f, 0.f, 0.f);
        if (cl > 0) pl = ps[cl - 1];
        float fl = (float)(cl - lo), fr = (float)(hi - ch);
        float inv = 1.f / (float)k;
        ma[kk][0] = (pc.x - pl.x + fl * x0.x + fr * xN.x) * inv;
        ma[kk][1] = (pc.y - pl.y + fl * x0.y + fr * xN.y) * inv;
        ma[kk][2] = (pc.z - pl.z + fl * x0.z + fr * xN.z) * inv;
        ma[kk][3] = (pc.w - pl.w + fl * x0.w + fr * xN.w) * inv;
    }
    float xa[4] = {x.x, x.y, x.z, x.w};
    float so[4], tr[4];
#pragma unroll
    for (int cc = 0; cc < 4; cc++) {
        float z[4], mx = -1e30f;
#pragma unroll
        for (int kk = 0; kk < 4; kk++) { z[kk] = xa[cc] * w4[kk] + b4[kk]; mx = fmaxf(mx, z[kk]); }
        float se = 0.f, mean = 0.f;
#pragma unroll
        for (int kk = 0; kk < 4; kk++) { float e2 = expf(z[kk] - mx); se += e2; mean += ma[kk][cc] * e2; }
        mean /= se;
        so[cc] = xa[cc] - mean;
        tr[cc] = mean;
    }
    *reinterpret_cast<float4*>(seas + base) = make_float4(so[0], so[1], so[2], so[3]);
    if (trend) {
        float4 tv = make_float4(tr[0], tr[1], tr[2], tr[3]);
        if (accum) {
            float4 old = *reinterpret_cast<float4*>(trend + base);
            tv = f4add(tv, old);
        }
        *reinterpret_cast<float4*>(trend + base) = tv;
    }
}

// ------------------------------------------------------------------ trend/seasonal init
__global__ void trendbase_kernel(const float* __restrict__ dpw, const float* __restrict__ dpb) {
    int idx = blockIdx.x * blockDim.x + threadIdx.x;
    if (idx >= BZ * LZ) return;
    int t = idx & 1023, b = idx >> 10;
    float s = dpb[0];
#pragma unroll
    for (int c = 0; c < C7; c++) {
        float v = (t < 512) ? g_trend0[((size_t)(b * LZ + 512 + t)) * C7 + c]
                            : g_mean7[b * C7 + c];
        s += v * dpw[c];
    }
    g_trendbase[idx] = s;
}

__global__ void seasinit_kernel() {
    int idx = blockIdx.x * blockDim.x + threadIdx.x;
    if (idx >= BZ * LZ * C7) return;
    int c = idx % C7;
    int t = (idx / C7) & 1023;
    int b = idx / (C7 * LZ);
    g_seasinit[idx] = (t < 512) ? g_seas0[((size_t)(b * LZ + 512 + t)) * C7 + c] : 0.f;
}

// ------------------------------------------------------------------ embedding
__global__ void embed_kernel(const float* __restrict__ in, const float* __restrict__ w,
                             float* __restrict__ out) {
    int idx = blockIdx.x * blockDim.x + threadIdx.x;
    if (idx >= BZ * LZ * DZ) return;
    int o = idx & 63;
    int t = (idx >> 6) & 1023;
    int b = idx >> 16;
    float s = 0.f;
#pragma unroll
    for (int j = 0; j < 3; j++) {
        int ts = (t + j - 1 + LZ) & (LZ - 1);
        const float* ip = in + ((size_t)(b * LZ + ts)) * C7;
#pragma unroll
        for (int c = 0; c < C7; c++) s += ip[c] * w[(o * C7 + c) * 3 + j];
    }
    out[idx] = s + g_pe[(t << 6) + o];
}

// ------------------------------------------------------------------ tf32 helpers
__device__ __forceinline__ uint32_t to_tf32(float x) {
    uint32_t r;
    asm("cvt.rna.tf32.f32 %0, %1;" : "=r"(r) : "f"(x));
    return r;
}

__device__ __forceinline__ void cpa16(uint32_t s, const float* g) {
    asm volatile("cp.async.ca.shared.global [%0], [%1], 16;" :: "r"(s), "l"(g));
}
__device__ __forceinline__ void cpa_commit() {
    asm volatile("cp.async.commit_group;");
}
__device__ __forceinline__ void cpa_wait1() {
    asm volatile("cp.async.wait_group 1;");
}

// ------------------------------------------------------------------ tf32 GEMM (cp.async 2-stage, dynamic smem)
#define GT_ASTRIDE (128*36)
#define GT_BSTRIDE (64*36)
#define GT_SMEM ((2*GT_ASTRIDE + 2*GT_BSTRIDE) * 4)

template <int ACT>
__global__ __launch_bounds__(128) void gemm_tc(const float* __restrict__ A,
                                               const float* __restrict__ W,
                                               const float* __restrict__ bias,
                                               float* __restrict__ C,
                                               int N, int K, int O) {
    extern __shared__ float dsm[];
    float* As = dsm;                        // [2][128][36]
    float* Bs = dsm + 2 * GT_ASTRIDE;       // [2][64][36]
    const int rb = blockIdx.x * 128;
    const int cb = blockIdx.y * 64;
    const int tid = threadIdx.x;
    const int lane = tid & 31;
    const int w = tid >> 5;
    const int wm = w & 1, wn = w >> 1;
    const int m0 = wm * 64, n0 = wn * 32;
    const int g = lane >> 2, tg = lane & 3;
    const int lrow = tid >> 3;
    const int lcol = (tid & 7) * 4;

    uint32_t sA = (uint32_t)__cvta_generic_to_shared(As);
    uint32_t sB = (uint32_t)__cvta_generic_to_shared(Bs);

    float acc[4][4][4];
#pragma unroll
    for (int mi = 0; mi < 4; mi++)
#pragma unroll
        for (int ni = 0; ni < 4; ni++)
#pragma unroll
            for (int r = 0; r < 4; r++) acc[mi][ni][r] = 0.f;

#pragma unroll
    for (int r = 0; r < 8; r++) {
        int row = lrow + r * 16;
        cpa16(sA + (uint32_t)((row * 36 + lcol) * 4), A + (size_t)(rb + row) * K + lcol);
    }
#pragma unroll
    for (int r = 0; r < 4; r++) {
        int row = lrow + r * 16;
        cpa16(sB + (uint32_t)((row * 36 + lcol) * 4), W + (size_t)(cb + row) * K + lcol);
    }
    cpa_commit();

    int st = 0;
    for (int k0 = 0; k0 < K; k0 += 32, st ^= 1) {
        if (k0 + 32 < K) {
            int nx = st ^ 1;
#pragma unroll
            for (int r = 0; r < 8; r++) {
                int row = lrow + r * 16;
                cpa16(sA + (uint32_t)((nx * GT_ASTRIDE + row * 36 + lcol) * 4),
                      A + (size_t)(rb + row) * K + k0 + 32 + lcol);
            }
#pragma unroll
            for (int r = 0; r < 4; r++) {
                int row = lrow + r * 16;
                cpa16(sB + (uint32_t)((nx * GT_BSTRIDE + row * 36 + lcol) * 4),
                      W + (size_t)(cb + row) * K + k0 + 32 + lcol);
            }
        }
        cpa_commit();
        cpa_wait1();
        __syncthreads();
        const float* Ast = As + st * GT_ASTRIDE;
        const float* Bst = Bs + st * GT_BSTRIDE;
#pragma unroll
        for (int kk = 0; kk < 32; kk += 8) {
            uint32_t a[4][4], bfr[4][2];
#pragma unroll
            for (int mi = 0; mi < 4; mi++) {
                int r = m0 + mi * 16 + g;
                a[mi][0] = to_tf32(Ast[r * 36 + kk + tg]);
                a[mi][1] = to_tf32(Ast[(r + 8) * 36 + kk + tg]);
                a[mi][2] = to_tf32(Ast[r * 36 + kk + tg + 4]);
                a[mi][3] = to_tf32(Ast[(r + 8) * 36 + kk + tg + 4]);
            }
#pragma unroll
            for (int ni = 0; ni < 4; ni++) {
                int c = n0 + ni * 8 + g;
                bfr[ni][0] = to_tf32(Bst[c * 36 + kk + tg]);
                bfr[ni][1] = to_tf32(Bst[c * 36 + kk + tg + 4]);
            }
#pragma unroll
            for (int mi = 0; mi < 4; mi++)
#pragma unroll
                for (int ni = 0; ni < 4; ni++) {
                    asm volatile(
                        "mma.sync.aligned.m16n8k8.row.col.f32.tf32.tf32.f32 "
                        "{%0,%1,%2,%3}, {%4,%5,%6,%7}, {%8,%9}, {%0,%1,%2,%3};"
                        : "+f"(acc[mi][ni][0]), "+f"(acc[mi][ni][1]),
                          "+f"(acc[mi][ni][2]), "+f"(acc[mi][ni][3])
                        : "r"(a[mi][0]), "r"(a[mi][1]), "r"(a[mi][2]), "r"(a[mi][3]),
                          "r"(bfr[ni][0]), "r"(bfr[ni][1]));
                }
        }
        __syncthreads();
    }
#pragma unroll
    for (int mi = 0; mi < 4; mi++) {
        int row0 = rb + m0 + mi * 16 + g;
#pragma unroll
        for (int ni = 0; ni < 4; ni++) {
            int col = cb + n0 + ni * 8 + 2 * tg;
#pragma unroll
            for (int half = 0; half < 2; half++) {
                int row = row0 + half * 8;
                float v0 = acc[mi][ni][half * 2 + 0];
                float v1 = acc[mi][ni][half * 2 + 1];
                if (bias) { v0 += bias[col]; v1 += bias[col + 1]; }
                if (ACT == 1) {
                    v0 = 0.5f * v0 * (1.f + erff(v0 * 0.70710678118654752f));
                    v1 = 0.5f * v1 * (1.f + erff(v1 * 0.70710678118654752f));
                }
                C[(size_t)row * O + col] = v0;
                C[(size_t)row * O + col + 1] = v1;
            }
        }
    }
}

// ------------------------------------------------------------------ DFT GEMM with fused transpose
// X[b*64+he, m2] += sum_t q[b,t,he] * F[m2,t]   (split-K over blockIdx.z)
__global__ __launch_bounds__(128) void gemm_dft(const float* __restrict__ Aq,
                                                const float* __restrict__ F,
                                                float* __restrict__ X) {
    __shared__ float As[64][33];
    __shared__ float Bs[64][36];
    const int b = blockIdx.x;
    const int cb = blockIdx.y * 64;
    const int tbase = blockIdx.z * 256;
    const int tid = threadIdx.x;
    const int lane = tid & 31;
    const int w = tid >> 5;
    const int wm = w & 1, wn = w >> 1;
    const int m0 = wm * 32, n0 = wn * 32;
    const int g = lane >> 2, tg = lane & 3;
    const int lrow = tid >> 3;
    const int lcol = (tid & 7) * 4;

    float acc[2][4][4];
#pragma unroll
    for (int mi = 0; mi < 2; mi++)
#pragma unroll
        for (int ni = 0; ni < 4; ni++)
#pragma unroll
            for (int r = 0; r < 4; r++) acc[mi][ni][r] = 0.f;

    for (int t0 = tbase; t0 < tbase + 256; t0 += 32) {
#pragma unroll
        for (int i = 0; i < 4; i++) {
            int f4 = i * 128 + tid;
            int tl = f4 >> 4;
            int he = (f4 & 15) * 4;
            float4 v = *reinterpret_cast<const float4*>(
                Aq + ((size_t)(b * LZ + t0 + tl)) * DZ + he);
            As[he + 0][tl] = v.x;
            As[he + 1][tl] = v.y;
            As[he + 2][tl] = v.z;
            As[he + 3][tl] = v.w;
        }
#pragma unroll
        for (int r = 0; r < 4; r++) {
            int row = lrow + r * 16;
            *reinterpret_cast<float4*>(&Bs[row][lcol]) =
                *reinterpret_cast<const float4*>(F + (size_t)(cb + row) * LZ + t0 + lcol);
        }
        __syncthreads();
#pragma unroll
        for (int kk = 0; kk < 32; kk += 8) {
            uint32_t a[2][4], bfr[4][2];
#pragma unroll
            for (int mi = 0; mi < 2; mi++) {
                int r = m0 + mi * 16 + g;
                a[mi][0] = to_tf32(As[r][kk + tg]);
                a[mi][1] = to_tf32(As[r + 8][kk + tg]);
                a[mi][2] = to_tf32(As[r][kk + tg + 4]);
                a[mi][3] = to_tf32(As[r + 8][kk + tg + 4]);
            }
#pragma unroll
            for (int ni = 0; ni < 4; ni++) {
                int c = n0 + ni * 8 + g;
                bfr[ni][0] = to_tf32(Bs[c][kk + tg]);
                bfr[ni][1] = to_tf32(Bs[c][kk + tg + 4]);
            }
#pragma unroll
            for (int mi = 0; mi < 2; mi++)
#pragma unroll
                for (int ni = 0; ni < 4; ni++) {
                    asm volatile(
                        "mma.sync.aligned.m16n8k8.row.col.f32.tf32.tf32.f32 "
                        "{%0,%1,%2,%3}, {%4,%5,%6,%7}, {%8,%9}, {%0,%1,%2,%3};"
                        : "+f"(acc[mi][ni][0]), "+f"(acc[mi][ni][1]),
                          "+f"(acc[mi][ni][2]), "+f"(acc[mi][ni][3])
                        : "r"(a[mi][0]), "r"(a[mi][1]), "r"(a[mi][2]), "r"(a[mi][3]),
                          "r"(bfr[ni][0]), "r"(bfr[ni][1]));
                }
        }
        __syncthreads();
    }
#pragma unroll
    for (int mi = 0; mi < 2; mi++) {
        int r0 = m0 + mi * 16 + g;
#pragma unroll
        for (int ni = 0; ni < 4; ni++) {
            int col = cb + n0 + ni * 8 + 2 * tg;
#pragma unroll
            for (int half = 0; half < 2; half++) {
                int row = r0 + half * 8;
                atomicAdd(&X[(size_t)(b * 64 + row) * M2 + col], acc[mi][ni][half * 2 + 0]);
                atomicAdd(&X[(size_t)(b * 64 + row) * M2 + col + 1], acc[mi][ni][half * 2 + 1]);
            }
        }
    }
}

// ------------------------------------------------------------------ mode mixing / cross attn
__global__ void mode_mix_kernel(const float* __restrict__ X, const float* __restrict__ wr,
                                const float* __restrict__ wi, float* __restrict__ sel,
                                float scale) {
    int idx = blockIdx.x * blockDim.x + threadIdx.x;
    if (idx >= BZ * HZ * EZ * MZ) return;
    int m = idx & 63;
    int o = (idx >> 6) & 7;
    int h = (idx >> 9) & 7;
    int b = idx >> 12;
    float ar = 0.f, ai = 0.f;
#pragma unroll
    for (int e = 0; e < 8; e++) {
        int rx = (b * 64 + h * 8 + e) * M2 + 2 * m;
        float xr = X[rx], xi = X[rx + 1];
        int wix = ((h * 8 + e) * 8 + o) * MZ + m;
        float wrv = wr[wix], wiv = wi[wix];
        ar += xr * wrv - xi * wiv;
        ai += xr * wiv + xi * wrv;
    }
    int ro = (b * 64 + h * 8 + o) * M2 + 2 * m;
    sel[ro] = ar * scale;
    sel[ro + 1] = ai * scale;
}

__global__ void qk_kernel(const float* __restrict__ Qf, const float* __restrict__ Kf,
                          float* __restrict__ qk) {
    int idx = blockIdx.x * blockDim.x + threadIdx.x;
    if (idx >= BZ * HZ * MZ * MZ) return;
    int y = idx & 63;
    int x = (idx >> 6) & 63;
    int h = (idx >> 12) & 7;
    int b = idx >> 15;
    float ar = 0.f, ai = 0.f;
#pragma unroll
    for (int e = 0; e < 8; e++) {
        int rq = (b * 64 + h * 8 + e) * M2;
        float qr = Qf[rq + 2 * x], qi = Qf[rq + 2 * x + 1];
        float kr = Kf[rq + 2 * y], ki = Kf[rq + 2 * y + 1];
        ar += qr * kr - qi * ki;
        ai += qr * ki + qi * kr;
    }
    float a2 = 2.f * ar, b2 = 2.f * ai;
    float tr, ti;
    if (fabsf(a2) > 30.f) {
        tr = copysignf(1.f, ar);
        ti = 0.f;
    } else {
        float sn, cs;
        sincosf(b2, &sn, &cs);
        float ex = expf(a2);
        float exi = 1.f / ex;
        float den = 0.5f * (ex + exi) + cs;
        tr = 0.5f * (ex - exi) / den;
        ti = sn / den;
    }
    size_t o = ((size_t)((b * 8 + h) * 64 + x) * 64 + y) * 2;
    qk[o] = tr;
    qk[o + 1] = ti;
}

__global__ void qkv_kernel(const float* __restrict__ qk, const float* __restrict__ Kf,
                           float* __restrict__ out) {
    int idx = blockIdx.x * blockDim.x + threadIdx.x;
    if (idx >= BZ * HZ * EZ * MZ) return;
    int x = idx & 63;
    int e = (idx >> 6) & 7;
    int h = (idx >> 9) & 7;
    int b = idx >> 12;
    const float* qrow = qk + ((size_t)((b * 8 + h) * 64 + x) * 64) * 2;
    const float* krow = Kf + (size_t)(b * 64 + h * 8 + e) * M2;
    float ar = 0.f, ai = 0.f;
    for (int y = 0; y < 64; y++) {
        float qr = qrow[2 * y], qi = qrow[2 * y + 1];
        float kr = krow[2 * y], ki = krow[2 * y + 1];
        ar += qr * kr - qi * ki;
        ai += qr * ki + qi * kr;
    }
    int ro = (b * 64 + h * 8 + e) * M2 + 2 * x;
    out[ro] = ar;
    out[ro + 1] = ai;
}

// ------------------------------------------------------------------ layernorm family
__global__ void ln_row_kernel(const float* __restrict__ X, const float* __restrict__ g,
                              const float* __restrict__ be, float* __restrict__ out) {
    __shared__ float red[256];
    int tid = threadIdx.x;
    int sub = tid >> 6;
    int d = tid & 63;
    int row = blockIdx.x * 4 + sub;
    float v = X[(size_t)row * DZ + d];
    red[tid] = v;
    __syncthreads();
    for (int s = 32; s > 0; s >>= 1) {
        if (d < s) red[tid] += red[tid + s];
        __syncthreads();
    }
    float mu = red[sub * 64] * (1.f / 64.f);
    __syncthreads();
    float dv = v - mu;
    red[tid] = dv * dv;
    __syncthreads();
    for (int s = 32; s > 0; s >>= 1) {
        if (d < s) red[tid] += red[tid + s];
        __syncthreads();
    }
    float var = red[sub * 64] * (1.f / 64.f);
    out[(size_t)row * DZ + d] = dv * rsqrtf(var + 1e-5f) * g[d] + be[d];
}

__global__ void colmean_kernel(const float* __restrict__ X, float* __restrict__ cm) {
    __shared__ float r[256];
    int b = blockIdx.x / DZ, d = blockIdx.x % DZ;
    float s = 0.f;
    for (int t = threadIdx.x; t < LZ; t += 256) s += X[((size_t)(b * LZ + t)) * DZ + d];
    r[threadIdx.x] = s;
    __syncthreads();
    for (int o = 128; o > 0; o >>= 1) {
        if (threadIdx.x < o) r[threadIdx.x] += r[threadIdx.x + o];
        __syncthreads();
    }
    if (threadIdx.x == 0) cm[b * DZ + d] = r[0] * (1.f / LZ);
}

__global__ void subtract_cm_kernel(const float* __restrict__ X, const float* __restrict__ cm,
                                   float* __restrict__ out) {
    int idx = blockIdx.x * blockDim.x + threadIdx.x;
    if (idx >= NROW * DZ) return;
    int d = idx & 63;
    int b = idx >> 16;
    out[idx] = X[idx] - cm[b * DZ + d];
}

// ------------------------------------------------------------------ final epilogue
__global__ void final_kernel(const float* __restrict__ xln, const float* __restrict__ tacc,
                             const float* __restrict__ tbase, const float* __restrict__ tw,
                             const float* __restrict__ pw, const float* __restrict__ pb,
                             float* __restrict__ out) {
    int idx = blockIdx.x * blockDim.x + threadIdx.x;
    if (idx >= BZ * 512) return;
    int t = idx & 511, b = idx >> 9;
    int tt = t + 512;
    float cv = 0.f;
#pragma unroll
    for (int j = 0; j < 3; j++) {
        int ts = (tt + j - 1) & (LZ - 1);
        const float* row = tacc + ((size_t)(b * LZ + ts)) * DZ;
        for (int d = 0; d < DZ; d++) cv += row[d] * tw[d * 3 + j];
    }
    float p = pb[0];
    const float* xr = xln + ((size_t)(b * LZ + tt)) * DZ;
    for (int d = 0; d < DZ; d++) p += xr[d] * pw[d];
    out[idx] = p + cv + tbase[b * LZ + tt];
}

static float* symaddr_f(const void* sym) {
    void* p = nullptr;
    cudaGetSymbolAddress(&p, sym);
    return (float*)p;
}

extern "C" void kernel_launch(void* const* d_in, const int* in_sizes, int n_in,
                              void* d_out, int out_size) {
    const float* x_enc       = (const float*)d_in[0];
    const float* dp_w        = (const float*)d_in[1];
    const float* dp_b        = (const float*)d_in[2];
    const float* emb_enc_w   = (const float*)d_in[3];
    const float* emb_dec_w   = (const float*)d_in[4];
    const float* decomp_w    = (const float*)d_in[5];
    const float* decomp_b    = (const float*)d_in[6];
    const float* enc_attn_w  = (const float*)d_in[7];
    const float* enc_attn_b  = (const float*)d_in[8];
    const float* enc_four_wr = (const float*)d_in[9];
    const float* enc_four_wi = (const float*)d_in[10];
    const float* enc_c1      = (const float*)d_in[11];
    const float* enc_c2      = (const float*)d_in[12];
    const float* enc_ln_g    = (const float*)d_in[13];
    const float* enc_ln_b    = (const float*)d_in[14];
    const float* dec_self_w  = (const float*)d_in[15];
    const float* dec_self_b  = (const float*)d_in[16];
    const float* dec_four_wr = (const float*)d_in[17];
    const float* dec_four_wi = (const float*)d_in[18];
    const float* dec_cross_w = (const float*)d_in[19];
    const float* dec_cross_b = (const float*)d_in[20];
    const float* dec_cross_wr= (const float*)d_in[21];
    const float* dec_cross_wi= (const float*)d_in[22];
    const float* dec_c1      = (const float*)d_in[23];
    const float* dec_c2      = (const float*)d_in[24];
    const float* dec_trend_w = (const float*)d_in[25];
    const float* dec_ln_g    = (const float*)d_in[26];
    const float* dec_ln_b    = (const float*)d_in[27];
    const float* dec_proj_w  = (const float*)d_in[28];
    const float* dec_proj_b  = (const float*)d_in[29];
    float* out = (float*)d_out;

    float* px        = symaddr_f(g_x);
    float* pseas0    = symaddr_f(g_seas0);
    float* ptrend0   = symaddr_f(g_trend0);
    float* pseasinit = symaddr_f(g_seasinit);
    float* ph        = symaddr_f(g_h);
    float* pq        = symaddr_f(g_q);
    float* py        = symaddr_f(g_y);
    float* pa        = symaddr_f(g_a);
    float* pffn      = symaddr_f(g_ffn);
    float* pXf       = symaddr_f(g_Xf);
    float* pXk       = symaddr_f(g_Xk);
    float* psel      = symaddr_f(g_sel);
    float* pqk       = symaddr_f(g_qk);
    float* pxd       = symaddr_f(g_xd);
    float* ptacc     = symaddr_f(g_tacc);
    float* pcm       = symaddr_f(g_cm);
    float* pln       = symaddr_f(g_ln);
    float* pF        = symaddr_f(g_F);
    float* pFi       = symaddr_f(g_Fi);
    float* ptbase    = symaddr_f(g_trendbase);

    cudaFuncSetAttribute(gemm_tc<0>, cudaFuncAttributeMaxDynamicSharedMemorySize, GT_SMEM);
    cudaFuncSetAttribute(gemm_tc<1>, cudaFuncAttributeMaxDynamicSharedMemorySize, GT_SMEM);

    dim3 dftg(BZ, 2, 4);

    build_tables_kernel<<<512, 256>>>();
    build_pe_kernel<<<256, 256>>>();
    transpose_in_kernel<<<1792, 256>>>(x_enc);
    colmean7_kernel<<<BZ * C7, 256>>>(x_enc);
    decomp7_kernel<<<BZ * C7, LZ>>>(px, decomp_w + 0, decomp_b + 0, pseas0, ptrend0);
    trendbase_kernel<<<256, 256>>>(dp_w, dp_b);
    seasinit_kernel<<<1792, 256>>>();

    embed_kernel<<<16384, 256>>>(px, emb_enc_w, ph);
    for (int l = 0; l < 2; l++) {
        const float* wq = enc_attn_w + (size_t)(l * 4 + 0) * 4096;
        const float* bq = enc_attn_b + (size_t)(l * 4 + 0) * 64;
        const float* wo = enc_attn_w + (size_t)(l * 4 + 3) * 4096;
        const float* bo = enc_attn_b + (size_t)(l * 4 + 3) * 64;
        gemm_tc<0><<<dim3(512, 1), 128, GT_SMEM>>>(ph, wq, bq, pq, NROW, 64, 64);
        cudaMemsetAsync(pXf, 0, (size_t)NHE * M2 * sizeof(float));
        gemm_dft<<<dftg, 128>>>(pq, pF, pXf);
        mode_mix_kernel<<<1024, 256>>>(pXf, enc_four_wr + (size_t)l * 32768,
                                       enc_four_wi + (size_t)l * 32768, psel, 1.0f);
        gemm_tc<0><<<dim3(32, 16), 128, GT_SMEM>>>(psel, pFi, nullptr, py, NHE, 128, 1024);
        gemm_tc<0><<<dim3(512, 1), 128, GT_SMEM>>>(py, wo, bo, pa, NROW, 64, 64);
        decomp64_kernel<<<1024, LZ>>>(ph, pa, decomp_w + (1 + 2 * l) * 4,
                                      decomp_b + (1 + 2 * l) * 4, ph, nullptr, 0);
        gemm_tc<1><<<dim3(512, 4), 128, GT_SMEM>>>(ph, enc_c1 + (size_t)l * 16384, nullptr, pffn,
                                                   NROW, 64, 256);
        gemm_tc<0><<<dim3(512, 1), 128, GT_SMEM>>>(pffn, enc_c2 + (size_t)l * 16384, nullptr, py,
                                                   NROW, 256, 64);
        decomp64_kernel<<<1024, LZ>>>(ph, py, decomp_w + (2 + 2 * l) * 4,
                                      decomp_b + (2 + 2 * l) * 4, ph, nullptr, 0);
    }
    ln_row_kernel<<<16384, 256>>>(ph, enc_ln_g, enc_ln_b, pln);
    colmean_kernel<<<BZ * DZ, 256>>>(pln, pcm);
    subtract_cm_kernel<<<16384, 256>>>(pln, pcm, ph);

    embed_kernel<<<16384, 256>>>(pseasinit, emb_dec_w, pxd);
    gemm_tc<0><<<dim3(512, 1), 128, GT_SMEM>>>(pxd, dec_self_w + 0, dec_self_b + 0, pq, NROW, 64, 64);
    cudaMemsetAsync(pXf, 0, (size_t)NHE * M2 * sizeof(float));
    gemm_dft<<<dftg, 128>>>(pq, pF, pXf);
    mode_mix_kernel<<<1024, 256>>>(pXf, dec_four_wr, dec_four_wi, psel, 1.0f);
    gemm_tc<0><<<dim3(32, 16), 128, GT_SMEM>>>(psel, pFi, nullptr, py, NHE, 128, 1024);
    gemm_tc<0><<<dim3(512, 1), 128, GT_SMEM>>>(py, dec_self_w + 3 * 4096, dec_self_b + 3 * 64, pa,
                                               NROW, 64, 64);
    decomp64_kernel<<<1024, LZ>>>(pxd, pa, decomp_w + 5 * 4, decomp_b + 5 * 4, pxd, ptacc, 0);

    gemm_tc<0><<<dim3(512, 1), 128, GT_SMEM>>>(pxd, dec_cross_w + 0, dec_cross_b + 0, pq, NROW, 64, 64);
    cudaMemsetAsync(pXf, 0, (size_t)NHE * M2 * sizeof(float));
    gemm_dft<<<dftg, 128>>>(pq, pF, pXf);
    gemm_tc<0><<<dim3(512, 1), 128, GT_SMEM>>>(ph, dec_cross_w + 1 * 4096, dec_cross_b + 1 * 64, pq,
                                               NROW, 64, 64);
    cudaMemsetAsync(pXk, 0, (size_t)NHE * M2 * sizeof(float));
    gemm_dft<<<dftg, 128>>>(pq, pF, pXk);
    qk_kernel<<<8192, 256>>>(pXf, pXk, pqk);
    qkv_kernel<<<1024, 256>>>(pqk, pXk, pXf);
    mode_mix_kernel<<<1024, 256>>>(pXf, dec_cross_wr, dec_cross_wi, psel, 1.0f / 4096.0f);
    gemm_tc<0><<<dim3(32, 16), 128, GT_SMEM>>>(psel, pFi, nullptr, py, NHE, 128, 1024);
    gemm_tc<0><<<dim3(512, 1), 128, GT_SMEM>>>(py, dec_cross_w + 3 * 4096, dec_cross_b + 3 * 64, pa,
                                               NROW, 64, 64);
    decomp64_kernel<<<1024, LZ>>>(pxd, pa, decomp_w + 6 * 4, decomp_b + 6 * 4, pxd, ptacc, 1);

    gemm_tc<1><<<dim3(512, 4), 128, GT_SMEM>>>(pxd, dec_c1, nullptr, pffn, NROW, 64, 256);
    gemm_tc<0><<<dim3(512, 1), 128, GT_SMEM>>>(pffn, dec_c2, nullptr, py, NROW, 256, 64);
    decomp64_kernel<<<1024, LZ>>>(pxd, py, decomp_w + 7 * 4, decomp_b + 7 * 4, pxd, ptacc, 1);

    ln_row_kernel<<<16384, 256>>>(pxd, dec_ln_g, dec_ln_b, pln);
    colmean_kernel<<<BZ * DZ, 256>>>(pln, pcm);
    subtract_cm_kernel<<<16384, 256>>>(pln, pcm, pln);
    final_kernel<<<128, 256>>>(pln, ptacc, ptbase, dec_trend_w, dec_proj_w, dec_proj_b, out);
}

// round 7
// speedup vs baseline: 1.9083x; 1.0177x over previous
#include <cuda_runtime.h>
#include <cstdint>

#define BZ 64
#define LZ 1024
#define DZ 64
#define C7 7
#define HZ 8
#define EZ 8
#define MZ 64
#define M2 128
#define DFFD 256
#define NROW (BZ*LZ)
#define NHE  (BZ*DZ)

__device__ float g_x[BZ*LZ*C7];
__device__ float g_seas0[BZ*LZ*C7];
__device__ float g_trend0[BZ*LZ*C7];
__device__ float g_mean7[BZ*C7];
__device__ float g_trendbase[BZ*LZ];
__device__ float g_seasinit[BZ*LZ*C7];
__device__ float g_h[NROW*DZ];
__device__ float g_q[NROW*DZ];
__device__ float g_y[NROW*DZ];
__device__ float g_a[NROW*DZ];
__device__ float g_ffn[NROW*DFFD];
__device__ float g_Xf[NHE*M2];
__device__ float g_Xk[NHE*M2];
__device__ float g_sel[NHE*M2];
__device__ float g_qk[BZ*HZ*MZ*MZ*2];
__device__ float g_xd[NROW*DZ];
__device__ float g_tacc[NROW*DZ];
__device__ float g_cm[BZ*DZ];
__device__ float g_ln[NROW*DZ];
__device__ float g_F[M2*LZ];
__device__ float g_Fi[LZ*M2];
__device__ float g_pe[LZ*DZ];

// ------------------------------------------------------------------ tables
__global__ void build_tables_kernel() {
    int idx = blockIdx.x * blockDim.x + threadIdx.x;
    if (idx >= LZ * M2) return;
    int t = idx >> 7;
    int m2 = idx & 127;
    int m = m2 >> 1;
    int r = (m * t) & (LZ - 1);
    float a = (float)r * (6.28318530717958647692f / (float)LZ);
    float s, c;
    sincosf(a, &s, &c);
    float v = (m2 & 1) ? -s : c;
    g_F[(size_t)m2 * LZ + t] = v;
    float cm = (m == 0) ? 1.f : 2.f;
    g_Fi[(size_t)t * M2 + m2] = v * (cm / (float)LZ);
}

__global__ void build_pe_kernel() {
    int idx = blockIdx.x * blockDim.x + threadIdx.x;
    if (idx >= LZ * DZ) return;
    int o = idx & 63;
    int t = idx >> 6;
    int i2 = o & ~1;
    float div = expf(-(float)i2 * 0.14391156831212793f);
    float arg = (float)t * div;
    g_pe[idx] = (o & 1) ? cosf(arg) : sinf(arg);
}

// ------------------------------------------------------------------ input prep
__global__ void transpose_in_kernel(const float* __restrict__ xe) {
    int idx = blockIdx.x * blockDim.x + threadIdx.x;
    if (idx >= BZ * C7 * LZ) return;
    int t = idx & 1023;
    int c = (idx >> 10) % C7;
    int b = idx / (C7 * LZ);
    g_x[((size_t)(b * LZ + t)) * C7 + c] = xe[idx];
}

__global__ void colmean7_kernel(const float* __restrict__ xe) {
    __shared__ float r[256];
    int bc = blockIdx.x;
    float s = 0.f;
    for (int t = threadIdx.x; t < LZ; t += 256) s += xe[(size_t)bc * LZ + t];
    r[threadIdx.x] = s;
    __syncthreads();
    for (int o = 128; o > 0; o >>= 1) {
        if (threadIdx.x < o) r[threadIdx.x] += r[threadIdx.x + o];
        __syncthreads();
    }
    if (threadIdx.x == 0) g_mean7[bc] = r[0] * (1.f / LZ);
}

// ------------------------------------------------------------------ decomp7 (warp-shuffle scan)
__global__ void decomp7_kernel(const float* __restrict__ A,
                               const float* __restrict__ w4, const float* __restrict__ b4,
                               float* __restrict__ seas, float* __restrict__ trend) {
    __shared__ float ps[LZ];
    __shared__ float wsum[32];
    __shared__ float sx0, sxN;
    int c = blockIdx.x % C7, b = blockIdx.x / C7;
    int t = threadIdx.x, lane = t & 31, wid = t >> 5;
    size_t idx = ((size_t)(b * LZ + t)) * C7 + c;
    float x = A[idx];
    float s = x;
#pragma unroll
    for (int off = 1; off < 32; off <<= 1) {
        float v = __shfl_up_sync(0xffffffffu, s, off);
        if (lane >= off) s += v;
    }
    if (lane == 31) wsum[wid] = s;
    if (t == 0) sx0 = x;
    if (t == LZ - 1) sxN = x;
    __syncthreads();
    if (wid == 0) {
        float v = wsum[lane];
#pragma unroll
        for (int off = 1; off < 32; off <<= 1) {
            float u = __shfl_up_sync(0xffffffffu, v, off);
            if (lane >= off) v += u;
        }
        wsum[lane] = v;
    }
    __syncthreads();
    if (wid > 0) s += wsum[wid - 1];
    ps[t] = s;
    __syncthreads();
    float x0 = sx0, xN = sxN;
    const int ks[4] = {10, 50, 100, 500};
    float ma[4];
#pragma unroll
    for (int kk = 0; kk < 4; kk++) {
        int k = ks[kk], f = (k - 1) >> 1, e = k >> 1;
        int lo = t - f, hi = t + e;
        int cl = lo < 0 ? 0 : lo, ch = hi > LZ - 1 ? LZ - 1 : hi;
        float sw = ps[ch] - (cl > 0 ? ps[cl - 1] : 0.f)
                 + (float)(cl - lo) * x0 + (float)(hi - ch) * xN;
        ma[kk] = sw / (float)k;
    }
    float z[4], mx = -1e30f;
#pragma unroll
    for (int kk = 0; kk < 4; kk++) { z[kk] = x * w4[kk] + b4[kk]; mx = fmaxf(mx, z[kk]); }
    float se = 0.f, mean = 0.f;
#pragma unroll
    for (int kk = 0; kk < 4; kk++) { float e2 = expf(z[kk] - mx); se += e2; mean += ma[kk] * e2; }
    mean /= se;
    seas[idx] = x - mean;
    trend[idx] = mean;
}

__device__ __forceinline__ float4 f4add(float4 a, float4 b) {
    return make_float4(a.x + b.x, a.y + b.y, a.z + b.z, a.w + b.w);
}

// ------------------------------------------------------------------ decomp64: 256 threads x 4 t each
__global__ __launch_bounds__(256) void decomp64_kernel(
    const float* __restrict__ A, const float* __restrict__ Bb,
    const float* __restrict__ w4, const float* __restrict__ b4,
    float* __restrict__ seas, float* __restrict__ trend, int accum) {
    __shared__ float4 ps[LZ];
    __shared__ float4 wsum[8];
    __shared__ float4 sedge[2];
    int c4 = blockIdx.x & 15, b = blockIdx.x >> 4;
    int tid = threadIdx.x, lane = tid & 31, wid = tid >> 5;
    int t4 = tid * 4;
    size_t base = ((size_t)(b * LZ + t4)) * DZ + c4 * 4;

    float4 x[4], p[4];
#pragma unroll
    for (int j = 0; j < 4; j++) {
        x[j] = *reinterpret_cast<const float4*>(A + base + (size_t)j * DZ);
        if (Bb) x[j] = f4add(x[j], *reinterpret_cast<const float4*>(Bb + base + (size_t)j * DZ));
    }
    p[0] = x[0];
#pragma unroll
    for (int j = 1; j < 4; j++) p[j] = f4add(p[j - 1], x[j]);

    float4 s = p[3];
#pragma unroll
    for (int off = 1; off < 32; off <<= 1) {
        float4 v;
        v.x = __shfl_up_sync(0xffffffffu, s.x, off);
        v.y = __shfl_up_sync(0xffffffffu, s.y, off);
        v.z = __shfl_up_sync(0xffffffffu, s.z, off);
        v.w = __shfl_up_sync(0xffffffffu, s.w, off);
        if (lane >= off) s = f4add(s, v);
    }
    if (lane == 31) wsum[wid] = s;
    if (tid == 0) sedge[0] = x[0];
    if (tid == 255) sedge[1] = x[3];
    __syncthreads();
    if (wid == 0 && lane < 8) {
        float4 v = wsum[lane];
#pragma unroll
        for (int off = 1; off < 8; off <<= 1) {
            float4 u;
            u.x = __shfl_up_sync(0xffu, v.x, off);
            u.y = __shfl_up_sync(0xffu, v.y, off);
            u.z = __shfl_up_sync(0xffu, v.z, off);
            u.w = __shfl_up_sync(0xffu, v.w, off);
            if (lane >= off) v = f4add(v, u);
        }
        wsum[lane] = v;
    }
    __syncthreads();
    // exclusive base for this thread
    float4 ex = make_float4(0.f, 0.f, 0.f, 0.f);
    if (wid > 0) ex = wsum[wid - 1];
    {
        float4 d;
        d.x = s.x - p[3].x; d.y = s.y - p[3].y; d.z = s.z - p[3].z; d.w = s.w - p[3].w;
        ex = f4add(ex, d);
    }
#pragma unroll
    for (int j = 0; j < 4; j++) ps[t4 + j] = f4add(ex, p[j]);
    __syncthreads();

    float4 x0 = sedge[0], xN = sedge[1];
    const int ks[4] = {10, 50, 100, 500};
#pragma unroll
    for (int j = 0; j < 4; j++) {
        int t = t4 + j;
        float ma[4][4];
#pragma unroll
        for (int kk = 0; kk < 4; kk++) {
            int k = ks[kk], f = (k - 1) >> 1, e = k >> 1;
            int lo = t - f, hi = t + e;
            int cl = lo < 0 ? 0 : lo, ch = hi > LZ - 1 ? LZ - 1 : hi;
            float4 pc = ps[ch];
            float4 pl = make_float4(0.f, 0.f, 0.f, 0.f);
            if (cl > 0) pl = ps[cl - 1];
            float fl = (float)(cl - lo), fr = (float)(hi - ch);
            float inv = 1.f / (float)k;
            ma[kk][0] = (pc.x - pl.x + fl * x0.x + fr * xN.x) * inv;
            ma[kk][1] = (pc.y - pl.y + fl * x0.y + fr * xN.y) * inv;
            ma[kk][2] = (pc.z - pl.z + fl * x0.z + fr * xN.z) * inv;
            ma[kk][3] = (pc.w - pl.w + fl * x0.w + fr * xN.w) * inv;
        }
        float xa[4] = {x[j].x, x[j].y, x[j].z, x[j].w};
        float so[4], tr[4];
#pragma unroll
        for (int cc = 0; cc < 4; cc++) {
            float z[4], mx = -1e30f;
#pragma unroll
            for (int kk = 0; kk < 4; kk++) { z[kk] = xa[cc] * w4[kk] + b4[kk]; mx = fmaxf(mx, z[kk]); }
            float se = 0.f, mean = 0.f;
#pragma unroll
            for (int kk = 0; kk < 4; kk++) { float e2 = expf(z[kk] - mx); se += e2; mean += ma[kk][cc] * e2; }
            mean /= se;
            so[cc] = xa[cc] - mean;
            tr[cc] = mean;
        }
        *reinterpret_cast<float4*>(seas + base + (size_t)j * DZ) =
            make_float4(so[0], so[1], so[2], so[3]);
        if (trend) {
            float4 tv = make_float4(tr[0], tr[1], tr[2], tr[3]);
            if (accum) {
                float4 old = *reinterpret_cast<float4*>(trend + base + (size_t)j * DZ);
                tv = f4add(tv, old);
            }
            *reinterpret_cast<float4*>(trend + base + (size_t)j * DZ) = tv;
        }
    }
}

// ------------------------------------------------------------------ trend/seasonal init
__global__ void trendbase_kernel(const float* __restrict__ dpw, const float* __restrict__ dpb) {
    int idx = blockIdx.x * blockDim.x + threadIdx.x;
    if (idx >= BZ * LZ) return;
    int t = idx & 1023, b = idx >> 10;
    float s = dpb[0];
#pragma unroll
    for (int c = 0; c < C7; c++) {
        float v = (t < 512) ? g_trend0[((size_t)(b * LZ + 512 + t)) * C7 + c]
                            : g_mean7[b * C7 + c];
        s += v * dpw[c];
    }
    g_trendbase[idx] = s;
}

__global__ void seasinit_kernel() {
    int idx = blockIdx.x * blockDim.x + threadIdx.x;
    if (idx >= BZ * LZ * C7) return;
    int c = idx % C7;
    int t = (idx / C7) & 1023;
    int b = idx / (C7 * LZ);
    g_seasinit[idx] = (t < 512) ? g_seas0[((size_t)(b * LZ + 512 + t)) * C7 + c] : 0.f;
}

// ------------------------------------------------------------------ embedding
__global__ void embed_kernel(const float* __restrict__ in, const float* __restrict__ w,
                             float* __restrict__ out) {
    int idx = blockIdx.x * blockDim.x + threadIdx.x;
    if (idx >= BZ * LZ * DZ) return;
    int o = idx & 63;
    int t = (idx >> 6) & 1023;
    int b = idx >> 16;
    float s = 0.f;
#pragma unroll
    for (int j = 0; j < 3; j++) {
        int ts = (t + j - 1 + LZ) & (LZ - 1);
        const float* ip = in + ((size_t)(b * LZ + ts)) * C7;
#pragma unroll
        for (int c = 0; c < C7; c++) s += ip[c] * w[(o * C7 + c) * 3 + j];
    }
    out[idx] = s + g_pe[(t << 6) + o];
}

// ------------------------------------------------------------------ tf32 helpers
__device__ __forceinline__ uint32_t to_tf32(float x) {
    uint32_t r;
    asm("cvt.rna.tf32.f32 %0, %1;" : "=r"(r) : "f"(x));
    return r;
}

__device__ __forceinline__ void cpa16(uint32_t s, const float* g) {
    asm volatile("cp.async.ca.shared.global [%0], [%1], 16;" :: "r"(s), "l"(g));
}
__device__ __forceinline__ void cpa_commit() {
    asm volatile("cp.async.commit_group;");
}
__device__ __forceinline__ void cpa_wait1() {
    asm volatile("cp.async.wait_group 1;");
}

// ------------------------------------------------------------------ tf32 GEMM (cp.async 2-stage, dynamic smem)
#define GT_ASTRIDE (128*36)
#define GT_BSTRIDE (64*36)
#define GT_SMEM ((2*GT_ASTRIDE + 2*GT_BSTRIDE) * 4)

template <int ACT>
__global__ __launch_bounds__(128) void gemm_tc(const float* __restrict__ A,
                                               const float* __restrict__ W,
                                               const float* __restrict__ bias,
                                               float* __restrict__ C,
                                               int N, int K, int O) {
    extern __shared__ float dsm[];
    float* As = dsm;
    float* Bs = dsm + 2 * GT_ASTRIDE;
    const int rb = blockIdx.x * 128;
    const int cb = blockIdx.y * 64;
    const int tid = threadIdx.x;
    const int lane = tid & 31;
    const int w = tid >> 5;
    const int wm = w & 1, wn = w >> 1;
    const int m0 = wm * 64, n0 = wn * 32;
    const int g = lane >> 2, tg = lane & 3;
    const int lrow = tid >> 3;
    const int lcol = (tid & 7) * 4;

    uint32_t sA = (uint32_t)__cvta_generic_to_shared(As);
    uint32_t sB = (uint32_t)__cvta_generic_to_shared(Bs);

    float acc[4][4][4];
#pragma unroll
    for (int mi = 0; mi < 4; mi++)
#pragma unroll
        for (int ni = 0; ni < 4; ni++)
#pragma unroll
            for (int r = 0; r < 4; r++) acc[mi][ni][r] = 0.f;

#pragma unroll
    for (int r = 0; r < 8; r++) {
        int row = lrow + r * 16;
        cpa16(sA + (uint32_t)((row * 36 + lcol) * 4), A + (size_t)(rb + row) * K + lcol);
    }
#pragma unroll
    for (int r = 0; r < 4; r++) {
        int row = lrow + r * 16;
        cpa16(sB + (uint32_t)((row * 36 + lcol) * 4), W + (size_t)(cb + row) * K + lcol);
    }
    cpa_commit();

    int st = 0;
    for (int k0 = 0; k0 < K; k0 += 32, st ^= 1) {
        if (k0 + 32 < K) {
            int nx = st ^ 1;
#pragma unroll
            for (int r = 0; r < 8; r++) {
                int row = lrow + r * 16;
                cpa16(sA + (uint32_t)((nx * GT_ASTRIDE + row * 36 + lcol) * 4),
                      A + (size_t)(rb + row) * K + k0 + 32 + lcol);
            }
#pragma unroll
            for (int r = 0; r < 4; r++) {
                int row = lrow + r * 16;
                cpa16(sB + (uint32_t)((nx * GT_BSTRIDE + row * 36 + lcol) * 4),
                      W + (size_t)(cb + row) * K + k0 + 32 + lcol);
            }
        }
        cpa_commit();
        cpa_wait1();
        __syncthreads();
        const float* Ast = As + st * GT_ASTRIDE;
        const float* Bst = Bs + st * GT_BSTRIDE;
#pragma unroll
        for (int kk = 0; kk < 32; kk += 8) {
            uint32_t a[4][4], bfr[4][2];
#pragma unroll
            for (int mi = 0; mi < 4; mi++) {
                int r = m0 + mi * 16 + g;
                a[mi][0] = to_tf32(Ast[r * 36 + kk + tg]);
                a[mi][1] = to_tf32(Ast[(r + 8) * 36 + kk + tg]);
                a[mi][2] = to_tf32(Ast[r * 36 + kk + tg + 4]);
                a[mi][3] = to_tf32(Ast[(r + 8) * 36 + kk + tg + 4]);
            }
#pragma unroll
            for (int ni = 0; ni < 4; ni++) {
                int c = n0 + ni * 8 + g;
                bfr[ni][0] = to_tf32(Bst[c * 36 + kk + tg]);
                bfr[ni][1] = to_tf32(Bst[c * 36 + kk + tg + 4]);
            }
#pragma unroll
            for (int mi = 0; mi < 4; mi++)
#pragma unroll
                for (int ni = 0; ni < 4; ni++) {
                    asm volatile(
                        "mma.sync.aligned.m16n8k8.row.col.f32.tf32.tf32.f32 "
                        "{%0,%1,%2,%3}, {%4,%5,%6,%7}, {%8,%9}, {%0,%1,%2,%3};"
                        : "+f"(acc[mi][ni][0]), "+f"(acc[mi][ni][1]),
                          "+f"(acc[mi][ni][2]), "+f"(acc[mi][ni][3])
                        : "r"(a[mi][0]), "r"(a[mi][1]), "r"(a[mi][2]), "r"(a[mi][3]),
                          "r"(bfr[ni][0]), "r"(bfr[ni][1]));
                }
        }
        __syncthreads();
    }
#pragma unroll
    for (int mi = 0; mi < 4; mi++) {
        int row0 = rb + m0 + mi * 16 + g;
#pragma unroll
        for (int ni = 0; ni < 4; ni++) {
            int col = cb + n0 + ni * 8 + 2 * tg;
#pragma unroll
            for (int half = 0; half < 2; half++) {
                int row = row0 + half * 8;
                float v0 = acc[mi][ni][half * 2 + 0];
                float v1 = acc[mi][ni][half * 2 + 1];
                if (bias) { v0 += bias[col]; v1 += bias[col + 1]; }
                if (ACT == 1) {
                    v0 = 0.5f * v0 * (1.f + erff(v0 * 0.70710678118654752f));
                    v1 = 0.5f * v1 * (1.f + erff(v1 * 0.70710678118654752f));
                }
                C[(size_t)row * O + col] = v0;
                C[(size_t)row * O + col + 1] = v1;
            }
        }
    }
}

// ------------------------------------------------------------------ DFT GEMM with fused transpose
__device__ __forceinline__ void dft_body(const float* __restrict__ Aq,
                                         const float* __restrict__ F,
                                         float* __restrict__ X,
                                         int b, int cb, int zz) {
    __shared__ float As[64][33];
    __shared__ float Bs[64][36];
    const int tbase = zz * 256;
    const int tid = threadIdx.x;
    const int lane = tid & 31;
    const int w = tid >> 5;
    const int wm = w & 1, wn = w >> 1;
    const int m0 = wm * 32, n0 = wn * 32;
    const int g = lane >> 2, tg = lane & 3;
    const int lrow = tid >> 3;
    const int lcol = (tid & 7) * 4;

    float acc[2][4][4];
#pragma unroll
    for (int mi = 0; mi < 2; mi++)
#pragma unroll
        for (int ni = 0; ni < 4; ni++)
#pragma unroll
            for (int r = 0; r < 4; r++) acc[mi][ni][r] = 0.f;

    for (int t0 = tbase; t0 < tbase + 256; t0 += 32) {
#pragma unroll
        for (int i = 0; i < 4; i++) {
            int f4 = i * 128 + tid;
            int tl = f4 >> 4;
            int he = (f4 & 15) * 4;
            float4 v = *reinterpret_cast<const float4*>(
                Aq + ((size_t)(b * LZ + t0 + tl)) * DZ + he);
            As[he + 0][tl] = v.x;
            As[he + 1][tl] = v.y;
            As[he + 2][tl] = v.z;
            As[he + 3][tl] = v.w;
        }
#pragma unroll
        for (int r = 0; r < 4; r++) {
            int row = lrow + r * 16;
            *reinterpret_cast<float4*>(&Bs[row][lcol]) =
                *reinterpret_cast<const float4*>(F + (size_t)(cb + row) * LZ + t0 + lcol);
        }
        __syncthreads();
#pragma unroll
        for (int kk = 0; kk < 32; kk += 8) {
            uint32_t a[2][4], bfr[4][2];
#pragma unroll
            for (int mi = 0; mi < 2; mi++) {
                int r = m0 + mi * 16 + g;
                a[mi][0] = to_tf32(As[r][kk + tg]);
                a[mi][1] = to_tf32(As[r + 8][kk + tg]);
                a[mi][2] = to_tf32(As[r][kk + tg + 4]);
                a[mi][3] = to_tf32(As[r + 8][kk + tg + 4]);
            }
#pragma unroll
            for (int ni = 0; ni < 4; ni++) {
                int c = n0 + ni * 8 + g;
                bfr[ni][0] = to_tf32(Bs[c][kk + tg]);
                bfr[ni][1] = to_tf32(Bs[c][kk + tg + 4]);
            }
#pragma unroll
            for (int mi = 0; mi < 2; mi++)
#pragma unroll
                for (int ni = 0; ni < 4; ni++) {
                    asm volatile(
                        "mma.sync.aligned.m16n8k8.row.col.f32.tf32.tf32.f32 "
                        "{%0,%1,%2,%3}, {%4,%5,%6,%7}, {%8,%9}, {%0,%1,%2,%3};"
                        : "+f"(acc[mi][ni][0]), "+f"(acc[mi][ni][1]),
                          "+f"(acc[mi][ni][2]), "+f"(acc[mi][ni][3])
                        : "r"(a[mi][0]), "r"(a[mi][1]), "r"(a[mi][2]), "r"(a[mi][3]),
                          "r"(bfr[ni][0]), "r"(bfr[ni][1]));
                }
        }
        __syncthreads();
    }
#pragma unroll
    for (int mi = 0; mi < 2; mi++) {
        int r0 = m0 + mi * 16 + g;
#pragma unroll
        for (int ni = 0; ni < 4; ni++) {
            int col = cb + n0 + ni * 8 + 2 * tg;
#pragma unroll
            for (int half = 0; half < 2; half++) {
                int row = r0 + half * 8;
                atomicAdd(&X[(size_t)(b * 64 + row) * M2 + col], acc[mi][ni][half * 2 + 0]);
                atomicAdd(&X[(size_t)(b * 64 + row) * M2 + col + 1], acc[mi][ni][half * 2 + 1]);
            }
        }
    }
}

__global__ __launch_bounds__(128) void gemm_dft(const float* __restrict__ Aq,
                                                const float* __restrict__ F,
                                                float* __restrict__ X) {
    dft_body(Aq, F, X, blockIdx.x, blockIdx.y * 64, blockIdx.z);
}

__global__ __launch_bounds__(128) void gemm_dft2(const float* __restrict__ Aq1,
                                                 float* __restrict__ X1,
                                                 const float* __restrict__ Aq2,
                                                 float* __restrict__ X2,
                                                 const float* __restrict__ F) {
    int z = blockIdx.z;
    if (z < 4) dft_body(Aq1, F, X1, blockIdx.x, blockIdx.y * 64, z);
    else       dft_body(Aq2, F, X2, blockIdx.x, blockIdx.y * 64, z - 4);
}

// ------------------------------------------------------------------ mode mixing / cross attn
__global__ void mode_mix_kernel(const float* __restrict__ X, const float* __restrict__ wr,
                                const float* __restrict__ wi, float* __restrict__ sel,
                                float scale) {
    int idx = blockIdx.x * blockDim.x + threadIdx.x;
    if (idx >= BZ * HZ * EZ * MZ) return;
    int m = idx & 63;
    int o = (idx >> 6) & 7;
    int h = (idx >> 9) & 7;
    int b = idx >> 12;
    float ar = 0.f, ai = 0.f;
#pragma unroll
    for (int e = 0; e < 8; e++) {
        int rx = (b * 64 + h * 8 + e) * M2 + 2 * m;
        float xr = X[rx], xi = X[rx + 1];
        int wix = ((h * 8 + e) * 8 + o) * MZ + m;
        float wrv = wr[wix], wiv = wi[wix];
        ar += xr * wrv - xi * wiv;
        ai += xr * wiv + xi * wrv;
    }
    int ro = (b * 64 + h * 8 + o) * M2 + 2 * m;
    sel[ro] = ar * scale;
    sel[ro + 1] = ai * scale;
}

// qk with smem-staged tiles: one block per (b,h)
__global__ __launch_bounds__(256) void qk_kernel(const float* __restrict__ Qf,
                                                 const float* __restrict__ Kf,
                                                 float* __restrict__ qk) {
    __shared__ float Qs[8][128];
    __shared__ float Ks[8][128];
    int bh = blockIdx.x;
    int h = bh & 7, b = bh >> 3;
    int tid = threadIdx.x;
    size_t tbase = (size_t)(b * 64 + h * 8) * M2;
#pragma unroll
    for (int i = 0; i < 4; i++) {
        int f = i * 256 + tid;
        int e = f >> 7, c = f & 127;
        Qs[e][c] = Qf[tbase + e * M2 + c];
        Ks[e][c] = Kf[tbase + e * M2 + c];
    }
    __syncthreads();
    int x = tid >> 2;
    int ys = tid & 3;
    size_t obase = ((size_t)(bh * 64 + x) * 64) * 2;
#pragma unroll
    for (int j = 0; j < 16; j++) {
        int y = ys * 16 + j;
        float ar = 0.f, ai = 0.f;
#pragma unroll
        for (int e = 0; e < 8; e++) {
            float qr = Qs[e][2 * x], qi = Qs[e][2 * x + 1];
            float kr = Ks[e][2 * y], ki = Ks[e][2 * y + 1];
            ar += qr * kr - qi * ki;
            ai += qr * ki + qi * kr;
        }
        float a2 = 2.f * ar, b2 = 2.f * ai;
        float tr, ti;
        if (fabsf(a2) > 30.f) {
            tr = copysignf(1.f, ar);
            ti = 0.f;
        } else {
            float sn, cs;
            sincosf(b2, &sn, &cs);
            float ex = expf(a2);
            float exi = 1.f / ex;
            float den = 0.5f * (ex + exi) + cs;
            tr = 0.5f * (ex - exi) / den;
            ti = sn / den;
        }
        qk[obase + 2 * y] = tr;
        qk[obase + 2 * y + 1] = ti;
    }
}

__global__ void qkv_kernel(const float* __restrict__ qk, const float* __restrict__ Kf,
                           float* __restrict__ out) {
    int idx = blockIdx.x * blockDim.x + threadIdx.x;
    if (idx >= BZ * HZ * EZ * MZ) return;
    int x = idx & 63;
    int e = (idx >> 6) & 7;
    int h = (idx >> 9) & 7;
    int b = idx >> 12;
    const float* qrow = qk + ((size_t)((b * 8 + h) * 64 + x) * 64) * 2;
    const float* krow = Kf + (size_t)(b * 64 + h * 8 + e) * M2;
    float ar = 0.f, ai = 0.f;
    for (int y = 0; y < 64; y++) {
        float qr = qrow[2 * y], qi = qrow[2 * y + 1];
        float kr = krow[2 * y], ki = krow[2 * y + 1];
        ar += qr * kr - qi * ki;
        ai += qr * ki + qi * kr;
    }
    int ro = (b * 64 + h * 8 + e) * M2 + 2 * x;
    out[ro] = ar;
    out[ro + 1] = ai;
}

// ------------------------------------------------------------------ layernorm family
__global__ void ln_row_kernel(const float* __restrict__ X, const float* __restrict__ g,
                              const float* __restrict__ be, float* __restrict__ out) {
    __shared__ float red[256];
    int tid = threadIdx.x;
    int sub = tid >> 6;
    int d = tid & 63;
    int row = blockIdx.x * 4 + sub;
    float v = X[(size_t)row * DZ + d];
    red[tid] = v;
    __syncthreads();
    for (int s = 32; s > 0; s >>= 1) {
        if (d < s) red[tid] += red[tid + s];
        __syncthreads();
    }
    float mu = red[sub * 64] * (1.f / 64.f);
    __syncthreads();
    float dv = v - mu;
    red[tid] = dv * dv;
    __syncthreads();
    for (int s = 32; s > 0; s >>= 1) {
        if (d < s) red[tid] += red[tid + s];
        __syncthreads();
    }
    float var = red[sub * 64] * (1.f / 64.f);
    out[(size_t)row * DZ + d] = dv * rsqrtf(var + 1e-5f) * g[d] + be[d];
}

__global__ void colmean_kernel(const float* __restrict__ X, float* __restrict__ cm) {
    __shared__ float r[256];
    int b = blockIdx.x / DZ, d = blockIdx.x % DZ;
    float s = 0.f;
    for (int t = threadIdx.x; t < LZ; t += 256) s += X[((size_t)(b * LZ + t)) * DZ + d];
    r[threadIdx.x] = s;
    __syncthreads();
    for (int o = 128; o > 0; o >>= 1) {
        if (threadIdx.x < o) r[threadIdx.x] += r[threadIdx.x + o];
        __syncthreads();
    }
    if (threadIdx.x == 0) cm[b * DZ + d] = r[0] * (1.f / LZ);
}

__global__ void subtract_cm_kernel(const float* __restrict__ X, const float* __restrict__ cm,
                                   float* __restrict__ out) {
    int idx = blockIdx.x * blockDim.x + threadIdx.x;
    if (idx >= NROW * DZ) return;
    int d = idx & 63;
    int b = idx >> 16;
    out[idx] = X[idx] - cm[b * DZ + d];
}

// ------------------------------------------------------------------ final epilogue
__global__ void final_kernel(const float* __restrict__ xln, const float* __restrict__ tacc,
                             const float* __restrict__ tbase, const float* __restrict__ tw,
                             const float* __restrict__ pw, const float* __restrict__ pb,
                             float* __restrict__ out) {
    int idx = blockIdx.x * blockDim.x + threadIdx.x;
    if (idx >= BZ * 512) return;
    int t = idx & 511, b = idx >> 9;
    int tt = t + 512;
    float cv = 0.f;
#pragma unroll
    for (int j = 0; j < 3; j++) {
        int ts = (tt + j - 1) & (LZ - 1);
        const float* row = tacc + ((size_t)(b * LZ + ts)) * DZ;
        for (int d = 0; d < DZ; d++) cv += row[d] * tw[d * 3 + j];
    }
    float p = pb[0];
    const float* xr = xln + ((size_t)(b * LZ + tt)) * DZ;
    for (int d = 0; d < DZ; d++) p += xr[d] * pw[d];
    out[idx] = p + cv + tbase[b * LZ + tt];
}

static float* symaddr_f(const void* sym) {
    void* p = nullptr;
    cudaGetSymbolAddress(&p, sym);
    return (float*)p;
}

extern "C" void kernel_launch(void* const* d_in, const int* in_sizes, int n_in,
                              void* d_out, int out_size) {
    const float* x_enc       = (const float*)d_in[0];
    const float* dp_w        = (const float*)d_in[1];
    const float* dp_b        = (const float*)d_in[2];
    const float* emb_enc_w   = (const float*)d_in[3];
    const float* emb_dec_w   = (const float*)d_in[4];
    const float* decomp_w    = (const float*)d_in[5];
    const float* decomp_b    = (const float*)d_in[6];
    const float* enc_attn_w  = (const float*)d_in[7];
    const float* enc_attn_b  = (const float*)d_in[8];
    const float* enc_four_wr = (const float*)d_in[9];
    const float* enc_four_wi = (const float*)d_in[10];
    const float* enc_c1      = (const float*)d_in[11];
    const float* enc_c2      = (const float*)d_in[12];
    const float* enc_ln_g    = (const float*)d_in[13];
    const float* enc_ln_b    = (const float*)d_in[14];
    const float* dec_self_w  = (const float*)d_in[15];
    const float* dec_self_b  = (const float*)d_in[16];
    const float* dec_four_wr = (const float*)d_in[17];
    const float* dec_four_wi = (const float*)d_in[18];
    const float* dec_cross_w = (const float*)d_in[19];
    const float* dec_cross_b = (const float*)d_in[20];
    const float* dec_cross_wr= (const float*)d_in[21];
    const float* dec_cross_wi= (const float*)d_in[22];
    const float* dec_c1      = (const float*)d_in[23];
    const float* dec_c2      = (const float*)d_in[24];
    const float* dec_trend_w = (const float*)d_in[25];
    const float* dec_ln_g    = (const float*)d_in[26];
    const float* dec_ln_b    = (const float*)d_in[27];
    const float* dec_proj_w  = (const float*)d_in[28];
    const float* dec_proj_b  = (const float*)d_in[29];
    float* out = (float*)d_out;

    float* px        = symaddr_f(g_x);
    float* pseas0    = symaddr_f(g_seas0);
    float* ptrend0   = symaddr_f(g_trend0);
    float* pseasinit = symaddr_f(g_seasinit);
    float* ph        = symaddr_f(g_h);
    float* pq        = symaddr_f(g_q);
    float* py        = symaddr_f(g_y);
    float* pa        = symaddr_f(g_a);
    float* pffn      = symaddr_f(g_ffn);
    float* pXf       = symaddr_f(g_Xf);
    float* pXk       = symaddr_f(g_Xk);
    float* psel      = symaddr_f(g_sel);
    float* pqk       = symaddr_f(g_qk);
    float* pxd       = symaddr_f(g_xd);
    float* ptacc     = symaddr_f(g_tacc);
    float* pcm       = symaddr_f(g_cm);
    float* pln       = symaddr_f(g_ln);
    float* pF        = symaddr_f(g_F);
    float* pFi       = symaddr_f(g_Fi);
    float* ptbase    = symaddr_f(g_trendbase);

    cudaFuncSetAttribute(gemm_tc<0>, cudaFuncAttributeMaxDynamicSharedMemorySize, GT_SMEM);
    cudaFuncSetAttribute(gemm_tc<1>, cudaFuncAttributeMaxDynamicSharedMemorySize, GT_SMEM);

    dim3 dftg(BZ, 2, 4);
    dim3 dftg2(BZ, 2, 8);

    build_tables_kernel<<<512, 256>>>();
    build_pe_kernel<<<256, 256>>>();
    transpose_in_kernel<<<1792, 256>>>(x_enc);
    colmean7_kernel<<<BZ * C7, 256>>>(x_enc);
    decomp7_kernel<<<BZ * C7, LZ>>>(px, decomp_w + 0, decomp_b + 0, pseas0, ptrend0);
    trendbase_kernel<<<256, 256>>>(dp_w, dp_b);
    seasinit_kernel<<<1792, 256>>>();

    embed_kernel<<<16384, 256>>>(px, emb_enc_w, ph);
    for (int l = 0; l < 2; l++) {
        const float* wq = enc_attn_w + (size_t)(l * 4 + 0) * 4096;
        const float* bq = enc_attn_b + (size_t)(l * 4 + 0) * 64;
        const float* wo = enc_attn_w + (size_t)(l * 4 + 3) * 4096;
        const float* bo = enc_attn_b + (size_t)(l * 4 + 3) * 64;
        gemm_tc<0><<<dim3(512, 1), 128, GT_SMEM>>>(ph, wq, bq, pq, NROW, 64, 64);
        cudaMemsetAsync(pXf, 0, (size_t)NHE * M2 * sizeof(float));
        gemm_dft<<<dftg, 128>>>(pq, pF, pXf);
        mode_mix_kernel<<<1024, 256>>>(pXf, enc_four_wr + (size_t)l * 32768,
                                       enc_four_wi + (size_t)l * 32768, psel, 1.0f);
        gemm_tc<0><<<dim3(32, 16), 128, GT_SMEM>>>(psel, pFi, nullptr, py, NHE, 128, 1024);
        gemm_tc<0><<<dim3(512, 1), 128, GT_SMEM>>>(py, wo, bo, pa, NROW, 64, 64);
        decomp64_kernel<<<1024, 256>>>(ph, pa, decomp_w + (1 + 2 * l) * 4,
                                       decomp_b + (1 + 2 * l) * 4, ph, nullptr, 0);
        gemm_tc<1><<<dim3(512, 4), 128, GT_SMEM>>>(ph, enc_c1 + (size_t)l * 16384, nullptr, pffn,
                                                   NROW, 64, 256);
        gemm_tc<0><<<dim3(512, 1), 128, GT_SMEM>>>(pffn, enc_c2 + (size_t)l * 16384, nullptr, py,
                                                   NROW, 256, 64);
        decomp64_kernel<<<1024, 256>>>(ph, py, decomp_w + (2 + 2 * l) * 4,
                                       decomp_b + (2 + 2 * l) * 4, ph, nullptr, 0);
    }
    ln_row_kernel<<<16384, 256>>>(ph, enc_ln_g, enc_ln_b, pln);
    colmean_kernel<<<BZ * DZ, 256>>>(pln, pcm);
    subtract_cm_kernel<<<16384, 256>>>(pln, pcm, ph);

    embed_kernel<<<16384, 256>>>(pseasinit, emb_dec_w, pxd);
    gemm_tc<0><<<dim3(512, 1), 128, GT_SMEM>>>(pxd, dec_self_w + 0, dec_self_b + 0, pq, NROW, 64, 64);
    cudaMemsetAsync(pXf, 0, (size_t)NHE * M2 * sizeof(float));
    gemm_dft<<<dftg, 128>>>(pq, pF, pXf);
    mode_mix_kernel<<<1024, 256>>>(pXf, dec_four_wr, dec_four_wi, psel, 1.0f);
    gemm_tc<0><<<dim3(32, 16), 128, GT_SMEM>>>(psel, pFi, nullptr, py, NHE, 128, 1024);
    gemm_tc<0><<<dim3(512, 1), 128, GT_SMEM>>>(py, dec_self_w + 3 * 4096, dec_self_b + 3 * 64, pa,
                                               NROW, 64, 64);
    decomp64_kernel<<<1024, 256>>>(pxd, pa, decomp_w + 5 * 4, decomp_b + 5 * 4, pxd, ptacc, 0);

    gemm_tc<0><<<dim3(512, 1), 128, GT_SMEM>>>(pxd, dec_cross_w + 0, dec_cross_b + 0, pq, NROW, 64, 64);
    gemm_tc<0><<<dim3(512, 1), 128, GT_SMEM>>>(ph, dec_cross_w + 1 * 4096, dec_cross_b + 1 * 64, py,
                                               NROW, 64, 64);
    cudaMemsetAsync(pXf, 0, (size_t)NHE * M2 * sizeof(float));
    cudaMemsetAsync(pXk, 0, (size_t)NHE * M2 * sizeof(float));
    gemm_dft2<<<dftg2, 128>>>(pq, pXf, py, pXk, pF);
    qk_kernel<<<512, 256>>>(pXf, pXk, pqk);
    qkv_kernel<<<1024, 256>>>(pqk, pXk, pXf);
    mode_mix_kernel<<<1024, 256>>>(pXf, dec_cross_wr, dec_cross_wi, psel, 1.0f / 4096.0f);
    gemm_tc<0><<<dim3(32, 16), 128, GT_SMEM>>>(psel, pFi, nullptr, py, NHE, 128, 1024);
    gemm_tc<0><<<dim3(512, 1), 128, GT_SMEM>>>(py, dec_cross_w + 3 * 4096, dec_cross_b + 3 * 64, pa,
                                               NROW, 64, 64);
    decomp64_kernel<<<1024, 256>>>(pxd, pa, decomp_w + 6 * 4, decomp_b + 6 * 4, pxd, ptacc, 1);

    gemm_tc<1><<<dim3(512, 4), 128, GT_SMEM>>>(pxd, dec_c1, nullptr, pffn, NROW, 64, 256);
    gemm_tc<0><<<dim3(512, 1), 128, GT_SMEM>>>(pffn, dec_c2, nullptr, py, NROW, 256, 64);
    decomp64_kernel<<<1024, 256>>>(pxd, py, decomp_w + 7 * 4, decomp_b + 7 * 4, pxd, ptacc, 1);

    ln_row_kernel<<<16384, 256>>>(pxd, dec_ln_g, dec_ln_b, pln);
    colmean_kernel<<<BZ * DZ, 256>>>(pln, pcm);
    subtract_cm_kernel<<<16384, 256>>>(pln, pcm, pln);
    final_kernel<<<128, 256>>>(pln, ptacc, ptbase, dec_trend_w, dec_proj_w, dec_proj_b, out);
}

// round 8
// speedup vs baseline: 2.1490x; 1.1262x over previous
#include <cuda_runtime.h>
#include <cstdint>

#define BZ 64
#define LZ 1024
#define DZ 64
#define C7 7
#define HZ 8
#define EZ 8
#define MZ 64
#define M2 128
#define DFFD 256
#define NROW (BZ*LZ)
#define NHE  (BZ*DZ)

__device__ float g_x[BZ*LZ*C7];
__device__ float g_seas0[BZ*LZ*C7];
__device__ float g_trend0[BZ*LZ*C7];
__device__ float g_mean7[BZ*C7];
__device__ float g_trendbase[BZ*LZ];
__device__ float g_seasinit[BZ*LZ*C7];
__device__ float g_h[NROW*DZ];
__device__ float g_y[NROW*DZ];
__device__ float g_a[NROW*DZ];
__device__ float g_ffn[NROW*DFFD];
__device__ float g_Hf[2*NHE*M2];
__device__ float g_Xf[NHE*M2];
__device__ float g_Xk[NHE*M2];
__device__ float g_sel[NHE*M2];
__device__ float g_xd[NROW*DZ];
__device__ float g_tacc[NROW*DZ];
__device__ float g_cm[BZ*DZ];
__device__ float g_ln[NROW*DZ];
__device__ float g_F[M2*LZ];
__device__ float g_Fi[LZ*M2];
__device__ float g_pe[LZ*DZ];

// ------------------------------------------------------------------ tables (DFT + PE fused)
__global__ void build_tables_kernel() {
    int idx = blockIdx.x * blockDim.x + threadIdx.x;
    if (idx < LZ * M2) {
        int t = idx >> 7;
        int m2 = idx & 127;
        int m = m2 >> 1;
        int r = (m * t) & (LZ - 1);
        float a = (float)r * (6.28318530717958647692f / (float)LZ);
        float s, c;
        sincosf(a, &s, &c);
        float v = (m2 & 1) ? -s : c;
        g_F[(size_t)m2 * LZ + t] = v;
        float cm = (m == 0) ? 1.f : 2.f;
        g_Fi[(size_t)t * M2 + m2] = v * (cm / (float)LZ);
    }
    if (idx < LZ * DZ) {
        int o = idx & 63;
        int t = idx >> 6;
        int i2 = o & ~1;
        float div = expf(-(float)i2 * 0.14391156831212793f);
        float arg = (float)t * div;
        g_pe[idx] = (o & 1) ? cosf(arg) : sinf(arg);
    }
}

// ------------------------------------------------------------------ input prep
__global__ void transpose_in_kernel(const float* __restrict__ xe) {
    int idx = blockIdx.x * blockDim.x + threadIdx.x;
    if (idx >= BZ * C7 * LZ) return;
    int t = idx & 1023;
    int c = (idx >> 10) % C7;
    int b = idx / (C7 * LZ);
    g_x[((size_t)(b * LZ + t)) * C7 + c] = xe[idx];
}

__global__ void colmean7_kernel(const float* __restrict__ xe) {
    __shared__ float r[256];
    int bc = blockIdx.x;
    float s = 0.f;
    for (int t = threadIdx.x; t < LZ; t += 256) s += xe[(size_t)bc * LZ + t];
    r[threadIdx.x] = s;
    __syncthreads();
    for (int o = 128; o > 0; o >>= 1) {
        if (threadIdx.x < o) r[threadIdx.x] += r[threadIdx.x + o];
        __syncthreads();
    }
    if (threadIdx.x == 0) g_mean7[bc] = r[0] * (1.f / LZ);
}

// ------------------------------------------------------------------ decomp7
__global__ void decomp7_kernel(const float* __restrict__ A,
                               const float* __restrict__ w4, const float* __restrict__ b4,
                               float* __restrict__ seas, float* __restrict__ trend) {
    __shared__ float ps[LZ];
    __shared__ float wsum[32];
    __shared__ float sx0, sxN;
    int c = blockIdx.x % C7, b = blockIdx.x / C7;
    int t = threadIdx.x, lane = t & 31, wid = t >> 5;
    size_t idx = ((size_t)(b * LZ + t)) * C7 + c;
    float x = A[idx];
    float s = x;
#pragma unroll
    for (int off = 1; off < 32; off <<= 1) {
        float v = __shfl_up_sync(0xffffffffu, s, off);
        if (lane >= off) s += v;
    }
    if (lane == 31) wsum[wid] = s;
    if (t == 0) sx0 = x;
    if (t == LZ - 1) sxN = x;
    __syncthreads();
    if (wid == 0) {
        float v = wsum[lane];
#pragma unroll
        for (int off = 1; off < 32; off <<= 1) {
            float u = __shfl_up_sync(0xffffffffu, v, off);
            if (lane >= off) v += u;
        }
        wsum[lane] = v;
    }
    __syncthreads();
    if (wid > 0) s += wsum[wid - 1];
    ps[t] = s;
    __syncthreads();
    float x0 = sx0, xN = sxN;
    const int ks[4] = {10, 50, 100, 500};
    float ma[4];
#pragma unroll
    for (int kk = 0; kk < 4; kk++) {
        int k = ks[kk], f = (k - 1) >> 1, e = k >> 1;
        int lo = t - f, hi = t + e;
        int cl = lo < 0 ? 0 : lo, ch = hi > LZ - 1 ? LZ - 1 : hi;
        float sw = ps[ch] - (cl > 0 ? ps[cl - 1] : 0.f)
                 + (float)(cl - lo) * x0 + (float)(hi - ch) * xN;
        ma[kk] = sw / (float)k;
    }
    float z[4], mx = -1e30f;
#pragma unroll
    for (int kk = 0; kk < 4; kk++) { z[kk] = x * w4[kk] + b4[kk]; mx = fmaxf(mx, z[kk]); }
    float se = 0.f, mean = 0.f;
#pragma unroll
    for (int kk = 0; kk < 4; kk++) { float e2 = expf(z[kk] - mx); se += e2; mean += ma[kk] * e2; }
    mean /= se;
    seas[idx] = x - mean;
    trend[idx] = mean;
}

__device__ __forceinline__ float4 f4add(float4 a, float4 b) {
    return make_float4(a.x + b.x, a.y + b.y, a.z + b.z, a.w + b.w);
}

// ------------------------------------------------------------------ decomp64: 256 threads x 4 t
__global__ __launch_bounds__(256) void decomp64_kernel(
    const float* __restrict__ A, const float* __restrict__ Bb,
    const float* __restrict__ w4, const float* __restrict__ b4,
    float* __restrict__ seas, float* __restrict__ trend, int accum) {
    __shared__ float4 ps[LZ];
    __shared__ float4 wsum[8];
    __shared__ float4 sedge[2];
    int c4 = blockIdx.x & 15, b = blockIdx.x >> 4;
    int tid = threadIdx.x, lane = tid & 31, wid = tid >> 5;
    int t4 = tid * 4;
    size_t base = ((size_t)(b * LZ + t4)) * DZ + c4 * 4;

    float4 x[4], p[4];
#pragma unroll
    for (int j = 0; j < 4; j++) {
        x[j] = *reinterpret_cast<const float4*>(A + base + (size_t)j * DZ);
        if (Bb) x[j] = f4add(x[j], *reinterpret_cast<const float4*>(Bb + base + (size_t)j * DZ));
    }
    p[0] = x[0];
#pragma unroll
    for (int j = 1; j < 4; j++) p[j] = f4add(p[j - 1], x[j]);

    float4 s = p[3];
#pragma unroll
    for (int off = 1; off < 32; off <<= 1) {
        float4 v;
        v.x = __shfl_up_sync(0xffffffffu, s.x, off);
        v.y = __shfl_up_sync(0xffffffffu, s.y, off);
        v.z = __shfl_up_sync(0xffffffffu, s.z, off);
        v.w = __shfl_up_sync(0xffffffffu, s.w, off);
        if (lane >= off) s = f4add(s, v);
    }
    if (lane == 31) wsum[wid] = s;
    if (tid == 0) sedge[0] = x[0];
    if (tid == 255) sedge[1] = x[3];
    __syncthreads();
    if (wid == 0 && lane < 8) {
        float4 v = wsum[lane];
#pragma unroll
        for (int off = 1; off < 8; off <<= 1) {
            float4 u;
            u.x = __shfl_up_sync(0xffu, v.x, off);
            u.y = __shfl_up_sync(0xffu, v.y, off);
            u.z = __shfl_up_sync(0xffu, v.z, off);
            u.w = __shfl_up_sync(0xffu, v.w, off);
            if (lane >= off) v = f4add(v, u);
        }
        wsum[lane] = v;
    }
    __syncthreads();
    float4 ex = make_float4(0.f, 0.f, 0.f, 0.f);
    if (wid > 0) ex = wsum[wid - 1];
    {
        float4 d;
        d.x = s.x - p[3].x; d.y = s.y - p[3].y; d.z = s.z - p[3].z; d.w = s.w - p[3].w;
        ex = f4add(ex, d);
    }
#pragma unroll
    for (int j = 0; j < 4; j++) ps[t4 + j] = f4add(ex, p[j]);
    __syncthreads();

    float4 x0 = sedge[0], xN = sedge[1];
    const int ks[4] = {10, 50, 100, 500};
#pragma unroll
    for (int j = 0; j < 4; j++) {
        int t = t4 + j;
        float ma[4][4];
#pragma unroll
        for (int kk = 0; kk < 4; kk++) {
            int k = ks[kk], f = (k - 1) >> 1, e = k >> 1;
            int lo = t - f, hi = t + e;
            int cl = lo < 0 ? 0 : lo, ch = hi > LZ - 1 ? LZ - 1 : hi;
            float4 pc = ps[ch];
            float4 pl = make_float4(0.f, 0.f, 0.f, 0.f);
            if (cl > 0) pl = ps[cl - 1];
            float fl = (float)(cl - lo), fr = (float)(hi - ch);
            float inv = 1.f / (float)k;
            ma[kk][0] = (pc.x - pl.x + fl * x0.x + fr * xN.x) * inv;
            ma[kk][1] = (pc.y - pl.y + fl * x0.y + fr * xN.y) * inv;
            ma[kk][2] = (pc.z - pl.z + fl * x0.z + fr * xN.z) * inv;
            ma[kk][3] = (pc.w - pl.w + fl * x0.w + fr * xN.w) * inv;
        }
        float xa[4] = {x[j].x, x[j].y, x[j].z, x[j].w};
        float so[4], tr[4];
#pragma unroll
        for (int cc = 0; cc < 4; cc++) {
            float z[4], mx = -1e30f;
#pragma unroll
            for (int kk = 0; kk < 4; kk++) { z[kk] = xa[cc] * w4[kk] + b4[kk]; mx = fmaxf(mx, z[kk]); }
            float se = 0.f, mean = 0.f;
#pragma unroll
            for (int kk = 0; kk < 4; kk++) { float e2 = expf(z[kk] - mx); se += e2; mean += ma[kk][cc] * e2; }
            mean /= se;
            so[cc] = xa[cc] - mean;
            tr[cc] = mean;
        }
        *reinterpret_cast<float4*>(seas + base + (size_t)j * DZ) =
            make_float4(so[0], so[1], so[2], so[3]);
        if (trend) {
            float4 tv = make_float4(tr[0], tr[1], tr[2], tr[3]);
            if (accum) {
                float4 old = *reinterpret_cast<float4*>(trend + base + (size_t)j * DZ);
                tv = f4add(tv, old);
            }
            *reinterpret_cast<float4*>(trend + base + (size_t)j * DZ) = tv;
        }
    }
}

// ------------------------------------------------------------------ trend/seasonal init
__global__ void trendbase_kernel(const float* __restrict__ dpw, const float* __restrict__ dpb) {
    int idx = blockIdx.x * blockDim.x + threadIdx.x;
    if (idx >= BZ * LZ) return;
    int t = idx & 1023, b = idx >> 10;
    float s = dpb[0];
#pragma unroll
    for (int c = 0; c < C7; c++) {
        float v = (t < 512) ? g_trend0[((size_t)(b * LZ + 512 + t)) * C7 + c]
                            : g_mean7[b * C7 + c];
        s += v * dpw[c];
    }
    g_trendbase[idx] = s;
}

__global__ void seasinit_kernel() {
    int idx = blockIdx.x * blockDim.x + threadIdx.x;
    if (idx >= BZ * LZ * C7) return;
    int c = idx % C7;
    int t = (idx / C7) & 1023;
    int b = idx / (C7 * LZ);
    g_seasinit[idx] = (t < 512) ? g_seas0[((size_t)(b * LZ + 512 + t)) * C7 + c] : 0.f;
}

// ------------------------------------------------------------------ embedding
__global__ void embed_kernel(const float* __restrict__ in, const float* __restrict__ w,
                             float* __restrict__ out) {
    int idx = blockIdx.x * blockDim.x + threadIdx.x;
    if (idx >= BZ * LZ * DZ) return;
    int o = idx & 63;
    int t = (idx >> 6) & 1023;
    int b = idx >> 16;
    float s = 0.f;
#pragma unroll
    for (int j = 0; j < 3; j++) {
        int ts = (t + j - 1 + LZ) & (LZ - 1);
        const float* ip = in + ((size_t)(b * LZ + ts)) * C7;
#pragma unroll
        for (int c = 0; c < C7; c++) s += ip[c] * w[(o * C7 + c) * 3 + j];
    }
    out[idx] = s + g_pe[(t << 6) + o];
}

// ------------------------------------------------------------------ tf32 helpers
__device__ __forceinline__ uint32_t to_tf32(float x) {
    uint32_t r;
    asm("cvt.rna.tf32.f32 %0, %1;" : "=r"(r) : "f"(x));
    return r;
}
__device__ __forceinline__ void cpa16(uint32_t s, const float* g) {
    asm volatile("cp.async.ca.shared.global [%0], [%1], 16;" :: "r"(s), "l"(g));
}
__device__ __forceinline__ void cpa_commit() {
    asm volatile("cp.async.commit_group;");
}
__device__ __forceinline__ void cpa_wait1() {
    asm volatile("cp.async.wait_group 1;");
}

// ------------------------------------------------------------------ tf32 GEMM (cp.async 2-stage, dyn smem)
#define GT_ASTRIDE (128*36)
#define GT_BSTRIDE (64*36)
#define GT_SMEM ((2*GT_ASTRIDE + 2*GT_BSTRIDE) * 4)

template <int ACT>
__global__ __launch_bounds__(128) void gemm_tc(const float* __restrict__ A,
                                               const float* __restrict__ W,
                                               const float* __restrict__ bias,
                                               float* __restrict__ C,
                                               int N, int K, int O) {
    extern __shared__ float dsm[];
    float* As = dsm;
    float* Bs = dsm + 2 * GT_ASTRIDE;
    const int rb = blockIdx.x * 128;
    const int cb = blockIdx.y * 64;
    const int tid = threadIdx.x;
    const int lane = tid & 31;
    const int w = tid >> 5;
    const int wm = w & 1, wn = w >> 1;
    const int m0 = wm * 64, n0 = wn * 32;
    const int g = lane >> 2, tg = lane & 3;
    const int lrow = tid >> 3;
    const int lcol = (tid & 7) * 4;

    uint32_t sA = (uint32_t)__cvta_generic_to_shared(As);
    uint32_t sB = (uint32_t)__cvta_generic_to_shared(Bs);

    float acc[4][4][4];
#pragma unroll
    for (int mi = 0; mi < 4; mi++)
#pragma unroll
        for (int ni = 0; ni < 4; ni++)
#pragma unroll
            for (int r = 0; r < 4; r++) acc[mi][ni][r] = 0.f;

#pragma unroll
    for (int r = 0; r < 8; r++) {
        int row = lrow + r * 16;
        cpa16(sA + (uint32_t)((row * 36 + lcol) * 4), A + (size_t)(rb + row) * K + lcol);
    }
#pragma unroll
    for (int r = 0; r < 4; r++) {
        int row = lrow + r * 16;
        cpa16(sB + (uint32_t)((row * 36 + lcol) * 4), W + (size_t)(cb + row) * K + lcol);
    }
    cpa_commit();

    int st = 0;
    for (int k0 = 0; k0 < K; k0 += 32, st ^= 1) {
        if (k0 + 32 < K) {
            int nx = st ^ 1;
#pragma unroll
            for (int r = 0; r < 8; r++) {
                int row = lrow + r * 16;
                cpa16(sA + (uint32_t)((nx * GT_ASTRIDE + row * 36 + lcol) * 4),
                      A + (size_t)(rb + row) * K + k0 + 32 + lcol);
            }
#pragma unroll
            for (int r = 0; r < 4; r++) {
                int row = lrow + r * 16;
                cpa16(sB + (uint32_t)((nx * GT_BSTRIDE + row * 36 + lcol) * 4),
                      W + (size_t)(cb + row) * K + k0 + 32 + lcol);
            }
        }
        cpa_commit();
        cpa_wait1();
        __syncthreads();
        const float* Ast = As + st * GT_ASTRIDE;
        const float* Bst = Bs + st * GT_BSTRIDE;
#pragma unroll
        for (int kk = 0; kk < 32; kk += 8) {
            uint32_t a[4][4], bfr[4][2];
#pragma unroll
            for (int mi = 0; mi < 4; mi++) {
                int r = m0 + mi * 16 + g;
                a[mi][0] = to_tf32(Ast[r * 36 + kk + tg]);
                a[mi][1] = to_tf32(Ast[(r + 8) * 36 + kk + tg]);
                a[mi][2] = to_tf32(Ast[r * 36 + kk + tg + 4]);
                a[mi][3] = to_tf32(Ast[(r + 8) * 36 + kk + tg + 4]);
            }
#pragma unroll
            for (int ni = 0; ni < 4; ni++) {
                int c = n0 + ni * 8 + g;
                bfr[ni][0] = to_tf32(Bst[c * 36 + kk + tg]);
                bfr[ni][1] = to_tf32(Bst[c * 36 + kk + tg + 4]);
            }
#pragma unroll
            for (int mi = 0; mi < 4; mi++)
#pragma unroll
                for (int ni = 0; ni < 4; ni++) {
                    asm volatile(
                        "mma.sync.aligned.m16n8k8.row.col.f32.tf32.tf32.f32 "
                        "{%0,%1,%2,%3}, {%4,%5,%6,%7}, {%8,%9}, {%0,%1,%2,%3};"
                        : "+f"(acc[mi][ni][0]), "+f"(acc[mi][ni][1]),
                          "+f"(acc[mi][ni][2]), "+f"(acc[mi][ni][3])
                        : "r"(a[mi][0]), "r"(a[mi][1]), "r"(a[mi][2]), "r"(a[mi][3]),
                          "r"(bfr[ni][0]), "r"(bfr[ni][1]));
                }
        }
        __syncthreads();
    }
#pragma unroll
    for (int mi = 0; mi < 4; mi++) {
        int row0 = rb + m0 + mi * 16 + g;
#pragma unroll
        for (int ni = 0; ni < 4; ni++) {
            int col = cb + n0 + ni * 8 + 2 * tg;
#pragma unroll
            for (int half = 0; half < 2; half++) {
                int row = row0 + half * 8;
                float v0 = acc[mi][ni][half * 2 + 0];
                float v1 = acc[mi][ni][half * 2 + 1];
                if (bias) { v0 += bias[col]; v1 += bias[col + 1]; }
                if (ACT == 1) {
                    v0 = 0.5f * v0 * (1.f + erff(v0 * 0.70710678118654752f));
                    v1 = 0.5f * v1 * (1.f + erff(v1 * 0.70710678118654752f));
                }
                C[(size_t)row * O + col] = v0;
                C[(size_t)row * O + col + 1] = v1;
            }
        }
    }
}

// ------------------------------------------------------------------ DFT GEMM with fused transpose
__device__ __forceinline__ void dft_body(const float* __restrict__ Aq,
                                         const float* __restrict__ F,
                                         float* __restrict__ X,
                                         int b, int cb, int zz) {
    __shared__ float As[64][33];
    __shared__ float Bs[64][36];
    const int tbase = zz * 256;
    const int tid = threadIdx.x;
    const int lane = tid & 31;
    const int w = tid >> 5;
    const int wm = w & 1, wn = w >> 1;
    const int m0 = wm * 32, n0 = wn * 32;
    const int g = lane >> 2, tg = lane & 3;
    const int lrow = tid >> 3;
    const int lcol = (tid & 7) * 4;

    float acc[2][4][4];
#pragma unroll
    for (int mi = 0; mi < 2; mi++)
#pragma unroll
        for (int ni = 0; ni < 4; ni++)
#pragma unroll
            for (int r = 0; r < 4; r++) acc[mi][ni][r] = 0.f;

    for (int t0 = tbase; t0 < tbase + 256; t0 += 32) {
#pragma unroll
        for (int i = 0; i < 4; i++) {
            int f4 = i * 128 + tid;
            int tl = f4 >> 4;
            int he = (f4 & 15) * 4;
            float4 v = *reinterpret_cast<const float4*>(
                Aq + ((size_t)(b * LZ + t0 + tl)) * DZ + he);
            As[he + 0][tl] = v.x;
            As[he + 1][tl] = v.y;
            As[he + 2][tl] = v.z;
            As[he + 3][tl] = v.w;
        }
#pragma unroll
        for (int r = 0; r < 4; r++) {
            int row = lrow + r * 16;
            *reinterpret_cast<float4*>(&Bs[row][lcol]) =
                *reinterpret_cast<const float4*>(F + (size_t)(cb + row) * LZ + t0 + lcol);
        }
        __syncthreads();
#pragma unroll
        for (int kk = 0; kk < 32; kk += 8) {
            uint32_t a[2][4], bfr[4][2];
#pragma unroll
            for (int mi = 0; mi < 2; mi++) {
                int r = m0 + mi * 16 + g;
                a[mi][0] = to_tf32(As[r][kk + tg]);
                a[mi][1] = to_tf32(As[r + 8][kk + tg]);
                a[mi][2] = to_tf32(As[r][kk + tg + 4]);
                a[mi][3] = to_tf32(As[r + 8][kk + tg + 4]);
            }
#pragma unroll
            for (int ni = 0; ni < 4; ni++) {
                int c = n0 + ni * 8 + g;
                bfr[ni][0] = to_tf32(Bs[c][kk + tg]);
                bfr[ni][1] = to_tf32(Bs[c][kk + tg + 4]);
            }
#pragma unroll
            for (int mi = 0; mi < 2; mi++)
#pragma unroll
                for (int ni = 0; ni < 4; ni++) {
                    asm volatile(
                        "mma.sync.aligned.m16n8k8.row.col.f32.tf32.tf32.f32 "
                        "{%0,%1,%2,%3}, {%4,%5,%6,%7}, {%8,%9}, {%0,%1,%2,%3};"
                        : "+f"(acc[mi][ni][0]), "+f"(acc[mi][ni][1]),
                          "+f"(acc[mi][ni][2]), "+f"(acc[mi][ni][3])
                        : "r"(a[mi][0]), "r"(a[mi][1]), "r"(a[mi][2]), "r"(a[mi][3]),
                          "r"(bfr[ni][0]), "r"(bfr[ni][1]));
                }
        }
        __syncthreads();
    }
#pragma unroll
    for (int mi = 0; mi < 2; mi++) {
        int r0 = m0 + mi * 16 + g;
#pragma unroll
        for (int ni = 0; ni < 4; ni++) {
            int col = cb + n0 + ni * 8 + 2 * tg;
#pragma unroll
            for (int half = 0; half < 2; half++) {
                int row = r0 + half * 8;
                atomicAdd(&X[(size_t)(b * 64 + row) * M2 + col], acc[mi][ni][half * 2 + 0]);
                atomicAdd(&X[(size_t)(b * 64 + row) * M2 + col + 1], acc[mi][ni][half * 2 + 1]);
            }
        }
    }
}

__global__ __launch_bounds__(128) void gemm_dft(const float* __restrict__ Aq,
                                                const float* __restrict__ F,
                                                float* __restrict__ X) {
    dft_body(Aq, F, X, blockIdx.x, blockIdx.y * 64, blockIdx.z);
}

__global__ __launch_bounds__(128) void gemm_dft2(const float* __restrict__ Aq1,
                                                 float* __restrict__ X1,
                                                 const float* __restrict__ Aq2,
                                                 float* __restrict__ X2,
                                                 const float* __restrict__ F) {
    int z = blockIdx.z;
    if (z < 4) dft_body(Aq1, F, X1, blockIdx.x, blockIdx.y * 64, z);
    else       dft_body(Aq2, F, X2, blockIdx.x, blockIdx.y * 64, z - 4);
}

// ------------------------------------------------------------------ mode-space projection
// Qf[(b*64+he), m2] = sum_d Wq[he,d] * Hf[(b*64+d), m2]  (+ bias*1024 at m2==0)
__global__ __launch_bounds__(256) void modeproj_kernel(const float* __restrict__ Hf,
                                                       const float* __restrict__ Wq,
                                                       const float* __restrict__ bq,
                                                       float* __restrict__ Qf) {
    __shared__ float Hs[64][68];
    __shared__ float Ws[64][68];
    int b = blockIdx.x;
    int mh = blockIdx.y;            // m2 half: [mh*64, mh*64+64)
    int tid = threadIdx.x;
    // load Hf half: 64 rows x 64 m2 (float4)
    for (int i = tid; i < 64 * 16; i += 256) {
        int d = i >> 4;
        int c4 = (i & 15) * 4;
        *reinterpret_cast<float4*>(&Hs[d][c4]) =
            *reinterpret_cast<const float4*>(Hf + ((size_t)(b * 64 + d)) * M2 + mh * 64 + c4);
    }
    for (int i = tid; i < 64 * 16; i += 256) {
        int he = i >> 4;
        int c4 = (i & 15) * 4;
        *reinterpret_cast<float4*>(&Ws[he][c4]) =
            *reinterpret_cast<const float4*>(Wq + he * 64 + c4);
    }
    __syncthreads();
    int he = tid >> 2;
    int mg = tid & 3;
#pragma unroll
    for (int j = 0; j < 16; j++) {
        int ml = mg + 4 * j;        // local m2 (stride-4, bank-friendly)
        float s = 0.f;
#pragma unroll
        for (int d = 0; d < 64; d++) s += Ws[he][d] * Hs[d][ml];
        int m2 = mh * 64 + ml;
        if (m2 == 0) s += bq[he] * 1024.f;
        Qf[((size_t)(b * 64 + he)) * M2 + m2] = s;
    }
}

// ------------------------------------------------------------------ mode mixing
__global__ void mode_mix_kernel(const float* __restrict__ X, const float* __restrict__ wr,
                                const float* __restrict__ wi, float* __restrict__ sel,
                                float scale) {
    int idx = blockIdx.x * blockDim.x + threadIdx.x;
    if (idx >= BZ * HZ * EZ * MZ) return;
    int m = idx & 63;
    int o = (idx >> 6) & 7;
    int h = (idx >> 9) & 7;
    int b = idx >> 12;
    float ar = 0.f, ai = 0.f;
#pragma unroll
    for (int e = 0; e < 8; e++) {
        int rx = (b * 64 + h * 8 + e) * M2 + 2 * m;
        float xr = X[rx], xi = X[rx + 1];
        int wix = ((h * 8 + e) * 8 + o) * MZ + m;
        float wrv = wr[wix], wiv = wi[wix];
        ar += xr * wrv - xi * wiv;
        ai += xr * wiv + xi * wrv;
    }
    int ro = (b * 64 + h * 8 + o) * M2 + 2 * m;
    sel[ro] = ar * scale;
    sel[ro + 1] = ai * scale;
}

// ------------------------------------------------------------------ fused cross attention (qk tanh + qkv)
__global__ __launch_bounds__(256) void qkattn_kernel(const float* __restrict__ Qf,
                                                     const float* __restrict__ Kf,
                                                     float* __restrict__ Xout) {
    __shared__ float Qs[8][128];
    __shared__ float Ks[8][128];
    __shared__ float qks[64][130];
    int bh = blockIdx.x;
    int h = bh & 7, b = bh >> 3;
    int tid = threadIdx.x;
    size_t tbase = (size_t)(b * 64 + h * 8) * M2;
#pragma unroll
    for (int i = 0; i < 4; i++) {
        int f = i * 256 + tid;
        int e = f >> 7, c = f & 127;
        Qs[e][c] = Qf[tbase + e * M2 + c];
        Ks[e][c] = Kf[tbase + e * M2 + c];
    }
    __syncthreads();
    {
        int x = tid >> 2;
        int ys = tid & 3;
#pragma unroll
        for (int j = 0; j < 16; j++) {
            int y = ys * 16 + j;
            float ar = 0.f, ai = 0.f;
#pragma unroll
            for (int e = 0; e < 8; e++) {
                float qr = Qs[e][2 * x], qi = Qs[e][2 * x + 1];
                float kr = Ks[e][2 * y], ki = Ks[e][2 * y + 1];
                ar += qr * kr - qi * ki;
                ai += qr * ki + qi * kr;
            }
            float a2 = 2.f * ar, b2 = 2.f * ai;
            float tr, ti;
            if (fabsf(a2) > 30.f) {
                tr = copysignf(1.f, ar);
                ti = 0.f;
            } else {
                float sn, cs;
                sincosf(b2, &sn, &cs);
                float ex = expf(a2);
                float exi = 1.f / ex;
                float den = 0.5f * (ex + exi) + cs;
                tr = 0.5f * (ex - exi) / den;
                ti = sn / den;
            }
            qks[x][2 * y] = tr;
            qks[x][2 * y + 1] = ti;
        }
    }
    __syncthreads();
    // qkv: out[(b*64+h*8+e), 2x(+1)] = sum_y qk[x,y]*K[e,y]
    {
        int flat0 = tid * 2;
#pragma unroll
        for (int u = 0; u < 2; u++) {
            int flat = flat0 + u;
            int e = flat >> 6, x = flat & 63;
            float ar = 0.f, ai = 0.f;
#pragma unroll 16
            for (int y = 0; y < 64; y++) {
                float qr = qks[x][2 * y], qi = qks[x][2 * y + 1];
                float kr = Ks[e][2 * y], ki = Ks[e][2 * y + 1];
                ar += qr * kr - qi * ki;
                ai += qr * ki + qi * kr;
            }
            Xout[tbase + (size_t)e * M2 + 2 * x] = ar;
            Xout[tbase + (size_t)e * M2 + 2 * x + 1] = ai;
        }
    }
}

// ------------------------------------------------------------------ layernorm family
__global__ void ln_row_kernel(const float* __restrict__ X, const float* __restrict__ g,
                              const float* __restrict__ be, float* __restrict__ out) {
    __shared__ float red[256];
    int tid = threadIdx.x;
    int sub = tid >> 6;
    int d = tid & 63;
    int row = blockIdx.x * 4 + sub;
    float v = X[(size_t)row * DZ + d];
    red[tid] = v;
    __syncthreads();
    for (int s = 32; s > 0; s >>= 1) {
        if (d < s) red[tid] += red[tid + s];
        __syncthreads();
    }
    float mu = red[sub * 64] * (1.f / 64.f);
    __syncthreads();
    float dv = v - mu;
    red[tid] = dv * dv;
    __syncthreads();
    for (int s = 32; s > 0; s >>= 1) {
        if (d < s) red[tid] += red[tid + s];
        __syncthreads();
    }
    float var = red[sub * 64] * (1.f / 64.f);
    out[(size_t)row * DZ + d] = dv * rsqrtf(var + 1e-5f) * g[d] + be[d];
}

__global__ void colmean_kernel(const float* __restrict__ X, float* __restrict__ cm) {
    __shared__ float r[256];
    int b = blockIdx.x / DZ, d = blockIdx.x % DZ;
    float s = 0.f;
    for (int t = threadIdx.x; t < LZ; t += 256) s += X[((size_t)(b * LZ + t)) * DZ + d];
    r[threadIdx.x] = s;
    __syncthreads();
    for (int o = 128; o > 0; o >>= 1) {
        if (threadIdx.x < o) r[threadIdx.x] += r[threadIdx.x + o];
        __syncthreads();
    }
    if (threadIdx.x == 0) cm[b * DZ + d] = r[0] * (1.f / LZ);
}

__global__ void subtract_cm_kernel(const float* __restrict__ X, const float* __restrict__ cm,
                                   float* __restrict__ out) {
    int idx = blockIdx.x * blockDim.x + threadIdx.x;
    if (idx >= NROW * DZ) return;
    int d = idx & 63;
    int b = idx >> 16;
    out[idx] = X[idx] - cm[b * DZ + d];
}

// ------------------------------------------------------------------ final epilogue
__global__ void final_kernel(const float* __restrict__ xln, const float* __restrict__ tacc,
                             const float* __restrict__ tbase, const float* __restrict__ tw,
                             const float* __restrict__ pw, const float* __restrict__ pb,
                             float* __restrict__ out) {
    int idx = blockIdx.x * blockDim.x + threadIdx.x;
    if (idx >= BZ * 512) return;
    int t = idx & 511, b = idx >> 9;
    int tt = t + 512;
    float cv = 0.f;
#pragma unroll
    for (int j = 0; j < 3; j++) {
        int ts = (tt + j - 1) & (LZ - 1);
        const float* row = tacc + ((size_t)(b * LZ + ts)) * DZ;
        for (int d = 0; d < DZ; d++) cv += row[d] * tw[d * 3 + j];
    }
    float p = pb[0];
    const float* xr = xln + ((size_t)(b * LZ + tt)) * DZ;
    for (int d = 0; d < DZ; d++) p += xr[d] * pw[d];
    out[idx] = p + cv + tbase[b * LZ + tt];
}

static float* symaddr_f(const void* sym) {
    void* p = nullptr;
    cudaGetSymbolAddress(&p, sym);
    return (float*)p;
}

extern "C" void kernel_launch(void* const* d_in, const int* in_sizes, int n_in,
                              void* d_out, int out_size) {
    const float* x_enc       = (const float*)d_in[0];
    const float* dp_w        = (const float*)d_in[1];
    const float* dp_b        = (const float*)d_in[2];
    const float* emb_enc_w   = (const float*)d_in[3];
    const float* emb_dec_w   = (const float*)d_in[4];
    const float* decomp_w    = (const float*)d_in[5];
    const float* decomp_b    = (const float*)d_in[6];
    const float* enc_attn_w  = (const float*)d_in[7];
    const float* enc_attn_b  = (const float*)d_in[8];
    const float* enc_four_wr = (const float*)d_in[9];
    const float* enc_four_wi = (const float*)d_in[10];
    const float* enc_c1      = (const float*)d_in[11];
    const float* enc_c2      = (const float*)d_in[12];
    const float* enc_ln_g    = (const float*)d_in[13];
    const float* enc_ln_b    = (const float*)d_in[14];
    const float* dec_self_w  = (const float*)d_in[15];
    const float* dec_self_b  = (const float*)d_in[16];
    const float* dec_four_wr = (const float*)d_in[17];
    const float* dec_four_wi = (const float*)d_in[18];
    const float* dec_cross_w = (const float*)d_in[19];
    const float* dec_cross_b = (const float*)d_in[20];
    const float* dec_cross_wr= (const float*)d_in[21];
    const float* dec_cross_wi= (const float*)d_in[22];
    const float* dec_c1      = (const float*)d_in[23];
    const float* dec_c2      = (const float*)d_in[24];
    const float* dec_trend_w = (const float*)d_in[25];
    const float* dec_ln_g    = (const float*)d_in[26];
    const float* dec_ln_b    = (const float*)d_in[27];
    const float* dec_proj_w  = (const float*)d_in[28];
    const float* dec_proj_b  = (const float*)d_in[29];
    float* out = (float*)d_out;

    float* px        = symaddr_f(g_x);
    float* pseas0    = symaddr_f(g_seas0);
    float* ptrend0   = symaddr_f(g_trend0);
    float* pseasinit = symaddr_f(g_seasinit);
    float* ph        = symaddr_f(g_h);
    float* py        = symaddr_f(g_y);
    float* pa        = symaddr_f(g_a);
    float* pffn      = symaddr_f(g_ffn);
    float* pHf       = symaddr_f(g_Hf);
    float* pHf2      = pHf + (size_t)NHE * M2;
    float* pXf       = symaddr_f(g_Xf);
    float* pXk       = symaddr_f(g_Xk);
    float* psel      = symaddr_f(g_sel);
    float* pxd       = symaddr_f(g_xd);
    float* ptacc     = symaddr_f(g_tacc);
    float* pcm       = symaddr_f(g_cm);
    float* pln       = symaddr_f(g_ln);
    float* pF        = symaddr_f(g_F);
    float* pFi       = symaddr_f(g_Fi);
    float* ptbase    = symaddr_f(g_trendbase);

    cudaFuncSetAttribute(gemm_tc<0>, cudaFuncAttributeMaxDynamicSharedMemorySize, GT_SMEM);
    cudaFuncSetAttribute(gemm_tc<1>, cudaFuncAttributeMaxDynamicSharedMemorySize, GT_SMEM);

    dim3 dftg(BZ, 2, 4);
    dim3 dftg2(BZ, 2, 8);
    dim3 mpg(BZ, 2);

    build_tables_kernel<<<512, 256>>>();
    transpose_in_kernel<<<1792, 256>>>(x_enc);
    colmean7_kernel<<<BZ * C7, 256>>>(x_enc);
    decomp7_kernel<<<BZ * C7, LZ>>>(px, decomp_w + 0, decomp_b + 0, pseas0, ptrend0);
    trendbase_kernel<<<256, 256>>>(dp_w, dp_b);
    seasinit_kernel<<<1792, 256>>>();

    embed_kernel<<<16384, 256>>>(px, emb_enc_w, ph);
    for (int l = 0; l < 2; l++) {
        const float* wq = enc_attn_w + (size_t)(l * 4 + 0) * 4096;
        const float* bq = enc_attn_b + (size_t)(l * 4 + 0) * 64;
        const float* wo = enc_attn_w + (size_t)(l * 4 + 3) * 4096;
        const float* bo = enc_attn_b + (size_t)(l * 4 + 3) * 64;
        cudaMemsetAsync(pHf, 0, (size_t)NHE * M2 * sizeof(float));
        gemm_dft<<<dftg, 128>>>(ph, pF, pHf);
        modeproj_kernel<<<mpg, 256>>>(pHf, wq, bq, pXf);
        mode_mix_kernel<<<1024, 256>>>(pXf, enc_four_wr + (size_t)l * 32768,
                                       enc_four_wi + (size_t)l * 32768, psel, 1.0f);
        gemm_tc<0><<<dim3(32, 16), 128, GT_SMEM>>>(psel, pFi, nullptr, py, NHE, 128, 1024);
        gemm_tc<0><<<dim3(512, 1), 128, GT_SMEM>>>(py, wo, bo, pa, NROW, 64, 64);
        decomp64_kernel<<<1024, 256>>>(ph, pa, decomp_w + (1 + 2 * l) * 4,
                                       decomp_b + (1 + 2 * l) * 4, ph, nullptr, 0);
        gemm_tc<1><<<dim3(512, 4), 128, GT_SMEM>>>(ph, enc_c1 + (size_t)l * 16384, nullptr, pffn,
                                                   NROW, 64, 256);
        gemm_tc<0><<<dim3(512, 1), 128, GT_SMEM>>>(pffn, enc_c2 + (size_t)l * 16384, nullptr, py,
                                                   NROW, 256, 64);
        decomp64_kernel<<<1024, 256>>>(ph, py, decomp_w + (2 + 2 * l) * 4,
                                       decomp_b + (2 + 2 * l) * 4, ph, nullptr, 0);
    }
    ln_row_kernel<<<16384, 256>>>(ph, enc_ln_g, enc_ln_b, pln);
    colmean_kernel<<<BZ * DZ, 256>>>(pln, pcm);
    subtract_cm_kernel<<<16384, 256>>>(pln, pcm, ph);

    embed_kernel<<<16384, 256>>>(pseasinit, emb_dec_w, pxd);
    // decoder self attention
    cudaMemsetAsync(pHf, 0, (size_t)NHE * M2 * sizeof(float));
    gemm_dft<<<dftg, 128>>>(pxd, pF, pHf);
    modeproj_kernel<<<mpg, 256>>>(pHf, dec_self_w + 0, dec_self_b + 0, pXf);
    mode_mix_kernel<<<1024, 256>>>(pXf, dec_four_wr, dec_four_wi, psel, 1.0f);
    gemm_tc<0><<<dim3(32, 16), 128, GT_SMEM>>>(psel, pFi, nullptr, py, NHE, 128, 1024);
    gemm_tc<0><<<dim3(512, 1), 128, GT_SMEM>>>(py, dec_self_w + 3 * 4096, dec_self_b + 3 * 64, pa,
                                               NROW, 64, 64);
    decomp64_kernel<<<1024, 256>>>(pxd, pa, decomp_w + 5 * 4, decomp_b + 5 * 4, pxd, ptacc, 0);

    // decoder cross attention
    cudaMemsetAsync(pHf, 0, (size_t)2 * NHE * M2 * sizeof(float));
    gemm_dft2<<<dftg2, 128>>>(pxd, pHf, ph, pHf2, pF);
    modeproj_kernel<<<mpg, 256>>>(pHf, dec_cross_w + 0, dec_cross_b + 0, pXf);
    modeproj_kernel<<<mpg, 256>>>(pHf2, dec_cross_w + 1 * 4096, dec_cross_b + 1 * 64, pXk);
    qkattn_kernel<<<512, 256>>>(pXf, pXk, pXf);
    mode_mix_kernel<<<1024, 256>>>(pXf, dec_cross_wr, dec_cross_wi, psel, 1.0f / 4096.0f);
    gemm_tc<0><<<dim3(32, 16), 128, GT_SMEM>>>(psel, pFi, nullptr, py, NHE, 128, 1024);
    gemm_tc<0><<<dim3(512, 1), 128, GT_SMEM>>>(py, dec_cross_w + 3 * 4096, dec_cross_b + 3 * 64, pa,
                                               NROW, 64, 64);
    decomp64_kernel<<<1024, 256>>>(pxd, pa, decomp_w + 6 * 4, decomp_b + 6 * 4, pxd, ptacc, 1);

    gemm_tc<1><<<dim3(512, 4), 128, GT_SMEM>>>(pxd, dec_c1, nullptr, pffn, NROW, 64, 256);
    gemm_tc<0><<<dim3(512, 1), 128, GT_SMEM>>>(pffn, dec_c2, nullptr, py, NROW, 256, 64);
    decomp64_kernel<<<1024, 256>>>(pxd, py, decomp_w + 7 * 4, decomp_b + 7 * 4, pxd, ptacc, 1);

    ln_row_kernel<<<16384, 256>>>(pxd, dec_ln_g, dec_ln_b, pln);
    colmean_kernel<<<BZ * DZ, 256>>>(pln, pcm);
    subtract_cm_kernel<<<16384, 256>>>(pln, pcm, pln);
    final_kernel<<<128, 256>>>(pln, ptacc, ptbase, dec_trend_w, dec_proj_w, dec_proj_b, out);
}

// round 9
// speedup vs baseline: 2.1898x; 1.0190x over previous
#include <cuda_runtime.h>
#include <cstdint>

#define BZ 64
#define LZ 1024
#define DZ 64
#define C7 7
#define HZ 8
#define EZ 8
#define MZ 64
#define M2 128
#define DFFD 256
#define NROW (BZ*LZ)
#define NHE  (BZ*DZ)

__device__ float g_x[BZ*LZ*C7];
__device__ float g_seas0[BZ*LZ*C7];
__device__ float g_trend0[BZ*LZ*C7];
__device__ float g_mean7[BZ*C7];
__device__ float g_trendbase[BZ*LZ];
__device__ float g_seasinit[BZ*LZ*C7];
__device__ float g_h[NROW*DZ];
__device__ float g_y[NROW*DZ];
__device__ float g_a[NROW*DZ];
__device__ float g_ffn[NROW*DFFD];
__device__ float g_Hf[2*NHE*M2];
__device__ float g_Xf[NHE*M2];
__device__ float g_Xk[NHE*M2];
__device__ float g_sel[NHE*M2];
__device__ float g_xd[NROW*DZ];
__device__ float g_tacc[NROW*DZ];
__device__ float g_cm[BZ*DZ];
__device__ float g_cm2[BZ*DZ];
__device__ float g_ln[NROW*DZ];
__device__ float g_F[M2*LZ];
__device__ float g_Fi[LZ*M2];
__device__ float g_pe[LZ*DZ];

// ------------------------------------------------------------------ tables
__global__ void build_tables_kernel() {
    int idx = blockIdx.x * blockDim.x + threadIdx.x;
    if (idx < LZ * M2) {
        int t = idx >> 7;
        int m2 = idx & 127;
        int m = m2 >> 1;
        int r = (m * t) & (LZ - 1);
        float a = (float)r * (6.28318530717958647692f / (float)LZ);
        float s, c;
        sincosf(a, &s, &c);
        float v = (m2 & 1) ? -s : c;
        g_F[(size_t)m2 * LZ + t] = v;
        float cm = (m == 0) ? 1.f : 2.f;
        g_Fi[(size_t)t * M2 + m2] = v * (cm / (float)LZ);
    }
    if (idx < LZ * DZ) {
        int o = idx & 63;
        int t = idx >> 6;
        int i2 = o & ~1;
        float div = expf(-(float)i2 * 0.14391156831212793f);
        float arg = (float)t * div;
        g_pe[idx] = (o & 1) ? cosf(arg) : sinf(arg);
    }
}

// ------------------------------------------------------------------ input prep
__global__ void transpose_in_kernel(const float* __restrict__ xe) {
    int idx = blockIdx.x * blockDim.x + threadIdx.x;
    if (idx >= BZ * C7 * LZ) return;
    int t = idx & 1023;
    int c = (idx >> 10) % C7;
    int b = idx / (C7 * LZ);
    g_x[((size_t)(b * LZ + t)) * C7 + c] = xe[idx];
}

__global__ void colmean7_kernel(const float* __restrict__ xe) {
    __shared__ float r[256];
    int bc = blockIdx.x;
    float s = 0.f;
    for (int t = threadIdx.x; t < LZ; t += 256) s += xe[(size_t)bc * LZ + t];
    r[threadIdx.x] = s;
    __syncthreads();
    for (int o = 128; o > 0; o >>= 1) {
        if (threadIdx.x < o) r[threadIdx.x] += r[threadIdx.x + o];
        __syncthreads();
    }
    if (threadIdx.x == 0) g_mean7[bc] = r[0] * (1.f / LZ);
}

// ------------------------------------------------------------------ decomp7
__global__ void decomp7_kernel(const float* __restrict__ A,
                               const float* __restrict__ w4, const float* __restrict__ b4,
                               float* __restrict__ seas, float* __restrict__ trend) {
    __shared__ float ps[LZ];
    __shared__ float wsum[32];
    __shared__ float sx0, sxN;
    int c = blockIdx.x % C7, b = blockIdx.x / C7;
    int t = threadIdx.x, lane = t & 31, wid = t >> 5;
    size_t idx = ((size_t)(b * LZ + t)) * C7 + c;
    float x = A[idx];
    float s = x;
#pragma unroll
    for (int off = 1; off < 32; off <<= 1) {
        float v = __shfl_up_sync(0xffffffffu, s, off);
        if (lane >= off) s += v;
    }
    if (lane == 31) wsum[wid] = s;
    if (t == 0) sx0 = x;
    if (t == LZ - 1) sxN = x;
    __syncthreads();
    if (wid == 0) {
        float v = wsum[lane];
#pragma unroll
        for (int off = 1; off < 32; off <<= 1) {
            float u = __shfl_up_sync(0xffffffffu, v, off);
            if (lane >= off) v += u;
        }
        wsum[lane] = v;
    }
    __syncthreads();
    if (wid > 0) s += wsum[wid - 1];
    ps[t] = s;
    __syncthreads();
    float x0 = sx0, xN = sxN;
    const int ks[4] = {10, 50, 100, 500};
    float ma[4];
#pragma unroll
    for (int kk = 0; kk < 4; kk++) {
        int k = ks[kk], f = (k - 1) >> 1, e = k >> 1;
        int lo = t - f, hi = t + e;
        int cl = lo < 0 ? 0 : lo, ch = hi > LZ - 1 ? LZ - 1 : hi;
        float sw = ps[ch] - (cl > 0 ? ps[cl - 1] : 0.f)
                 + (float)(cl - lo) * x0 + (float)(hi - ch) * xN;
        ma[kk] = sw / (float)k;
    }
    float z[4], mx = -1e30f;
#pragma unroll
    for (int kk = 0; kk < 4; kk++) { z[kk] = x * w4[kk] + b4[kk]; mx = fmaxf(mx, z[kk]); }
    float se = 0.f, mean = 0.f;
#pragma unroll
    for (int kk = 0; kk < 4; kk++) { float e2 = expf(z[kk] - mx); se += e2; mean += ma[kk] * e2; }
    mean /= se;
    seas[idx] = x - mean;
    trend[idx] = mean;
}

__device__ __forceinline__ float4 f4add(float4 a, float4 b) {
    return make_float4(a.x + b.x, a.y + b.y, a.z + b.z, a.w + b.w);
}

// ------------------------------------------------------------------ decomp64
__global__ __launch_bounds__(256) void decomp64_kernel(
    const float* __restrict__ A, const float* __restrict__ Bb,
    const float* __restrict__ w4, const float* __restrict__ b4,
    float* __restrict__ seas, float* __restrict__ trend, int accum) {
    __shared__ float4 ps[LZ];
    __shared__ float4 wsum[8];
    __shared__ float4 sedge[2];
    int c4 = blockIdx.x & 15, b = blockIdx.x >> 4;
    int tid = threadIdx.x, lane = tid & 31, wid = tid >> 5;
    int t4 = tid * 4;
    size_t base = ((size_t)(b * LZ + t4)) * DZ + c4 * 4;

    float4 x[4], p[4];
#pragma unroll
    for (int j = 0; j < 4; j++) {
        x[j] = *reinterpret_cast<const float4*>(A + base + (size_t)j * DZ);
        if (Bb) x[j] = f4add(x[j], *reinterpret_cast<const float4*>(Bb + base + (size_t)j * DZ));
    }
    p[0] = x[0];
#pragma unroll
    for (int j = 1; j < 4; j++) p[j] = f4add(p[j - 1], x[j]);

    float4 s = p[3];
#pragma unroll
    for (int off = 1; off < 32; off <<= 1) {
        float4 v;
        v.x = __shfl_up_sync(0xffffffffu, s.x, off);
        v.y = __shfl_up_sync(0xffffffffu, s.y, off);
        v.z = __shfl_up_sync(0xffffffffu, s.z, off);
        v.w = __shfl_up_sync(0xffffffffu, s.w, off);
        if (lane >= off) s = f4add(s, v);
    }
    if (lane == 31) wsum[wid] = s;
    if (tid == 0) sedge[0] = x[0];
    if (tid == 255) sedge[1] = x[3];
    __syncthreads();
    if (wid == 0 && lane < 8) {
        float4 v = wsum[lane];
#pragma unroll
        for (int off = 1; off < 8; off <<= 1) {
            float4 u;
            u.x = __shfl_up_sync(0xffu, v.x, off);
            u.y = __shfl_up_sync(0xffu, v.y, off);
            u.z = __shfl_up_sync(0xffu, v.z, off);
            u.w = __shfl_up_sync(0xffu, v.w, off);
            if (lane >= off) v = f4add(v, u);
        }
        wsum[lane] = v;
    }
    __syncthreads();
    float4 ex = make_float4(0.f, 0.f, 0.f, 0.f);
    if (wid > 0) ex = wsum[wid - 1];
    {
        float4 d;
        d.x = s.x - p[3].x; d.y = s.y - p[3].y; d.z = s.z - p[3].z; d.w = s.w - p[3].w;
        ex = f4add(ex, d);
    }
#pragma unroll
    for (int j = 0; j < 4; j++) ps[t4 + j] = f4add(ex, p[j]);
    __syncthreads();

    float4 x0 = sedge[0], xN = sedge[1];
    const int ks[4] = {10, 50, 100, 500};
#pragma unroll
    for (int j = 0; j < 4; j++) {
        int t = t4 + j;
        float ma[4][4];
#pragma unroll
        for (int kk = 0; kk < 4; kk++) {
            int k = ks[kk], f = (k - 1) >> 1, e = k >> 1;
            int lo = t - f, hi = t + e;
            int cl = lo < 0 ? 0 : lo, ch = hi > LZ - 1 ? LZ - 1 : hi;
            float4 pc = ps[ch];
            float4 pl = make_float4(0.f, 0.f, 0.f, 0.f);
            if (cl > 0) pl = ps[cl - 1];
            float fl = (float)(cl - lo), fr = (float)(hi - ch);
            float inv = 1.f / (float)k;
            ma[kk][0] = (pc.x - pl.x + fl * x0.x + fr * xN.x) * inv;
            ma[kk][1] = (pc.y - pl.y + fl * x0.y + fr * xN.y) * inv;
            ma[kk][2] = (pc.z - pl.z + fl * x0.z + fr * xN.z) * inv;
            ma[kk][3] = (pc.w - pl.w + fl * x0.w + fr * xN.w) * inv;
        }
        float xa[4] = {x[j].x, x[j].y, x[j].z, x[j].w};
        float so[4], tr[4];
#pragma unroll
        for (int cc = 0; cc < 4; cc++) {
            float z[4], mx = -1e30f;
#pragma unroll
            for (int kk = 0; kk < 4; kk++) { z[kk] = xa[cc] * w4[kk] + b4[kk]; mx = fmaxf(mx, z[kk]); }
            float se = 0.f, mean = 0.f;
#pragma unroll
            for (int kk = 0; kk < 4; kk++) { float e2 = expf(z[kk] - mx); se += e2; mean += ma[kk][cc] * e2; }
            mean /= se;
            so[cc] = xa[cc] - mean;
            tr[cc] = mean;
        }
        *reinterpret_cast<float4*>(seas + base + (size_t)j * DZ) =
            make_float4(so[0], so[1], so[2], so[3]);
        if (trend) {
            float4 tv = make_float4(tr[0], tr[1], tr[2], tr[3]);
            if (accum) {
                float4 old = *reinterpret_cast<float4*>(trend + base + (size_t)j * DZ);
                tv = f4add(tv, old);
            }
            *reinterpret_cast<float4*>(trend + base + (size_t)j * DZ) = tv;
        }
    }
}

// ------------------------------------------------------------------ trend/seasonal init
__global__ void trendbase_kernel(const float* __restrict__ dpw, const float* __restrict__ dpb) {
    int idx = blockIdx.x * blockDim.x + threadIdx.x;
    if (idx >= BZ * LZ) return;
    int t = idx & 1023, b = idx >> 10;
    float s = dpb[0];
#pragma unroll
    for (int c = 0; c < C7; c++) {
        float v = (t < 512) ? g_trend0[((size_t)(b * LZ + 512 + t)) * C7 + c]
                            : g_mean7[b * C7 + c];
        s += v * dpw[c];
    }
    g_trendbase[idx] = s;
}

__global__ void seasinit_kernel() {
    int idx = blockIdx.x * blockDim.x + threadIdx.x;
    if (idx >= BZ * LZ * C7) return;
    int c = idx % C7;
    int t = (idx / C7) & 1023;
    int b = idx / (C7 * LZ);
    g_seasinit[idx] = (t < 512) ? g_seas0[((size_t)(b * LZ + 512 + t)) * C7 + c] : 0.f;
}

// ------------------------------------------------------------------ embedding
__global__ void embed_kernel(const float* __restrict__ in, const float* __restrict__ w,
                             float* __restrict__ out) {
    int idx = blockIdx.x * blockDim.x + threadIdx.x;
    if (idx >= BZ * LZ * DZ) return;
    int o = idx & 63;
    int t = (idx >> 6) & 1023;
    int b = idx >> 16;
    float s = 0.f;
#pragma unroll
    for (int j = 0; j < 3; j++) {
        int ts = (t + j - 1 + LZ) & (LZ - 1);
        const float* ip = in + ((size_t)(b * LZ + ts)) * C7;
#pragma unroll
        for (int c = 0; c < C7; c++) s += ip[c] * w[(o * C7 + c) * 3 + j];
    }
    out[idx] = s + g_pe[(t << 6) + o];
}

// ------------------------------------------------------------------ tf32 helpers
__device__ __forceinline__ uint32_t to_tf32(float x) {
    uint32_t r;
    asm("cvt.rna.tf32.f32 %0, %1;" : "=r"(r) : "f"(x));
    return r;
}
__device__ __forceinline__ void cpa16(uint32_t s, const float* g) {
    asm volatile("cp.async.ca.shared.global [%0], [%1], 16;" :: "r"(s), "l"(g));
}
__device__ __forceinline__ void cpa_commit() {
    asm volatile("cp.async.commit_group;");
}
__device__ __forceinline__ void cpa_wait1() {
    asm volatile("cp.async.wait_group 1;");
}

// ------------------------------------------------------------------ tf32 GEMM
#define GT_ASTRIDE (128*36)
#define GT_BSTRIDE (64*36)
#define GT_SMEM ((2*GT_ASTRIDE + 2*GT_BSTRIDE) * 4)

template <int ACT>
__global__ __launch_bounds__(128) void gemm_tc(const float* __restrict__ A,
                                               const float* __restrict__ W,
                                               const float* __restrict__ bias,
                                               float* __restrict__ C,
                                               int N, int K, int O) {
    extern __shared__ float dsm[];
    float* As = dsm;
    float* Bs = dsm + 2 * GT_ASTRIDE;
    const int rb = blockIdx.x * 128;
    const int cb = blockIdx.y * 64;
    const int tid = threadIdx.x;
    const int lane = tid & 31;
    const int w = tid >> 5;
    const int wm = w & 1, wn = w >> 1;
    const int m0 = wm * 64, n0 = wn * 32;
    const int g = lane >> 2, tg = lane & 3;
    const int lrow = tid >> 3;
    const int lcol = (tid & 7) * 4;

    uint32_t sA = (uint32_t)__cvta_generic_to_shared(As);
    uint32_t sB = (uint32_t)__cvta_generic_to_shared(Bs);

    float acc[4][4][4];
#pragma unroll
    for (int mi = 0; mi < 4; mi++)
#pragma unroll
        for (int ni = 0; ni < 4; ni++)
#pragma unroll
            for (int r = 0; r < 4; r++) acc[mi][ni][r] = 0.f;

#pragma unroll
    for (int r = 0; r < 8; r++) {
        int row = lrow + r * 16;
        cpa16(sA + (uint32_t)((row * 36 + lcol) * 4), A + (size_t)(rb + row) * K + lcol);
    }
#pragma unroll
    for (int r = 0; r < 4; r++) {
        int row = lrow + r * 16;
        cpa16(sB + (uint32_t)((row * 36 + lcol) * 4), W + (size_t)(cb + row) * K + lcol);
    }
    cpa_commit();

    int st = 0;
    for (int k0 = 0; k0 < K; k0 += 32, st ^= 1) {
        if (k0 + 32 < K) {
            int nx = st ^ 1;
#pragma unroll
            for (int r = 0; r < 8; r++) {
                int row = lrow + r * 16;
                cpa16(sA + (uint32_t)((nx * GT_ASTRIDE + row * 36 + lcol) * 4),
                      A + (size_t)(rb + row) * K + k0 + 32 + lcol);
            }
#pragma unroll
            for (int r = 0; r < 4; r++) {
                int row = lrow + r * 16;
                cpa16(sB + (uint32_t)((nx * GT_BSTRIDE + row * 36 + lcol) * 4),
                      W + (size_t)(cb + row) * K + k0 + 32 + lcol);
            }
        }
        cpa_commit();
        cpa_wait1();
        __syncthreads();
        const float* Ast = As + st * GT_ASTRIDE;
        const float* Bst = Bs + st * GT_BSTRIDE;
#pragma unroll
        for (int kk = 0; kk < 32; kk += 8) {
            uint32_t a[4][4], bfr[4][2];
#pragma unroll
            for (int mi = 0; mi < 4; mi++) {
                int r = m0 + mi * 16 + g;
                a[mi][0] = to_tf32(Ast[r * 36 + kk + tg]);
                a[mi][1] = to_tf32(Ast[(r + 8) * 36 + kk + tg]);
                a[mi][2] = to_tf32(Ast[r * 36 + kk + tg + 4]);
                a[mi][3] = to_tf32(Ast[(r + 8) * 36 + kk + tg + 4]);
            }
#pragma unroll
            for (int ni = 0; ni < 4; ni++) {
                int c = n0 + ni * 8 + g;
                bfr[ni][0] = to_tf32(Bst[c * 36 + kk + tg]);
                bfr[ni][1] = to_tf32(Bst[c * 36 + kk + tg + 4]);
            }
#pragma unroll
            for (int mi = 0; mi < 4; mi++)
#pragma unroll
                for (int ni = 0; ni < 4; ni++) {
                    asm volatile(
                        "mma.sync.aligned.m16n8k8.row.col.f32.tf32.tf32.f32 "
                        "{%0,%1,%2,%3}, {%4,%5,%6,%7}, {%8,%9}, {%0,%1,%2,%3};"
                        : "+f"(acc[mi][ni][0]), "+f"(acc[mi][ni][1]),
                          "+f"(acc[mi][ni][2]), "+f"(acc[mi][ni][3])
                        : "r"(a[mi][0]), "r"(a[mi][1]), "r"(a[mi][2]), "r"(a[mi][3]),
                          "r"(bfr[ni][0]), "r"(bfr[ni][1]));
                }
        }
        __syncthreads();
    }
#pragma unroll
    for (int mi = 0; mi < 4; mi++) {
        int row0 = rb + m0 + mi * 16 + g;
#pragma unroll
        for (int ni = 0; ni < 4; ni++) {
            int col = cb + n0 + ni * 8 + 2 * tg;
#pragma unroll
            for (int half = 0; half < 2; half++) {
                int row = row0 + half * 8;
                float v0 = acc[mi][ni][half * 2 + 0];
                float v1 = acc[mi][ni][half * 2 + 1];
                if (bias) { v0 += bias[col]; v1 += bias[col + 1]; }
                if (ACT == 1) {
                    v0 = 0.5f * v0 * (1.f + erff(v0 * 0.70710678118654752f));
                    v1 = 0.5f * v1 * (1.f + erff(v1 * 0.70710678118654752f));
                }
                C[(size_t)row * O + col] = v0;
                C[(size_t)row * O + col + 1] = v1;
            }
        }
    }
}

// ------------------------------------------------------------------ DFT GEMM with fused transpose
__device__ __forceinline__ void dft_body(const float* __restrict__ Aq,
                                         const float* __restrict__ F,
                                         float* __restrict__ X,
                                         int b, int cb, int zz) {
    __shared__ float As[64][33];
    __shared__ float Bs[64][36];
    const int tbase = zz * 256;
    const int tid = threadIdx.x;
    const int lane = tid & 31;
    const int w = tid >> 5;
    const int wm = w & 1, wn = w >> 1;
    const int m0 = wm * 32, n0 = wn * 32;
    const int g = lane >> 2, tg = lane & 3;
    const int lrow = tid >> 3;
    const int lcol = (tid & 7) * 4;

    float acc[2][4][4];
#pragma unroll
    for (int mi = 0; mi < 2; mi++)
#pragma unroll
        for (int ni = 0; ni < 4; ni++)
#pragma unroll
            for (int r = 0; r < 4; r++) acc[mi][ni][r] = 0.f;

    for (int t0 = tbase; t0 < tbase + 256; t0 += 32) {
#pragma unroll
        for (int i = 0; i < 4; i++) {
            int f4 = i * 128 + tid;
            int tl = f4 >> 4;
            int he = (f4 & 15) * 4;
            float4 v = *reinterpret_cast<const float4*>(
                Aq + ((size_t)(b * LZ + t0 + tl)) * DZ + he);
            As[he + 0][tl] = v.x;
            As[he + 1][tl] = v.y;
            As[he + 2][tl] = v.z;
            As[he + 3][tl] = v.w;
        }
#pragma unroll
        for (int r = 0; r < 4; r++) {
            int row = lrow + r * 16;
            *reinterpret_cast<float4*>(&Bs[row][lcol]) =
                *reinterpret_cast<const float4*>(F + (size_t)(cb + row) * LZ + t0 + lcol);
        }
        __syncthreads();
#pragma unroll
        for (int kk = 0; kk < 32; kk += 8) {
            uint32_t a[2][4], bfr[4][2];
#pragma unroll
            for (int mi = 0; mi < 2; mi++) {
                int r = m0 + mi * 16 + g;
                a[mi][0] = to_tf32(As[r][kk + tg]);
                a[mi][1] = to_tf32(As[r + 8][kk + tg]);
                a[mi][2] = to_tf32(As[r][kk + tg + 4]);
                a[mi][3] = to_tf32(As[r + 8][kk + tg + 4]);
            }
#pragma unroll
            for (int ni = 0; ni < 4; ni++) {
                int c = n0 + ni * 8 + g;
                bfr[ni][0] = to_tf32(Bs[c][kk + tg]);
                bfr[ni][1] = to_tf32(Bs[c][kk + tg + 4]);
            }
#pragma unroll
            for (int mi = 0; mi < 2; mi++)
#pragma unroll
                for (int ni = 0; ni < 4; ni++) {
                    asm volatile(
                        "mma.sync.aligned.m16n8k8.row.col.f32.tf32.tf32.f32 "
                        "{%0,%1,%2,%3}, {%4,%5,%6,%7}, {%8,%9}, {%0,%1,%2,%3};"
                        : "+f"(acc[mi][ni][0]), "+f"(acc[mi][ni][1]),
                          "+f"(acc[mi][ni][2]), "+f"(acc[mi][ni][3])
                        : "r"(a[mi][0]), "r"(a[mi][1]), "r"(a[mi][2]), "r"(a[mi][3]),
                          "r"(bfr[ni][0]), "r"(bfr[ni][1]));
                }
        }
        __syncthreads();
    }
#pragma unroll
    for (int mi = 0; mi < 2; mi++) {
        int r0 = m0 + mi * 16 + g;
#pragma unroll
        for (int ni = 0; ni < 4; ni++) {
            int col = cb + n0 + ni * 8 + 2 * tg;
#pragma unroll
            for (int half = 0; half < 2; half++) {
                int row = r0 + half * 8;
                atomicAdd(&X[(size_t)(b * 64 + row) * M2 + col], acc[mi][ni][half * 2 + 0]);
                atomicAdd(&X[(size_t)(b * 64 + row) * M2 + col + 1], acc[mi][ni][half * 2 + 1]);
            }
        }
    }
}

__global__ __launch_bounds__(128) void gemm_dft(const float* __restrict__ Aq,
                                                const float* __restrict__ F,
                                                float* __restrict__ X) {
    dft_body(Aq, F, X, blockIdx.x, blockIdx.y * 64, blockIdx.z);
}

__global__ __launch_bounds__(128) void gemm_dft2(const float* __restrict__ Aq1,
                                                 float* __restrict__ X1,
                                                 const float* __restrict__ Aq2,
                                                 float* __restrict__ X2,
                                                 const float* __restrict__ F) {
    int z = blockIdx.z;
    if (z < 4) dft_body(Aq1, F, X1, blockIdx.x, blockIdx.y * 64, z);
    else       dft_body(Aq2, F, X2, blockIdx.x, blockIdx.y * 64, z - 4);
}

// ------------------------------------------------------------------ mode-space projection (standalone, cross path)
// Qf[(b*64+he), m2] = sum_d Wq[he,d] * (Hf[(b*64+d), m2] - [m2==0]*cm*1024) + [m2==0]*bias*1024
__global__ __launch_bounds__(256) void modeproj_kernel(const float* __restrict__ Hf,
                                                       const float* __restrict__ Wq,
                                                       const float* __restrict__ bq,
                                                       const float* __restrict__ cm,
                                                       float* __restrict__ Qf) {
    __shared__ float Hs[64][68];
    __shared__ float Ws[64][68];
    int b = blockIdx.x;
    int mh = blockIdx.y;
    int tid = threadIdx.x;
    for (int i = tid; i < 64 * 16; i += 256) {
        int d = i >> 4;
        int c4 = (i & 15) * 4;
        *reinterpret_cast<float4*>(&Hs[d][c4]) =
            *reinterpret_cast<const float4*>(Hf + ((size_t)(b * 64 + d)) * M2 + mh * 64 + c4);
    }
    for (int i = tid; i < 64 * 16; i += 256) {
        int he = i >> 4;
        int c4 = (i & 15) * 4;
        *reinterpret_cast<float4*>(&Ws[he][c4]) =
            *reinterpret_cast<const float4*>(Wq + he * 64 + c4);
    }
    __syncthreads();
    if (cm && mh == 0 && tid < 64) Hs[tid][0] -= cm[b * 64 + tid] * 1024.f;
    __syncthreads();
    int he = tid >> 2;
    int mg = tid & 3;
#pragma unroll
    for (int j = 0; j < 16; j++) {
        int ml = mg + 4 * j;
        float s = 0.f;
#pragma unroll
        for (int d = 0; d < 64; d++) s += Ws[he][d] * Hs[d][ml];
        int m2 = mh * 64 + ml;
        if (m2 == 0) s += bq[he] * 1024.f;
        Qf[((size_t)(b * 64 + he)) * M2 + m2] = s;
    }
}

// ------------------------------------------------------------------ fused modeproj + mode_mix (self-attn)
#define MPM_SMEM ((2*64*68 + 64*66) * 4)
__global__ __launch_bounds__(256) void modeproj_mix_kernel(const float* __restrict__ Hf,
                                                           const float* __restrict__ Wq,
                                                           const float* __restrict__ bq,
                                                           const float* __restrict__ wr,
                                                           const float* __restrict__ wi,
                                                           float* __restrict__ sel,
                                                           float scale) {
    extern __shared__ float sm[];
    float* Hs = sm;                 // [64][68]
    float* Ws = sm + 64 * 68;       // [64][68]
    float* Qs = sm + 2 * 64 * 68;   // [64][66]
    int b = blockIdx.x;
    int mh = blockIdx.y;
    int tid = threadIdx.x;
    for (int i = tid; i < 64 * 16; i += 256) {
        int d = i >> 4;
        int c4 = (i & 15) * 4;
        *reinterpret_cast<float4*>(&Hs[d * 68 + c4]) =
            *reinterpret_cast<const float4*>(Hf + ((size_t)(b * 64 + d)) * M2 + mh * 64 + c4);
    }
    for (int i = tid; i < 64 * 16; i += 256) {
        int he = i >> 4;
        int c4 = (i & 15) * 4;
        *reinterpret_cast<float4*>(&Ws[he * 68 + c4]) =
            *reinterpret_cast<const float4*>(Wq + he * 64 + c4);
    }
    __syncthreads();
    {
        int he = tid >> 2;
        int mg = tid & 3;
#pragma unroll
        for (int j = 0; j < 16; j++) {
            int ml = mg + 4 * j;
            float s = 0.f;
#pragma unroll
            for (int d = 0; d < 64; d++) s += Ws[he * 68 + d] * Hs[d * 68 + ml];
            if (mh == 0 && ml == 0) s += bq[he] * 1024.f;
            Qs[he * 66 + ml] = s;
        }
    }
    __syncthreads();
    {
        int lm = tid & 31;
        int hob = tid >> 5;
        int m = mh * 32 + lm;
#pragma unroll
        for (int j = 0; j < 8; j++) {
            int ho = hob * 8 + j;
            int h = ho >> 3, o = ho & 7;
            float ar = 0.f, ai = 0.f;
#pragma unroll
            for (int e = 0; e < 8; e++) {
                float xr = Qs[(h * 8 + e) * 66 + 2 * lm];
                float xi = Qs[(h * 8 + e) * 66 + 2 * lm + 1];
                int wix = ((h * 8 + e) * 8 + o) * MZ + m;
                float wrv = wr[wix], wiv = wi[wix];
                ar += xr * wrv - xi * wiv;
                ai += xr * wiv + xi * wrv;
            }
            size_t ro = ((size_t)(b * 64 + h * 8 + o)) * M2 + 2 * m;
            sel[ro] = ar * scale;
            sel[ro + 1] = ai * scale;
        }
    }
}

// ------------------------------------------------------------------ fused cross attention (qk tanh + qkv + mode mix)
__global__ __launch_bounds__(256) void qkattn_kernel(const float* __restrict__ Qf,
                                                     const float* __restrict__ Kf,
                                                     const float* __restrict__ wr,
                                                     const float* __restrict__ wi,
                                                     float* __restrict__ sel,
                                                     float scale) {
    __shared__ float Qs[8][128];
    __shared__ float Ks[8][128];
    __shared__ float qks[64][130];
    __shared__ float Vs[8][128];
    int bh = blockIdx.x;
    int h = bh & 7, b = bh >> 3;
    int tid = threadIdx.x;
    size_t tbase = (size_t)(b * 64 + h * 8) * M2;
#pragma unroll
    for (int i = 0; i < 4; i++) {
        int f = i * 256 + tid;
        int e = f >> 7, c = f & 127;
        Qs[e][c] = Qf[tbase + e * M2 + c];
        Ks[e][c] = Kf[tbase + e * M2 + c];
    }
    __syncthreads();
    {
        int x = tid >> 2;
        int ys = tid & 3;
#pragma unroll
        for (int j = 0; j < 16; j++) {
            int y = ys * 16 + j;
            float ar = 0.f, ai = 0.f;
#pragma unroll
            for (int e = 0; e < 8; e++) {
                float qr = Qs[e][2 * x], qi = Qs[e][2 * x + 1];
                float kr = Ks[e][2 * y], ki = Ks[e][2 * y + 1];
                ar += qr * kr - qi * ki;
                ai += qr * ki + qi * kr;
            }
            float a2 = 2.f * ar, b2 = 2.f * ai;
            float tr, ti;
            if (fabsf(a2) > 30.f) {
                tr = copysignf(1.f, ar);
                ti = 0.f;
            } else {
                float sn, cs;
                sincosf(b2, &sn, &cs);
                float ex = expf(a2);
                float exi = 1.f / ex;
                float den = 0.5f * (ex + exi) + cs;
                tr = 0.5f * (ex - exi) / den;
                ti = sn / den;
            }
            qks[x][2 * y] = tr;
            qks[x][2 * y + 1] = ti;
        }
    }
    __syncthreads();
    {
        int flat0 = tid * 2;
#pragma unroll
        for (int u = 0; u < 2; u++) {
            int flat = flat0 + u;
            int e = flat >> 6, x = flat & 63;
            float ar = 0.f, ai = 0.f;
#pragma unroll 16
            for (int y = 0; y < 64; y++) {
                float qr = qks[x][2 * y], qi = qks[x][2 * y + 1];
                float kr = Ks[e][2 * y], ki = Ks[e][2 * y + 1];
                ar += qr * kr - qi * ki;
                ai += qr * ki + qi * kr;
            }
            Vs[e][2 * x] = ar;
            Vs[e][2 * x + 1] = ai;
        }
    }
    __syncthreads();
    {
        int m = tid & 63;
        int og = tid >> 6;
#pragma unroll
        for (int j = 0; j < 2; j++) {
            int o = og * 2 + j;
            float ar = 0.f, ai = 0.f;
#pragma unroll
            for (int e = 0; e < 8; e++) {
                float xr = Vs[e][2 * m], xi = Vs[e][2 * m + 1];
                int wix = ((h * 8 + e) * 8 + o) * MZ + m;
                float wrv = wr[wix], wiv = wi[wix];
                ar += xr * wrv - xi * wiv;
                ai += xr * wiv + xi * wrv;
            }
            size_t ro = ((size_t)(b * 64 + h * 8 + o)) * M2 + 2 * m;
            sel[ro] = ar * scale;
            sel[ro + 1] = ai * scale;
        }
    }
}

// ------------------------------------------------------------------ layernorm family
__global__ void ln_row_kernel(const float* __restrict__ X, const float* __restrict__ g,
                              const float* __restrict__ be, float* __restrict__ out) {
    __shared__ float red[256];
    int tid = threadIdx.x;
    int sub = tid >> 6;
    int d = tid & 63;
    int row = blockIdx.x * 4 + sub;
    float v = X[(size_t)row * DZ + d];
    red[tid] = v;
    __syncthreads();
    for (int s = 32; s > 0; s >>= 1) {
        if (d < s) red[tid] += red[tid + s];
        __syncthreads();
    }
    float mu = red[sub * 64] * (1.f / 64.f);
    __syncthreads();
    float dv = v - mu;
    red[tid] = dv * dv;
    __syncthreads();
    for (int s = 32; s > 0; s >>= 1) {
        if (d < s) red[tid] += red[tid + s];
        __syncthreads();
    }
    float var = red[sub * 64] * (1.f / 64.f);
    out[(size_t)row * DZ + d] = dv * rsqrtf(var + 1e-5f) * g[d] + be[d];
}

__global__ void colmean_kernel(const float* __restrict__ X, float* __restrict__ cm) {
    __shared__ float r[256];
    int b = blockIdx.x / DZ, d = blockIdx.x % DZ;
    float s = 0.f;
    for (int t = threadIdx.x; t < LZ; t += 256) s += X[((size_t)(b * LZ + t)) * DZ + d];
    r[threadIdx.x] = s;
    __syncthreads();
    for (int o = 128; o > 0; o >>= 1) {
        if (threadIdx.x < o) r[threadIdx.x] += r[threadIdx.x + o];
        __syncthreads();
    }
    if (threadIdx.x == 0) cm[b * DZ + d] = r[0] * (1.f / LZ);
}

// ------------------------------------------------------------------ final epilogue (subtracts colmean)
__global__ void final_kernel(const float* __restrict__ xln, const float* __restrict__ cm,
                             const float* __restrict__ tacc,
                             const float* __restrict__ tbase, const float* __restrict__ tw,
                             const float* __restrict__ pw, const float* __restrict__ pb,
                             float* __restrict__ out) {
    int idx = blockIdx.x * blockDim.x + threadIdx.x;
    if (idx >= BZ * 512) return;
    int t = idx & 511, b = idx >> 9;
    int tt = t + 512;
    float cv = 0.f;
#pragma unroll
    for (int j = 0; j < 3; j++) {
        int ts = (tt + j - 1) & (LZ - 1);
        const float* row = tacc + ((size_t)(b * LZ + ts)) * DZ;
        for (int d = 0; d < DZ; d++) cv += row[d] * tw[d * 3 + j];
    }
    float p = pb[0];
    const float* xr = xln + ((size_t)(b * LZ + tt)) * DZ;
    const float* cmr = cm + b * DZ;
    for (int d = 0; d < DZ; d++) p += (xr[d] - cmr[d]) * pw[d];
    out[idx] = p + cv + tbase[b * LZ + tt];
}

static float* symaddr_f(const void* sym) {
    void* p = nullptr;
    cudaGetSymbolAddress(&p, sym);
    return (float*)p;
}

extern "C" void kernel_launch(void* const* d_in, const int* in_sizes, int n_in,
                              void* d_out, int out_size) {
    const float* x_enc       = (const float*)d_in[0];
    const float* dp_w        = (const float*)d_in[1];
    const float* dp_b        = (const float*)d_in[2];
    const float* emb_enc_w   = (const float*)d_in[3];
    const float* emb_dec_w   = (const float*)d_in[4];
    const float* decomp_w    = (const float*)d_in[5];
    const float* decomp_b    = (const float*)d_in[6];
    const float* enc_attn_w  = (const float*)d_in[7];
    const float* enc_attn_b  = (const float*)d_in[8];
    const float* enc_four_wr = (const float*)d_in[9];
    const float* enc_four_wi = (const float*)d_in[10];
    const float* enc_c1      = (const float*)d_in[11];
    const float* enc_c2      = (const float*)d_in[12];
    const float* enc_ln_g    = (const float*)d_in[13];
    const float* enc_ln_b    = (const float*)d_in[14];
    const float* dec_self_w  = (const float*)d_in[15];
    const float* dec_self_b  = (const float*)d_in[16];
    const float* dec_four_wr = (const float*)d_in[17];
    const float* dec_four_wi = (const float*)d_in[18];
    const float* dec_cross_w = (const float*)d_in[19];
    const float* dec_cross_b = (const float*)d_in[20];
    const float* dec_cross_wr= (const float*)d_in[21];
    const float* dec_cross_wi= (const float*)d_in[22];
    const float* dec_c1      = (const float*)d_in[23];
    const float* dec_c2      = (const float*)d_in[24];
    const float* dec_trend_w = (const float*)d_in[25];
    const float* dec_ln_g    = (const float*)d_in[26];
    const float* dec_ln_b    = (const float*)d_in[27];
    const float* dec_proj_w  = (const float*)d_in[28];
    const float* dec_proj_b  = (const float*)d_in[29];
    float* out = (float*)d_out;

    float* px        = symaddr_f(g_x);
    float* pseas0    = symaddr_f(g_seas0);
    float* ptrend0   = symaddr_f(g_trend0);
    float* pseasinit = symaddr_f(g_seasinit);
    float* ph        = symaddr_f(g_h);
    float* py        = symaddr_f(g_y);
    float* pa        = symaddr_f(g_a);
    float* pffn      = symaddr_f(g_ffn);
    float* pHf       = symaddr_f(g_Hf);
    float* pHf2      = pHf + (size_t)NHE * M2;
    float* pXf       = symaddr_f(g_Xf);
    float* pXk       = symaddr_f(g_Xk);
    float* psel      = symaddr_f(g_sel);
    float* pxd       = symaddr_f(g_xd);
    float* ptacc     = symaddr_f(g_tacc);
    float* pcm       = symaddr_f(g_cm);
    float* pcm2      = symaddr_f(g_cm2);
    float* pln       = symaddr_f(g_ln);
    float* pF        = symaddr_f(g_F);
    float* pFi       = symaddr_f(g_Fi);
    float* ptbase    = symaddr_f(g_trendbase);

    cudaFuncSetAttribute(gemm_tc<0>, cudaFuncAttributeMaxDynamicSharedMemorySize, GT_SMEM);
    cudaFuncSetAttribute(gemm_tc<1>, cudaFuncAttributeMaxDynamicSharedMemorySize, GT_SMEM);
    cudaFuncSetAttribute(modeproj_mix_kernel, cudaFuncAttributeMaxDynamicSharedMemorySize, MPM_SMEM);

    dim3 dftg(BZ, 2, 4);
    dim3 dftg2(BZ, 2, 8);
    dim3 mpg(BZ, 2);

    build_tables_kernel<<<512, 256>>>();
    transpose_in_kernel<<<1792, 256>>>(x_enc);
    colmean7_kernel<<<BZ * C7, 256>>>(x_enc);
    decomp7_kernel<<<BZ * C7, LZ>>>(px, decomp_w + 0, decomp_b + 0, pseas0, ptrend0);
    trendbase_kernel<<<256, 256>>>(dp_w, dp_b);
    seasinit_kernel<<<1792, 256>>>();

    embed_kernel<<<16384, 256>>>(px, emb_enc_w, ph);
    for (int l = 0; l < 2; l++) {
        const float* wq = enc_attn_w + (size_t)(l * 4 + 0) * 4096;
        const float* bq = enc_attn_b + (size_t)(l * 4 + 0) * 64;
        const float* wo = enc_attn_w + (size_t)(l * 4 + 3) * 4096;
        const float* bo = enc_attn_b + (size_t)(l * 4 + 3) * 64;
        cudaMemsetAsync(pHf, 0, (size_t)NHE * M2 * sizeof(float));
        gemm_dft<<<dftg, 128>>>(ph, pF, pHf);
        modeproj_mix_kernel<<<mpg, 256, MPM_SMEM>>>(pHf, wq, bq,
                                                    enc_four_wr + (size_t)l * 32768,
                                                    enc_four_wi + (size_t)l * 32768, psel, 1.0f);
        gemm_tc<0><<<dim3(32, 16), 128, GT_SMEM>>>(psel, pFi, nullptr, py, NHE, 128, 1024);
        gemm_tc<0><<<dim3(512, 1), 128, GT_SMEM>>>(py, wo, bo, pa, NROW, 64, 64);
        decomp64_kernel<<<1024, 256>>>(ph, pa, decomp_w + (1 + 2 * l) * 4,
                                       decomp_b + (1 + 2 * l) * 4, ph, nullptr, 0);
        gemm_tc<1><<<dim3(512, 4), 128, GT_SMEM>>>(ph, enc_c1 + (size_t)l * 16384, nullptr, pffn,
                                                   NROW, 64, 256);
        gemm_tc<0><<<dim3(512, 1), 128, GT_SMEM>>>(pffn, enc_c2 + (size_t)l * 16384, nullptr, py,
                                                   NROW, 256, 64);
        decomp64_kernel<<<1024, 256>>>(ph, py, decomp_w + (2 + 2 * l) * 4,
                                       decomp_b + (2 + 2 * l) * 4, ph, nullptr, 0);
    }
    ln_row_kernel<<<16384, 256>>>(ph, enc_ln_g, enc_ln_b, ph);
    colmean_kernel<<<BZ * DZ, 256>>>(ph, pcm2);

    embed_kernel<<<16384, 256>>>(pseasinit, emb_dec_w, pxd);
    // decoder self attention
    cudaMemsetAsync(pHf, 0, (size_t)NHE * M2 * sizeof(float));
    gemm_dft<<<dftg, 128>>>(pxd, pF, pHf);
    modeproj_mix_kernel<<<mpg, 256, MPM_SMEM>>>(pHf, dec_self_w + 0, dec_self_b + 0,
                                                dec_four_wr, dec_four_wi, psel, 1.0f);
    gemm_tc<0><<<dim3(32, 16), 128, GT_SMEM>>>(psel, pFi, nullptr, py, NHE, 128, 1024);
    gemm_tc<0><<<dim3(512, 1), 128, GT_SMEM>>>(py, dec_self_w + 3 * 4096, dec_self_b + 3 * 64, pa,
                                               NROW, 64, 64);
    decomp64_kernel<<<1024, 256>>>(pxd, pa, decomp_w + 5 * 4, decomp_b + 5 * 4, pxd, ptacc, 0);

    // decoder cross attention
    cudaMemsetAsync(pHf, 0, (size_t)2 * NHE * M2 * sizeof(float));
    gemm_dft2<<<dftg2, 128>>>(pxd, pHf, ph, pHf2, pF);
    modeproj_kernel<<<mpg, 256>>>(pHf, dec_cross_w + 0, dec_cross_b + 0, nullptr, pXf);
    modeproj_kernel<<<mpg, 256>>>(pHf2, dec_cross_w + 1 * 4096, dec_cross_b + 1 * 64, pcm2, pXk);
    qkattn_kernel<<<512, 256>>>(pXf, pXk, dec_cross_wr, dec_cross_wi, psel, 1.0f / 4096.0f);
    gemm_tc<0><<<dim3(32, 16), 128, GT_SMEM>>>(psel, pFi, nullptr, py, NHE, 128, 1024);
    gemm_tc<0><<<dim3(512, 1), 128, GT_SMEM>>>(py, dec_cross_w + 3 * 4096, dec_cross_b + 3 * 64, pa,
                                               NROW, 64, 64);
    decomp64_kernel<<<1024, 256>>>(pxd, pa, decomp_w + 6 * 4, decomp_b + 6 * 4, pxd, ptacc, 1);

    gemm_tc<1><<<dim3(512, 4), 128, GT_SMEM>>>(pxd, dec_c1, nullptr, pffn, NROW, 64, 256);
    gemm_tc<0><<<dim3(512, 1), 128, GT_SMEM>>>(pffn, dec_c2, nullptr, py, NROW, 256, 64);
    decomp64_kernel<<<1024, 256>>>(pxd, py, decomp_w + 7 * 4, decomp_b + 7 * 4, pxd, ptacc, 1);

    ln_row_kernel<<<16384, 256>>>(pxd, dec_ln_g, dec_ln_b, pln);
    colmean_kernel<<<BZ * DZ, 256>>>(pln, pcm);
    final_kernel<<<128, 256>>>(pln, pcm, ptacc, ptbase, dec_trend_w, dec_proj_w, dec_proj_b, out);
}

// round 10
// speedup vs baseline: 2.2764x; 1.0395x over previous
#include <cuda_runtime.h>
#include <cstdint>

#define BZ 64
#define LZ 1024
#define DZ 64
#define C7 7
#define HZ 8
#define EZ 8
#define MZ 64
#define M2 128
#define DFFD 256
#define NROW (BZ*LZ)
#define NHE  (BZ*DZ)

__device__ float g_x[BZ*LZ*C7];
__device__ float g_seas0[BZ*LZ*C7];
__device__ float g_trend0[BZ*LZ*C7];
__device__ float g_mean7[BZ*C7];
__device__ float g_trendbase[BZ*LZ];
__device__ float g_seasinit[BZ*LZ*C7];
__device__ float g_h[NROW*DZ];
__device__ float g_y[NROW*DZ];
__device__ float g_a[NROW*DZ];
__device__ float g_y2[NROW*DZ];
__device__ float g_a2[NROW*DZ];
__device__ float g_ffn[NROW*DFFD];
__device__ float g_Hf[2*NHE*M2];
__device__ float g_Xf[NHE*M2];
__device__ float g_Xk[NHE*M2];
__device__ float g_sel[NHE*M2];
__device__ float g_sel2[NHE*M2];
__device__ float g_xd[NROW*DZ];
__device__ float g_tacc[NROW*DZ];
__device__ float g_cm[BZ*DZ];
__device__ float g_cm2[BZ*DZ];
__device__ float g_ln[NROW*DZ];
__device__ float g_F[M2*LZ];
__device__ float g_Fi[LZ*M2];
__device__ float g_pe[LZ*DZ];

// ------------------------------------------------------------------ tables
__global__ void build_tables_kernel() {
    int idx = blockIdx.x * blockDim.x + threadIdx.x;
    if (idx < LZ * M2) {
        int t = idx >> 7;
        int m2 = idx & 127;
        int m = m2 >> 1;
        int r = (m * t) & (LZ - 1);
        float a = (float)r * (6.28318530717958647692f / (float)LZ);
        float s, c;
        sincosf(a, &s, &c);
        float v = (m2 & 1) ? -s : c;
        g_F[(size_t)m2 * LZ + t] = v;
        float cm = (m == 0) ? 1.f : 2.f;
        g_Fi[(size_t)t * M2 + m2] = v * (cm / (float)LZ);
    }
    if (idx < LZ * DZ) {
        int o = idx & 63;
        int t = idx >> 6;
        int i2 = o & ~1;
        float div = expf(-(float)i2 * 0.14391156831212793f);
        float arg = (float)t * div;
        g_pe[idx] = (o & 1) ? cosf(arg) : sinf(arg);
    }
}

// ------------------------------------------------------------------ input prep
__global__ void transpose_in_kernel(const float* __restrict__ xe) {
    int idx = blockIdx.x * blockDim.x + threadIdx.x;
    if (idx >= BZ * C7 * LZ) return;
    int t = idx & 1023;
    int c = (idx >> 10) % C7;
    int b = idx / (C7 * LZ);
    g_x[((size_t)(b * LZ + t)) * C7 + c] = xe[idx];
}

__global__ void colmean7_kernel(const float* __restrict__ xe) {
    __shared__ float r[256];
    int bc = blockIdx.x;
    float s = 0.f;
    for (int t = threadIdx.x; t < LZ; t += 256) s += xe[(size_t)bc * LZ + t];
    r[threadIdx.x] = s;
    __syncthreads();
    for (int o = 128; o > 0; o >>= 1) {
        if (threadIdx.x < o) r[threadIdx.x] += r[threadIdx.x + o];
        __syncthreads();
    }
    if (threadIdx.x == 0) g_mean7[bc] = r[0] * (1.f / LZ);
}

// ------------------------------------------------------------------ decomp7
__global__ void decomp7_kernel(const float* __restrict__ A,
                               const float* __restrict__ w4, const float* __restrict__ b4,
                               float* __restrict__ seas, float* __restrict__ trend) {
    __shared__ float ps[LZ];
    __shared__ float wsum[32];
    __shared__ float sx0, sxN;
    int c = blockIdx.x % C7, b = blockIdx.x / C7;
    int t = threadIdx.x, lane = t & 31, wid = t >> 5;
    size_t idx = ((size_t)(b * LZ + t)) * C7 + c;
    float x = A[idx];
    float s = x;
#pragma unroll
    for (int off = 1; off < 32; off <<= 1) {
        float v = __shfl_up_sync(0xffffffffu, s, off);
        if (lane >= off) s += v;
    }
    if (lane == 31) wsum[wid] = s;
    if (t == 0) sx0 = x;
    if (t == LZ - 1) sxN = x;
    __syncthreads();
    if (wid == 0) {
        float v = wsum[lane];
#pragma unroll
        for (int off = 1; off < 32; off <<= 1) {
            float u = __shfl_up_sync(0xffffffffu, v, off);
            if (lane >= off) v += u;
        }
        wsum[lane] = v;
    }
    __syncthreads();
    if (wid > 0) s += wsum[wid - 1];
    ps[t] = s;
    __syncthreads();
    float x0 = sx0, xN = sxN;
    const int ks[4] = {10, 50, 100, 500};
    float ma[4];
#pragma unroll
    for (int kk = 0; kk < 4; kk++) {
        int k = ks[kk], f = (k - 1) >> 1, e = k >> 1;
        int lo = t - f, hi = t + e;
        int cl = lo < 0 ? 0 : lo, ch = hi > LZ - 1 ? LZ - 1 : hi;
        float sw = ps[ch] - (cl > 0 ? ps[cl - 1] : 0.f)
                 + (float)(cl - lo) * x0 + (float)(hi - ch) * xN;
        ma[kk] = sw / (float)k;
    }
    float z[4], mx = -1e30f;
#pragma unroll
    for (int kk = 0; kk < 4; kk++) { z[kk] = x * w4[kk] + b4[kk]; mx = fmaxf(mx, z[kk]); }
    float se = 0.f, mean = 0.f;
#pragma unroll
    for (int kk = 0; kk < 4; kk++) { float e2 = expf(z[kk] - mx); se += e2; mean += ma[kk] * e2; }
    mean /= se;
    seas[idx] = x - mean;
    trend[idx] = mean;
}

__device__ __forceinline__ float4 f4add(float4 a, float4 b) {
    return make_float4(a.x + b.x, a.y + b.y, a.z + b.z, a.w + b.w);
}

// ------------------------------------------------------------------ decomp64
__global__ __launch_bounds__(256) void decomp64_kernel(
    const float* __restrict__ A, const float* __restrict__ Bb,
    const float* __restrict__ w4, const float* __restrict__ b4,
    float* __restrict__ seas, float* __restrict__ trend, int accum) {
    __shared__ float4 ps[LZ];
    __shared__ float4 wsum[8];
    __shared__ float4 sedge[2];
    int c4 = blockIdx.x & 15, b = blockIdx.x >> 4;
    int tid = threadIdx.x, lane = tid & 31, wid = tid >> 5;
    int t4 = tid * 4;
    size_t base = ((size_t)(b * LZ + t4)) * DZ + c4 * 4;

    float4 x[4], p[4];
#pragma unroll
    for (int j = 0; j < 4; j++) {
        x[j] = *reinterpret_cast<const float4*>(A + base + (size_t)j * DZ);
        if (Bb) x[j] = f4add(x[j], *reinterpret_cast<const float4*>(Bb + base + (size_t)j * DZ));
    }
    p[0] = x[0];
#pragma unroll
    for (int j = 1; j < 4; j++) p[j] = f4add(p[j - 1], x[j]);

    float4 s = p[3];
#pragma unroll
    for (int off = 1; off < 32; off <<= 1) {
        float4 v;
        v.x = __shfl_up_sync(0xffffffffu, s.x, off);
        v.y = __shfl_up_sync(0xffffffffu, s.y, off);
        v.z = __shfl_up_sync(0xffffffffu, s.z, off);
        v.w = __shfl_up_sync(0xffffffffu, s.w, off);
        if (lane >= off) s = f4add(s, v);
    }
    if (lane == 31) wsum[wid] = s;
    if (tid == 0) sedge[0] = x[0];
    if (tid == 255) sedge[1] = x[3];
    __syncthreads();
    if (wid == 0 && lane < 8) {
        float4 v = wsum[lane];
#pragma unroll
        for (int off = 1; off < 8; off <<= 1) {
            float4 u;
            u.x = __shfl_up_sync(0xffu, v.x, off);
            u.y = __shfl_up_sync(0xffu, v.y, off);
            u.z = __shfl_up_sync(0xffu, v.z, off);
            u.w = __shfl_up_sync(0xffu, v.w, off);
            if (lane >= off) v = f4add(v, u);
        }
        wsum[lane] = v;
    }
    __syncthreads();
    float4 ex = make_float4(0.f, 0.f, 0.f, 0.f);
    if (wid > 0) ex = wsum[wid - 1];
    {
        float4 d;
        d.x = s.x - p[3].x; d.y = s.y - p[3].y; d.z = s.z - p[3].z; d.w = s.w - p[3].w;
        ex = f4add(ex, d);
    }
#pragma unroll
    for (int j = 0; j < 4; j++) ps[t4 + j] = f4add(ex, p[j]);
    __syncthreads();

    float4 x0 = sedge[0], xN = sedge[1];
    const int ks[4] = {10, 50, 100, 500};
#pragma unroll
    for (int j = 0; j < 4; j++) {
        int t = t4 + j;
        float ma[4][4];
#pragma unroll
        for (int kk = 0; kk < 4; kk++) {
            int k = ks[kk], f = (k - 1) >> 1, e = k >> 1;
            int lo = t - f, hi = t + e;
            int cl = lo < 0 ? 0 : lo, ch = hi > LZ - 1 ? LZ - 1 : hi;
            float4 pc = ps[ch];
            float4 pl = make_float4(0.f, 0.f, 0.f, 0.f);
            if (cl > 0) pl = ps[cl - 1];
            float fl = (float)(cl - lo), fr = (float)(hi - ch);
            float inv = 1.f / (float)k;
            ma[kk][0] = (pc.x - pl.x + fl * x0.x + fr * xN.x) * inv;
            ma[kk][1] = (pc.y - pl.y + fl * x0.y + fr * xN.y) * inv;
            ma[kk][2] = (pc.z - pl.z + fl * x0.z + fr * xN.z) * inv;
            ma[kk][3] = (pc.w - pl.w + fl * x0.w + fr * xN.w) * inv;
        }
        float xa[4] = {x[j].x, x[j].y, x[j].z, x[j].w};
        float so[4], tr[4];
#pragma unroll
        for (int cc = 0; cc < 4; cc++) {
            float z[4], mx = -1e30f;
#pragma unroll
            for (int kk = 0; kk < 4; kk++) { z[kk] = xa[cc] * w4[kk] + b4[kk]; mx = fmaxf(mx, z[kk]); }
            float se = 0.f, mean = 0.f;
#pragma unroll
            for (int kk = 0; kk < 4; kk++) { float e2 = expf(z[kk] - mx); se += e2; mean += ma[kk][cc] * e2; }
            mean /= se;
            so[cc] = xa[cc] - mean;
            tr[cc] = mean;
        }
        *reinterpret_cast<float4*>(seas + base + (size_t)j * DZ) =
            make_float4(so[0], so[1], so[2], so[3]);
        if (trend) {
            float4 tv = make_float4(tr[0], tr[1], tr[2], tr[3]);
            if (accum) {
                float4 old = *reinterpret_cast<float4*>(trend + base + (size_t)j * DZ);
                tv = f4add(tv, old);
            }
            *reinterpret_cast<float4*>(trend + base + (size_t)j * DZ) = tv;
        }
    }
}

// ------------------------------------------------------------------ trend/seasonal init
__global__ void trendbase_kernel(const float* __restrict__ dpw, const float* __restrict__ dpb) {
    int idx = blockIdx.x * blockDim.x + threadIdx.x;
    if (idx >= BZ * LZ) return;
    int t = idx & 1023, b = idx >> 10;
    float s = dpb[0];
#pragma unroll
    for (int c = 0; c < C7; c++) {
        float v = (t < 512) ? g_trend0[((size_t)(b * LZ + 512 + t)) * C7 + c]
                            : g_mean7[b * C7 + c];
        s += v * dpw[c];
    }
    g_trendbase[idx] = s;
}

__global__ void seasinit_kernel() {
    int idx = blockIdx.x * blockDim.x + threadIdx.x;
    if (idx >= BZ * LZ * C7) return;
    int c = idx % C7;
    int t = (idx / C7) & 1023;
    int b = idx / (C7 * LZ);
    g_seasinit[idx] = (t < 512) ? g_seas0[((size_t)(b * LZ + 512 + t)) * C7 + c] : 0.f;
}

// ------------------------------------------------------------------ embedding
__global__ void embed_kernel(const float* __restrict__ in, const float* __restrict__ w,
                             float* __restrict__ out) {
    int idx = blockIdx.x * blockDim.x + threadIdx.x;
    if (idx >= BZ * LZ * DZ) return;
    int o = idx & 63;
    int t = (idx >> 6) & 1023;
    int b = idx >> 16;
    float s = 0.f;
#pragma unroll
    for (int j = 0; j < 3; j++) {
        int ts = (t + j - 1 + LZ) & (LZ - 1);
        const float* ip = in + ((size_t)(b * LZ + ts)) * C7;
#pragma unroll
        for (int c = 0; c < C7; c++) s += ip[c] * w[(o * C7 + c) * 3 + j];
    }
    out[idx] = s + g_pe[(t << 6) + o];
}

// ------------------------------------------------------------------ tf32 helpers
__device__ __forceinline__ uint32_t to_tf32(float x) {
    uint32_t r;
    asm("cvt.rna.tf32.f32 %0, %1;" : "=r"(r) : "f"(x));
    return r;
}
__device__ __forceinline__ void cpa16(uint32_t s, const float* g) {
    asm volatile("cp.async.ca.shared.global [%0], [%1], 16;" :: "r"(s), "l"(g));
}
__device__ __forceinline__ void cpa_commit() {
    asm volatile("cp.async.commit_group;");
}
__device__ __forceinline__ void cpa_wait1() {
    asm volatile("cp.async.wait_group 1;");
}

// ------------------------------------------------------------------ tf32 GEMM
#define GT_ASTRIDE (128*36)
#define GT_BSTRIDE (64*36)
#define GT_SMEM ((2*GT_ASTRIDE + 2*GT_BSTRIDE) * 4)

template <int ACT>
__global__ __launch_bounds__(128) void gemm_tc(const float* __restrict__ A,
                                               const float* __restrict__ W,
                                               const float* __restrict__ bias,
                                               float* __restrict__ C,
                                               int N, int K, int O) {
    extern __shared__ float dsm[];
    float* As = dsm;
    float* Bs = dsm + 2 * GT_ASTRIDE;
    const int rb = blockIdx.x * 128;
    const int cb = blockIdx.y * 64;
    const int tid = threadIdx.x;
    const int lane = tid & 31;
    const int w = tid >> 5;
    const int wm = w & 1, wn = w >> 1;
    const int m0 = wm * 64, n0 = wn * 32;
    const int g = lane >> 2, tg = lane & 3;
    const int lrow = tid >> 3;
    const int lcol = (tid & 7) * 4;

    uint32_t sA = (uint32_t)__cvta_generic_to_shared(As);
    uint32_t sB = (uint32_t)__cvta_generic_to_shared(Bs);

    float acc[4][4][4];
#pragma unroll
    for (int mi = 0; mi < 4; mi++)
#pragma unroll
        for (int ni = 0; ni < 4; ni++)
#pragma unroll
            for (int r = 0; r < 4; r++) acc[mi][ni][r] = 0.f;

#pragma unroll
    for (int r = 0; r < 8; r++) {
        int row = lrow + r * 16;
        cpa16(sA + (uint32_t)((row * 36 + lcol) * 4), A + (size_t)(rb + row) * K + lcol);
    }
#pragma unroll
    for (int r = 0; r < 4; r++) {
        int row = lrow + r * 16;
        cpa16(sB + (uint32_t)((row * 36 + lcol) * 4), W + (size_t)(cb + row) * K + lcol);
    }
    cpa_commit();

    int st = 0;
    for (int k0 = 0; k0 < K; k0 += 32, st ^= 1) {
        if (k0 + 32 < K) {
            int nx = st ^ 1;
#pragma unroll
            for (int r = 0; r < 8; r++) {
                int row = lrow + r * 16;
                cpa16(sA + (uint32_t)((nx * GT_ASTRIDE + row * 36 + lcol) * 4),
                      A + (size_t)(rb + row) * K + k0 + 32 + lcol);
            }
#pragma unroll
            for (int r = 0; r < 4; r++) {
                int row = lrow + r * 16;
                cpa16(sB + (uint32_t)((nx * GT_BSTRIDE + row * 36 + lcol) * 4),
                      W + (size_t)(cb + row) * K + k0 + 32 + lcol);
            }
        }
        cpa_commit();
        cpa_wait1();
        __syncthreads();
        const float* Ast = As + st * GT_ASTRIDE;
        const float* Bst = Bs + st * GT_BSTRIDE;
#pragma unroll
        for (int kk = 0; kk < 32; kk += 8) {
            uint32_t a[4][4], bfr[4][2];
#pragma unroll
            for (int mi = 0; mi < 4; mi++) {
                int r = m0 + mi * 16 + g;
                a[mi][0] = to_tf32(Ast[r * 36 + kk + tg]);
                a[mi][1] = to_tf32(Ast[(r + 8) * 36 + kk + tg]);
                a[mi][2] = to_tf32(Ast[r * 36 + kk + tg + 4]);
                a[mi][3] = to_tf32(Ast[(r + 8) * 36 + kk + tg + 4]);
            }
#pragma unroll
            for (int ni = 0; ni < 4; ni++) {
                int c = n0 + ni * 8 + g;
                bfr[ni][0] = to_tf32(Bst[c * 36 + kk + tg]);
                bfr[ni][1] = to_tf32(Bst[c * 36 + kk + tg + 4]);
            }
#pragma unroll
            for (int mi = 0; mi < 4; mi++)
#pragma unroll
                for (int ni = 0; ni < 4; ni++) {
                    asm volatile(
                        "mma.sync.aligned.m16n8k8.row.col.f32.tf32.tf32.f32 "
                        "{%0,%1,%2,%3}, {%4,%5,%6,%7}, {%8,%9}, {%0,%1,%2,%3};"
                        : "+f"(acc[mi][ni][0]), "+f"(acc[mi][ni][1]),
                          "+f"(acc[mi][ni][2]), "+f"(acc[mi][ni][3])
                        : "r"(a[mi][0]), "r"(a[mi][1]), "r"(a[mi][2]), "r"(a[mi][3]),
                          "r"(bfr[ni][0]), "r"(bfr[ni][1]));
                }
        }
        __syncthreads();
    }
#pragma unroll
    for (int mi = 0; mi < 4; mi++) {
        int row0 = rb + m0 + mi * 16 + g;
#pragma unroll
        for (int ni = 0; ni < 4; ni++) {
            int col = cb + n0 + ni * 8 + 2 * tg;
#pragma unroll
            for (int half = 0; half < 2; half++) {
                int row = row0 + half * 8;
                float v0 = acc[mi][ni][half * 2 + 0];
                float v1 = acc[mi][ni][half * 2 + 1];
                if (bias) { v0 += bias[col]; v1 += bias[col + 1]; }
                if (ACT == 1) {
                    v0 = 0.5f * v0 * (1.f + erff(v0 * 0.70710678118654752f));
                    v1 = 0.5f * v1 * (1.f + erff(v1 * 0.70710678118654752f));
                }
                C[(size_t)row * O + col] = v0;
                C[(size_t)row * O + col + 1] = v1;
            }
        }
    }
}

// ------------------------------------------------------------------ DFT GEMM with fused transpose
__device__ __forceinline__ void dft_body(const float* __restrict__ Aq,
                                         const float* __restrict__ F,
                                         float* __restrict__ X,
                                         int b, int cb, int zz) {
    __shared__ float As[64][33];
    __shared__ float Bs[64][36];
    const int tbase = zz * 256;
    const int tid = threadIdx.x;
    const int lane = tid & 31;
    const int w = tid >> 5;
    const int wm = w & 1, wn = w >> 1;
    const int m0 = wm * 32, n0 = wn * 32;
    const int g = lane >> 2, tg = lane & 3;
    const int lrow = tid >> 3;
    const int lcol = (tid & 7) * 4;

    float acc[2][4][4];
#pragma unroll
    for (int mi = 0; mi < 2; mi++)
#pragma unroll
        for (int ni = 0; ni < 4; ni++)
#pragma unroll
            for (int r = 0; r < 4; r++) acc[mi][ni][r] = 0.f;

    for (int t0 = tbase; t0 < tbase + 256; t0 += 32) {
#pragma unroll
        for (int i = 0; i < 4; i++) {
            int f4 = i * 128 + tid;
            int tl = f4 >> 4;
            int he = (f4 & 15) * 4;
            float4 v = *reinterpret_cast<const float4*>(
                Aq + ((size_t)(b * LZ + t0 + tl)) * DZ + he);
            As[he + 0][tl] = v.x;
            As[he + 1][tl] = v.y;
            As[he + 2][tl] = v.z;
            As[he + 3][tl] = v.w;
        }
#pragma unroll
        for (int r = 0; r < 4; r++) {
            int row = lrow + r * 16;
            *reinterpret_cast<float4*>(&Bs[row][lcol]) =
                *reinterpret_cast<const float4*>(F + (size_t)(cb + row) * LZ + t0 + lcol);
        }
        __syncthreads();
#pragma unroll
        for (int kk = 0; kk < 32; kk += 8) {
            uint32_t a[2][4], bfr[4][2];
#pragma unroll
            for (int mi = 0; mi < 2; mi++) {
                int r = m0 + mi * 16 + g;
                a[mi][0] = to_tf32(As[r][kk + tg]);
                a[mi][1] = to_tf32(As[r + 8][kk + tg]);
                a[mi][2] = to_tf32(As[r][kk + tg + 4]);
                a[mi][3] = to_tf32(As[r + 8][kk + tg + 4]);
            }
#pragma unroll
            for (int ni = 0; ni < 4; ni++) {
                int c = n0 + ni * 8 + g;
                bfr[ni][0] = to_tf32(Bs[c][kk + tg]);
                bfr[ni][1] = to_tf32(Bs[c][kk + tg + 4]);
            }
#pragma unroll
            for (int mi = 0; mi < 2; mi++)
#pragma unroll
                for (int ni = 0; ni < 4; ni++) {
                    asm volatile(
                        "mma.sync.aligned.m16n8k8.row.col.f32.tf32.tf32.f32 "
                        "{%0,%1,%2,%3}, {%4,%5,%6,%7}, {%8,%9}, {%0,%1,%2,%3};"
                        : "+f"(acc[mi][ni][0]), "+f"(acc[mi][ni][1]),
                          "+f"(acc[mi][ni][2]), "+f"(acc[mi][ni][3])
                        : "r"(a[mi][0]), "r"(a[mi][1]), "r"(a[mi][2]), "r"(a[mi][3]),
                          "r"(bfr[ni][0]), "r"(bfr[ni][1]));
                }
        }
        __syncthreads();
    }
#pragma unroll
    for (int mi = 0; mi < 2; mi++) {
        int r0 = m0 + mi * 16 + g;
#pragma unroll
        for (int ni = 0; ni < 4; ni++) {
            int col = cb + n0 + ni * 8 + 2 * tg;
#pragma unroll
            for (int half = 0; half < 2; half++) {
                int row = r0 + half * 8;
                atomicAdd(&X[(size_t)(b * 64 + row) * M2 + col], acc[mi][ni][half * 2 + 0]);
                atomicAdd(&X[(size_t)(b * 64 + row) * M2 + col + 1], acc[mi][ni][half * 2 + 1]);
            }
        }
    }
}

__global__ __launch_bounds__(128) void gemm_dft(const float* __restrict__ Aq,
                                                const float* __restrict__ F,
                                                float* __restrict__ X) {
    dft_body(Aq, F, X, blockIdx.x, blockIdx.y * 64, blockIdx.z);
}

__global__ __launch_bounds__(128) void gemm_dft2(const float* __restrict__ Aq1,
                                                 float* __restrict__ X1,
                                                 const float* __restrict__ Aq2,
                                                 float* __restrict__ X2,
                                                 const float* __restrict__ F) {
    int z = blockIdx.z;
    if (z < 4) dft_body(Aq1, F, X1, blockIdx.x, blockIdx.y * 64, z);
    else       dft_body(Aq2, F, X2, blockIdx.x, blockIdx.y * 64, z - 4);
}

// ------------------------------------------------------------------ mode-space projection (cross path)
__global__ __launch_bounds__(256) void modeproj_kernel(const float* __restrict__ Hf,
                                                       const float* __restrict__ Wq,
                                                       const float* __restrict__ bq,
                                                       const float* __restrict__ cm,
                                                       float* __restrict__ Qf) {
    __shared__ float Hs[64][68];
    __shared__ float Ws[64][68];
    int b = blockIdx.x;
    int mh = blockIdx.y;
    int tid = threadIdx.x;
    for (int i = tid; i < 64 * 16; i += 256) {
        int d = i >> 4;
        int c4 = (i & 15) * 4;
        *reinterpret_cast<float4*>(&Hs[d][c4]) =
            *reinterpret_cast<const float4*>(Hf + ((size_t)(b * 64 + d)) * M2 + mh * 64 + c4);
    }
    for (int i = tid; i < 64 * 16; i += 256) {
        int he = i >> 4;
        int c4 = (i & 15) * 4;
        *reinterpret_cast<float4*>(&Ws[he][c4]) =
            *reinterpret_cast<const float4*>(Wq + he * 64 + c4);
    }
    __syncthreads();
    if (cm && mh == 0 && tid < 64) Hs[tid][0] -= cm[b * 64 + tid] * 1024.f;
    __syncthreads();
    int he = tid >> 2;
    int mg = tid & 3;
#pragma unroll
    for (int j = 0; j < 16; j++) {
        int ml = mg + 4 * j;
        float s = 0.f;
#pragma unroll
        for (int d = 0; d < 64; d++) s += Ws[he][d] * Hs[d][ml];
        int m2 = mh * 64 + ml;
        if (m2 == 0) s += bq[he] * 1024.f;
        Qf[((size_t)(b * 64 + he)) * M2 + m2] = s;
    }
}

// ------------------------------------------------------------------ fused modeproj + mode_mix (self-attn)
#define MPM_SMEM ((2*64*68 + 64*66) * 4)
__global__ __launch_bounds__(256) void modeproj_mix_kernel(const float* __restrict__ Hf,
                                                           const float* __restrict__ Wq,
                                                           const float* __restrict__ bq,
                                                           const float* __restrict__ wr,
                                                           const float* __restrict__ wi,
                                                           float* __restrict__ sel,
                                                           float scale) {
    extern __shared__ float sm[];
    float* Hs = sm;
    float* Ws = sm + 64 * 68;
    float* Qs = sm + 2 * 64 * 68;
    int b = blockIdx.x;
    int mh = blockIdx.y;
    int tid = threadIdx.x;
    for (int i = tid; i < 64 * 16; i += 256) {
        int d = i >> 4;
        int c4 = (i & 15) * 4;
        *reinterpret_cast<float4*>(&Hs[d * 68 + c4]) =
            *reinterpret_cast<const float4*>(Hf + ((size_t)(b * 64 + d)) * M2 + mh * 64 + c4);
    }
    for (int i = tid; i < 64 * 16; i += 256) {
        int he = i >> 4;
        int c4 = (i & 15) * 4;
        *reinterpret_cast<float4*>(&Ws[he * 68 + c4]) =
            *reinterpret_cast<const float4*>(Wq + he * 64 + c4);
    }
    __syncthreads();
    {
        int he = tid >> 2;
        int mg = tid & 3;
#pragma unroll
        for (int j = 0; j < 16; j++) {
            int ml = mg + 4 * j;
            float s = 0.f;
#pragma unroll
            for (int d = 0; d < 64; d++) s += Ws[he * 68 + d] * Hs[d * 68 + ml];
            if (mh == 0 && ml == 0) s += bq[he] * 1024.f;
            Qs[he * 66 + ml] = s;
        }
    }
    __syncthreads();
    {
        int lm = tid & 31;
        int hob = tid >> 5;
        int m = mh * 32 + lm;
#pragma unroll
        for (int j = 0; j < 8; j++) {
            int ho = hob * 8 + j;
            int h = ho >> 3, o = ho & 7;
            float ar = 0.f, ai = 0.f;
#pragma unroll
            for (int e = 0; e < 8; e++) {
                float xr = Qs[(h * 8 + e) * 66 + 2 * lm];
                float xi = Qs[(h * 8 + e) * 66 + 2 * lm + 1];
                int wix = ((h * 8 + e) * 8 + o) * MZ + m;
                float wrv = wr[wix], wiv = wi[wix];
                ar += xr * wrv - xi * wiv;
                ai += xr * wiv + xi * wrv;
            }
            size_t ro = ((size_t)(b * 64 + h * 8 + o)) * M2 + 2 * m;
            sel[ro] = ar * scale;
            sel[ro + 1] = ai * scale;
        }
    }
}

// ------------------------------------------------------------------ fused cross attention
__global__ __launch_bounds__(256) void qkattn_kernel(const float* __restrict__ Qf,
                                                     const float* __restrict__ Kf,
                                                     const float* __restrict__ wr,
                                                     const float* __restrict__ wi,
                                                     float* __restrict__ sel,
                                                     float scale) {
    __shared__ float Qs[8][128];
    __shared__ float Ks[8][128];
    __shared__ float qks[64][130];
    __shared__ float Vs[8][128];
    int bh = blockIdx.x;
    int h = bh & 7, b = bh >> 3;
    int tid = threadIdx.x;
    size_t tbase = (size_t)(b * 64 + h * 8) * M2;
#pragma unroll
    for (int i = 0; i < 4; i++) {
        int f = i * 256 + tid;
        int e = f >> 7, c = f & 127;
        Qs[e][c] = Qf[tbase + e * M2 + c];
        Ks[e][c] = Kf[tbase + e * M2 + c];
    }
    __syncthreads();
    {
        int x = tid >> 2;
        int ys = tid & 3;
#pragma unroll
        for (int j = 0; j < 16; j++) {
            int y = ys * 16 + j;
            float ar = 0.f, ai = 0.f;
#pragma unroll
            for (int e = 0; e < 8; e++) {
                float qr = Qs[e][2 * x], qi = Qs[e][2 * x + 1];
                float kr = Ks[e][2 * y], ki = Ks[e][2 * y + 1];
                ar += qr * kr - qi * ki;
                ai += qr * ki + qi * kr;
            }
            float a2 = 2.f * ar, b2 = 2.f * ai;
            float tr, ti;
            if (fabsf(a2) > 30.f) {
                tr = copysignf(1.f, ar);
                ti = 0.f;
            } else {
                float sn, cs;
                sincosf(b2, &sn, &cs);
                float ex = expf(a2);
                float exi = 1.f / ex;
                float den = 0.5f * (ex + exi) + cs;
                tr = 0.5f * (ex - exi) / den;
                ti = sn / den;
            }
            qks[x][2 * y] = tr;
            qks[x][2 * y + 1] = ti;
        }
    }
    __syncthreads();
    {
        int flat0 = tid * 2;
#pragma unroll
        for (int u = 0; u < 2; u++) {
            int flat = flat0 + u;
            int e = flat >> 6, x = flat & 63;
            float ar = 0.f, ai = 0.f;
#pragma unroll 16
            for (int y = 0; y < 64; y++) {
                float qr = qks[x][2 * y], qi = qks[x][2 * y + 1];
                float kr = Ks[e][2 * y], ki = Ks[e][2 * y + 1];
                ar += qr * kr - qi * ki;
                ai += qr * ki + qi * kr;
            }
            Vs[e][2 * x] = ar;
            Vs[e][2 * x + 1] = ai;
        }
    }
    __syncthreads();
    {
        int m = tid & 63;
        int og = tid >> 6;
#pragma unroll
        for (int j = 0; j < 2; j++) {
            int o = og * 2 + j;
            float ar = 0.f, ai = 0.f;
#pragma unroll
            for (int e = 0; e < 8; e++) {
                float xr = Vs[e][2 * m], xi = Vs[e][2 * m + 1];
                int wix = ((h * 8 + e) * 8 + o) * MZ + m;
                float wrv = wr[wix], wiv = wi[wix];
                ar += xr * wrv - xi * wiv;
                ai += xr * wiv + xi * wrv;
            }
            size_t ro = ((size_t)(b * 64 + h * 8 + o)) * M2 + 2 * m;
            sel[ro] = ar * scale;
            sel[ro + 1] = ai * scale;
        }
    }
}

// ------------------------------------------------------------------ layernorm family
__global__ void ln_row_kernel(const float* __restrict__ X, const float* __restrict__ g,
                              const float* __restrict__ be, float* __restrict__ out) {
    __shared__ float red[256];
    int tid = threadIdx.x;
    int sub = tid >> 6;
    int d = tid & 63;
    int row = blockIdx.x * 4 + sub;
    float v = X[(size_t)row * DZ + d];
    red[tid] = v;
    __syncthreads();
    for (int s = 32; s > 0; s >>= 1) {
        if (d < s) red[tid] += red[tid + s];
        __syncthreads();
    }
    float mu = red[sub * 64] * (1.f / 64.f);
    __syncthreads();
    float dv = v - mu;
    red[tid] = dv * dv;
    __syncthreads();
    for (int s = 32; s > 0; s >>= 1) {
        if (d < s) red[tid] += red[tid + s];
        __syncthreads();
    }
    float var = red[sub * 64] * (1.f / 64.f);
    out[(size_t)row * DZ + d] = dv * rsqrtf(var + 1e-5f) * g[d] + be[d];
}

__global__ void colmean_kernel(const float* __restrict__ X, float* __restrict__ cm) {
    __shared__ float r[256];
    int b = blockIdx.x / DZ, d = blockIdx.x % DZ;
    float s = 0.f;
    for (int t = threadIdx.x; t < LZ; t += 256) s += X[((size_t)(b * LZ + t)) * DZ + d];
    r[threadIdx.x] = s;
    __syncthreads();
    for (int o = 128; o > 0; o >>= 1) {
        if (threadIdx.x < o) r[threadIdx.x] += r[threadIdx.x + o];
        __syncthreads();
    }
    if (threadIdx.x == 0) cm[b * DZ + d] = r[0] * (1.f / LZ);
}

// ------------------------------------------------------------------ final epilogue
__global__ void final_kernel(const float* __restrict__ xln, const float* __restrict__ cm,
                             const float* __restrict__ tacc,
                             const float* __restrict__ tbase, const float* __restrict__ tw,
                             const float* __restrict__ pw, const float* __restrict__ pb,
                             float* __restrict__ out) {
    int idx = blockIdx.x * blockDim.x + threadIdx.x;
    if (idx >= BZ * 512) return;
    int t = idx & 511, b = idx >> 9;
    int tt = t + 512;
    float cv = 0.f;
#pragma unroll
    for (int j = 0; j < 3; j++) {
        int ts = (tt + j - 1) & (LZ - 1);
        const float* row = tacc + ((size_t)(b * LZ + ts)) * DZ;
#pragma unroll 4
        for (int d4 = 0; d4 < 16; d4++) {
            float4 rv = *reinterpret_cast<const float4*>(row + d4 * 4);
            cv += rv.x * tw[(d4 * 4 + 0) * 3 + j] + rv.y * tw[(d4 * 4 + 1) * 3 + j]
                + rv.z * tw[(d4 * 4 + 2) * 3 + j] + rv.w * tw[(d4 * 4 + 3) * 3 + j];
        }
    }
    float p = pb[0];
    const float* xr = xln + ((size_t)(b * LZ + tt)) * DZ;
    const float* cmr = cm + b * DZ;
#pragma unroll 4
    for (int d4 = 0; d4 < 16; d4++) {
        float4 xv = *reinterpret_cast<const float4*>(xr + d4 * 4);
        float4 cvv = *reinterpret_cast<const float4*>(cmr + d4 * 4);
        float4 pv = *reinterpret_cast<const float4*>(pw + d4 * 4);
        p += (xv.x - cvv.x) * pv.x + (xv.y - cvv.y) * pv.y
           + (xv.z - cvv.z) * pv.z + (xv.w - cvv.w) * pv.w;
    }
    out[idx] = p + cv + tbase[b * LZ + tt];
}

static float* symaddr_f(const void* sym) {
    void* p = nullptr;
    cudaGetSymbolAddress(&p, sym);
    return (float*)p;
}

extern "C" void kernel_launch(void* const* d_in, const int* in_sizes, int n_in,
                              void* d_out, int out_size) {
    const float* x_enc       = (const float*)d_in[0];
    const float* dp_w        = (const float*)d_in[1];
    const float* dp_b        = (const float*)d_in[2];
    const float* emb_enc_w   = (const float*)d_in[3];
    const float* emb_dec_w   = (const float*)d_in[4];
    const float* decomp_w    = (const float*)d_in[5];
    const float* decomp_b    = (const float*)d_in[6];
    const float* enc_attn_w  = (const float*)d_in[7];
    const float* enc_attn_b  = (const float*)d_in[8];
    const float* enc_four_wr = (const float*)d_in[9];
    const float* enc_four_wi = (const float*)d_in[10];
    const float* enc_c1      = (const float*)d_in[11];
    const float* enc_c2      = (const float*)d_in[12];
    const float* enc_ln_g    = (const float*)d_in[13];
    const float* enc_ln_b    = (const float*)d_in[14];
    const float* dec_self_w  = (const float*)d_in[15];
    const float* dec_self_b  = (const float*)d_in[16];
    const float* dec_four_wr = (const float*)d_in[17];
    const float* dec_four_wi = (const float*)d_in[18];
    const float* dec_cross_w = (const float*)d_in[19];
    const float* dec_cross_b = (const float*)d_in[20];
    const float* dec_cross_wr= (const float*)d_in[21];
    const float* dec_cross_wi= (const float*)d_in[22];
    const float* dec_c1      = (const float*)d_in[23];
    const float* dec_c2      = (const float*)d_in[24];
    const float* dec_trend_w = (const float*)d_in[25];
    const float* dec_ln_g    = (const float*)d_in[26];
    const float* dec_ln_b    = (const float*)d_in[27];
    const float* dec_proj_w  = (const float*)d_in[28];
    const float* dec_proj_b  = (const float*)d_in[29];
    float* out = (float*)d_out;

    float* px        = symaddr_f(g_x);
    float* pseas0    = symaddr_f(g_seas0);
    float* ptrend0   = symaddr_f(g_trend0);
    float* pseasinit = symaddr_f(g_seasinit);
    float* ph        = symaddr_f(g_h);
    float* py        = symaddr_f(g_y);
    float* pa        = symaddr_f(g_a);
    float* py2       = symaddr_f(g_y2);
    float* pa2       = symaddr_f(g_a2);
    float* pffn      = symaddr_f(g_ffn);
    float* pHf       = symaddr_f(g_Hf);
    float* pHf2      = pHf + (size_t)NHE * M2;
    float* pXf       = symaddr_f(g_Xf);
    float* pXk       = symaddr_f(g_Xk);
    float* psel      = symaddr_f(g_sel);
    float* psel2     = symaddr_f(g_sel2);
    float* pxd       = symaddr_f(g_xd);
    float* ptacc     = symaddr_f(g_tacc);
    float* pcm       = symaddr_f(g_cm);
    float* pcm2      = symaddr_f(g_cm2);
    float* pln       = symaddr_f(g_ln);
    float* pF        = symaddr_f(g_F);
    float* pFi       = symaddr_f(g_Fi);
    float* ptbase    = symaddr_f(g_trendbase);

    cudaFuncSetAttribute(gemm_tc<0>, cudaFuncAttributeMaxDynamicSharedMemorySize, GT_SMEM);
    cudaFuncSetAttribute(gemm_tc<1>, cudaFuncAttributeMaxDynamicSharedMemorySize, GT_SMEM);
    cudaFuncSetAttribute(modeproj_mix_kernel, cudaFuncAttributeMaxDynamicSharedMemorySize, MPM_SMEM);

    static cudaStream_t s2 = nullptr;
    static cudaEvent_t evFork = nullptr, evJoin = nullptr;
    if (!s2) {
        cudaStreamCreateWithFlags(&s2, cudaStreamNonBlocking);
        cudaEventCreateWithFlags(&evFork, cudaEventDisableTiming);
        cudaEventCreateWithFlags(&evJoin, cudaEventDisableTiming);
    }

    dim3 dftg(BZ, 2, 4);
    dim3 dftg2(BZ, 2, 8);
    dim3 mpg(BZ, 2);

    // ---- shared prep (stream 0) ----
    build_tables_kernel<<<512, 256>>>();
    transpose_in_kernel<<<1792, 256>>>(x_enc);
    colmean7_kernel<<<BZ * C7, 256>>>(x_enc);
    decomp7_kernel<<<BZ * C7, LZ>>>(px, decomp_w + 0, decomp_b + 0, pseas0, ptrend0);
    trendbase_kernel<<<256, 256>>>(dp_w, dp_b);
    seasinit_kernel<<<1792, 256>>>();
    cudaEventRecord(evFork, 0);

    // ---- decoder prefix (stream s2) ----
    cudaStreamWaitEvent(s2, evFork, 0);
    embed_kernel<<<16384, 256, 0, s2>>>(pseasinit, emb_dec_w, pxd);
    cudaMemsetAsync(pHf2, 0, (size_t)NHE * M2 * sizeof(float), s2);
    gemm_dft<<<dftg, 128, 0, s2>>>(pxd, pF, pHf2);
    modeproj_mix_kernel<<<mpg, 256, MPM_SMEM, s2>>>(pHf2, dec_self_w + 0, dec_self_b + 0,
                                                    dec_four_wr, dec_four_wi, psel2, 1.0f);
    gemm_tc<0><<<dim3(32, 16), 128, GT_SMEM, s2>>>(psel2, pFi, nullptr, py2, NHE, 128, 1024);
    gemm_tc<0><<<dim3(512, 1), 128, GT_SMEM, s2>>>(py2, dec_self_w + 3 * 4096,
                                                   dec_self_b + 3 * 64, pa2, NROW, 64, 64);
    decomp64_kernel<<<1024, 256, 0, s2>>>(pxd, pa2, decomp_w + 5 * 4, decomp_b + 5 * 4,
                                          pxd, ptacc, 0);
    cudaEventRecord(evJoin, s2);

    // ---- encoder (stream 0) ----
    embed_kernel<<<16384, 256>>>(px, emb_enc_w, ph);
    for (int l = 0; l < 2; l++) {
        const float* wq = enc_attn_w + (size_t)(l * 4 + 0) * 4096;
        const float* bq = enc_attn_b + (size_t)(l * 4 + 0) * 64;
        const float* wo = enc_attn_w + (size_t)(l * 4 + 3) * 4096;
        const float* bo = enc_attn_b + (size_t)(l * 4 + 3) * 64;
        cudaMemsetAsync(pHf, 0, (size_t)NHE * M2 * sizeof(float));
        gemm_dft<<<dftg, 128>>>(ph, pF, pHf);
        modeproj_mix_kernel<<<mpg, 256, MPM_SMEM>>>(pHf, wq, bq,
                                                    enc_four_wr + (size_t)l * 32768,
                                                    enc_four_wi + (size_t)l * 32768, psel, 1.0f);
        gemm_tc<0><<<dim3(32, 16), 128, GT_SMEM>>>(psel, pFi, nullptr, py, NHE, 128, 1024);
        gemm_tc<0><<<dim3(512, 1), 128, GT_SMEM>>>(py, wo, bo, pa, NROW, 64, 64);
        decomp64_kernel<<<1024, 256>>>(ph, pa, decomp_w + (1 + 2 * l) * 4,
                                       decomp_b + (1 + 2 * l) * 4, ph, nullptr, 0);
        gemm_tc<1><<<dim3(512, 4), 128, GT_SMEM>>>(ph, enc_c1 + (size_t)l * 16384, nullptr, pffn,
                                                   NROW, 64, 256);
        gemm_tc<0><<<dim3(512, 1), 128, GT_SMEM>>>(pffn, enc_c2 + (size_t)l * 16384, nullptr, py,
                                                   NROW, 256, 64);
        decomp64_kernel<<<1024, 256>>>(ph, py, decomp_w + (2 + 2 * l) * 4,
                                       decomp_b + (2 + 2 * l) * 4, ph, nullptr, 0);
    }
    ln_row_kernel<<<16384, 256>>>(ph, enc_ln_g, enc_ln_b, ph);
    colmean_kernel<<<BZ * DZ, 256>>>(ph, pcm2);

    // ---- join, then cross attention ----
    cudaStreamWaitEvent(0, evJoin, 0);
    cudaMemsetAsync(pHf, 0, (size_t)2 * NHE * M2 * sizeof(float));
    gemm_dft2<<<dftg2, 128>>>(pxd, pHf, ph, pHf2, pF);
    modeproj_kernel<<<mpg, 256>>>(pHf, dec_cross_w + 0, dec_cross_b + 0, nullptr, pXf);
    modeproj_kernel<<<mpg, 256>>>(pHf2, dec_cross_w + 1 * 4096, dec_cross_b + 1 * 64, pcm2, pXk);
    qkattn_kernel<<<512, 256>>>(pXf, pXk, dec_cross_wr, dec_cross_wi, psel, 1.0f / 4096.0f);
    gemm_tc<0><<<dim3(32, 16), 128, GT_SMEM>>>(psel, pFi, nullptr, py, NHE, 128, 1024);
    gemm_tc<0><<<dim3(512, 1), 128, GT_SMEM>>>(py, dec_cross_w + 3 * 4096, dec_cross_b + 3 * 64, pa,
                                               NROW, 64, 64);
    decomp64_kernel<<<1024, 256>>>(pxd, pa, decomp_w + 6 * 4, decomp_b + 6 * 4, pxd, ptacc, 1);

    gemm_tc<1><<<dim3(512, 4), 128, GT_SMEM>>>(pxd, dec_c1, nullptr, pffn, NROW, 64, 256);
    gemm_tc<0><<<dim3(512, 1), 128, GT_SMEM>>>(pffn, dec_c2, nullptr, py, NROW, 256, 64);
    decomp64_kernel<<<1024, 256>>>(pxd, py, decomp_w + 7 * 4, decomp_b + 7 * 4, pxd, ptacc, 1);

    ln_row_kernel<<<16384, 256>>>(pxd, dec_ln_g, dec_ln_b, pln);
    colmean_kernel<<<BZ * DZ, 256>>>(pln, pcm);
    final_kernel<<<128, 256>>>(pln, pcm, ptacc, ptbase, dec_trend_w, dec_proj_w, dec_proj_b, out);
}

// round 11
// speedup vs baseline: 2.3077x; 1.0138x over previous
#include <cuda_runtime.h>
#include <cstdint>

#define BZ 64
#define LZ 1024
#define DZ 64
#define C7 7
#define HZ 8
#define EZ 8
#define MZ 64
#define M2 128
#define DFFD 256
#define NROW (BZ*LZ)
#define NHE  (BZ*DZ)

__device__ float g_x[BZ*LZ*C7];
__device__ float g_seas0[BZ*LZ*C7];
__device__ float g_trend0[BZ*LZ*C7];
__device__ float g_mean7[BZ*C7];
__device__ float g_trendbase[BZ*LZ];
__device__ float g_seasinit[BZ*LZ*C7];
__device__ float g_h[NROW*DZ];
__device__ float g_y[NROW*DZ];
__device__ float g_a[NROW*DZ];
__device__ float g_y2[NROW*DZ];
__device__ float g_a2[NROW*DZ];
__device__ float g_Hf[2*NHE*M2];
__device__ float g_Xf[NHE*M2];
__device__ float g_Xk[NHE*M2];
__device__ float g_sel[NHE*M2];
__device__ float g_sel2[NHE*M2];
__device__ float g_xd[NROW*DZ];
__device__ float g_tacc[NROW*DZ];
__device__ float g_cm[BZ*DZ];
__device__ float g_cm2[BZ*DZ];
__device__ float g_ln[NROW*DZ];
__device__ float g_F[M2*LZ];
__device__ float g_Fi[LZ*M2];
__device__ float g_pe[LZ*DZ];

// ------------------------------------------------------------------ tables
__global__ void build_tables_kernel() {
    int idx = blockIdx.x * blockDim.x + threadIdx.x;
    if (idx < LZ * M2) {
        int t = idx >> 7;
        int m2 = idx & 127;
        int m = m2 >> 1;
        int r = (m * t) & (LZ - 1);
        float a = (float)r * (6.28318530717958647692f / (float)LZ);
        float s, c;
        sincosf(a, &s, &c);
        float v = (m2 & 1) ? -s : c;
        g_F[(size_t)m2 * LZ + t] = v;
        float cm = (m == 0) ? 1.f : 2.f;
        g_Fi[(size_t)t * M2 + m2] = v * (cm / (float)LZ);
    }
    if (idx < LZ * DZ) {
        int o = idx & 63;
        int t = idx >> 6;
        int i2 = o & ~1;
        float div = expf(-(float)i2 * 0.14391156831212793f);
        float arg = (float)t * div;
        g_pe[idx] = (o & 1) ? cosf(arg) : sinf(arg);
    }
}

// ------------------------------------------------------------------ input prep
__global__ void transpose_in_kernel(const float* __restrict__ xe) {
    int idx = blockIdx.x * blockDim.x + threadIdx.x;
    if (idx >= BZ * C7 * LZ) return;
    int t = idx & 1023;
    int c = (idx >> 10) % C7;
    int b = idx / (C7 * LZ);
    g_x[((size_t)(b * LZ + t)) * C7 + c] = xe[idx];
}

__global__ void colmean7_kernel(const float* __restrict__ xe) {
    __shared__ float r[256];
    int bc = blockIdx.x;
    float s = 0.f;
    for (int t = threadIdx.x; t < LZ; t += 256) s += xe[(size_t)bc * LZ + t];
    r[threadIdx.x] = s;
    __syncthreads();
    for (int o = 128; o > 0; o >>= 1) {
        if (threadIdx.x < o) r[threadIdx.x] += r[threadIdx.x + o];
        __syncthreads();
    }
    if (threadIdx.x == 0) g_mean7[bc] = r[0] * (1.f / LZ);
}

// ------------------------------------------------------------------ decomp7
__global__ void decomp7_kernel(const float* __restrict__ A,
                               const float* __restrict__ w4, const float* __restrict__ b4,
                               float* __restrict__ seas, float* __restrict__ trend) {
    __shared__ float ps[LZ];
    __shared__ float wsum[32];
    __shared__ float sx0, sxN;
    int c = blockIdx.x % C7, b = blockIdx.x / C7;
    int t = threadIdx.x, lane = t & 31, wid = t >> 5;
    size_t idx = ((size_t)(b * LZ + t)) * C7 + c;
    float x = A[idx];
    float s = x;
#pragma unroll
    for (int off = 1; off < 32; off <<= 1) {
        float v = __shfl_up_sync(0xffffffffu, s, off);
        if (lane >= off) s += v;
    }
    if (lane == 31) wsum[wid] = s;
    if (t == 0) sx0 = x;
    if (t == LZ - 1) sxN = x;
    __syncthreads();
    if (wid == 0) {
        float v = wsum[lane];
#pragma unroll
        for (int off = 1; off < 32; off <<= 1) {
            float u = __shfl_up_sync(0xffffffffu, v, off);
            if (lane >= off) v += u;
        }
        wsum[lane] = v;
    }
    __syncthreads();
    if (wid > 0) s += wsum[wid - 1];
    ps[t] = s;
    __syncthreads();
    float x0 = sx0, xN = sxN;
    const int ks[4] = {10, 50, 100, 500};
    float ma[4];
#pragma unroll
    for (int kk = 0; kk < 4; kk++) {
        int k = ks[kk], f = (k - 1) >> 1, e = k >> 1;
        int lo = t - f, hi = t + e;
        int cl = lo < 0 ? 0 : lo, ch = hi > LZ - 1 ? LZ - 1 : hi;
        float sw = ps[ch] - (cl > 0 ? ps[cl - 1] : 0.f)
                 + (float)(cl - lo) * x0 + (float)(hi - ch) * xN;
        ma[kk] = sw / (float)k;
    }
    float z[4], mx = -1e30f;
#pragma unroll
    for (int kk = 0; kk < 4; kk++) { z[kk] = x * w4[kk] + b4[kk]; mx = fmaxf(mx, z[kk]); }
    float se = 0.f, mean = 0.f;
#pragma unroll
    for (int kk = 0; kk < 4; kk++) { float e2 = expf(z[kk] - mx); se += e2; mean += ma[kk] * e2; }
    mean /= se;
    seas[idx] = x - mean;
    trend[idx] = mean;
}

__device__ __forceinline__ float4 f4add(float4 a, float4 b) {
    return make_float4(a.x + b.x, a.y + b.y, a.z + b.z, a.w + b.w);
}

// ------------------------------------------------------------------ decomp64
__global__ __launch_bounds__(256) void decomp64_kernel(
    const float* __restrict__ A, const float* __restrict__ Bb,
    const float* __restrict__ w4, const float* __restrict__ b4,
    float* __restrict__ seas, float* __restrict__ trend, int accum) {
    __shared__ float4 ps[LZ];
    __shared__ float4 wsum[8];
    __shared__ float4 sedge[2];
    int c4 = blockIdx.x & 15, b = blockIdx.x >> 4;
    int tid = threadIdx.x, lane = tid & 31, wid = tid >> 5;
    int t4 = tid * 4;
    size_t base = ((size_t)(b * LZ + t4)) * DZ + c4 * 4;

    float4 x[4], p[4];
#pragma unroll
    for (int j = 0; j < 4; j++) {
        x[j] = *reinterpret_cast<const float4*>(A + base + (size_t)j * DZ);
        if (Bb) x[j] = f4add(x[j], *reinterpret_cast<const float4*>(Bb + base + (size_t)j * DZ));
    }
    p[0] = x[0];
#pragma unroll
    for (int j = 1; j < 4; j++) p[j] = f4add(p[j - 1], x[j]);

    float4 s = p[3];
#pragma unroll
    for (int off = 1; off < 32; off <<= 1) {
        float4 v;
        v.x = __shfl_up_sync(0xffffffffu, s.x, off);
        v.y = __shfl_up_sync(0xffffffffu, s.y, off);
        v.z = __shfl_up_sync(0xffffffffu, s.z, off);
        v.w = __shfl_up_sync(0xffffffffu, s.w, off);
        if (lane >= off) s = f4add(s, v);
    }
    if (lane == 31) wsum[wid] = s;
    if (tid == 0) sedge[0] = x[0];
    if (tid == 255) sedge[1] = x[3];
    __syncthreads();
    if (wid == 0 && lane < 8) {
        float4 v = wsum[lane];
#pragma unroll
        for (int off = 1; off < 8; off <<= 1) {
            float4 u;
            u.x = __shfl_up_sync(0xffu, v.x, off);
            u.y = __shfl_up_sync(0xffu, v.y, off);
            u.z = __shfl_up_sync(0xffu, v.z, off);
            u.w = __shfl_up_sync(0xffu, v.w, off);
            if (lane >= off) v = f4add(v, u);
        }
        wsum[lane] = v;
    }
    __syncthreads();
    float4 ex = make_float4(0.f, 0.f, 0.f, 0.f);
    if (wid > 0) ex = wsum[wid - 1];
    {
        float4 d;
        d.x = s.x - p[3].x; d.y = s.y - p[3].y; d.z = s.z - p[3].z; d.w = s.w - p[3].w;
        ex = f4add(ex, d);
    }
#pragma unroll
    for (int j = 0; j < 4; j++) ps[t4 + j] = f4add(ex, p[j]);
    __syncthreads();

    float4 x0 = sedge[0], xN = sedge[1];
    const int ks[4] = {10, 50, 100, 500};
#pragma unroll
    for (int j = 0; j < 4; j++) {
        int t = t4 + j;
        float ma[4][4];
#pragma unroll
        for (int kk = 0; kk < 4; kk++) {
            int k = ks[kk], f = (k - 1) >> 1, e = k >> 1;
            int lo = t - f, hi = t + e;
            int cl = lo < 0 ? 0 : lo, ch = hi > LZ - 1 ? LZ - 1 : hi;
            float4 pc = ps[ch];
            float4 pl = make_float4(0.f, 0.f, 0.f, 0.f);
            if (cl > 0) pl = ps[cl - 1];
            float fl = (float)(cl - lo), fr = (float)(hi - ch);
            float inv = 1.f / (float)k;
            ma[kk][0] = (pc.x - pl.x + fl * x0.x + fr * xN.x) * inv;
            ma[kk][1] = (pc.y - pl.y + fl * x0.y + fr * xN.y) * inv;
            ma[kk][2] = (pc.z - pl.z + fl * x0.z + fr * xN.z) * inv;
            ma[kk][3] = (pc.w - pl.w + fl * x0.w + fr * xN.w) * inv;
        }
        float xa[4] = {x[j].x, x[j].y, x[j].z, x[j].w};
        float so[4], tr[4];
#pragma unroll
        for (int cc = 0; cc < 4; cc++) {
            float z[4], mx = -1e30f;
#pragma unroll
            for (int kk = 0; kk < 4; kk++) { z[kk] = xa[cc] * w4[kk] + b4[kk]; mx = fmaxf(mx, z[kk]); }
            float se = 0.f, mean = 0.f;
#pragma unroll
            for (int kk = 0; kk < 4; kk++) { float e2 = expf(z[kk] - mx); se += e2; mean += ma[kk][cc] * e2; }
            mean /= se;
            so[cc] = xa[cc] - mean;
            tr[cc] = mean;
        }
        *reinterpret_cast<float4*>(seas + base + (size_t)j * DZ) =
            make_float4(so[0], so[1], so[2], so[3]);
        if (trend) {
            float4 tv = make_float4(tr[0], tr[1], tr[2], tr[3]);
            if (accum) {
                float4 old = *reinterpret_cast<float4*>(trend + base + (size_t)j * DZ);
                tv = f4add(tv, old);
            }
            *reinterpret_cast<float4*>(trend + base + (size_t)j * DZ) = tv;
        }
    }
}

// ------------------------------------------------------------------ trend/seasonal init
__global__ void trendbase_kernel(const float* __restrict__ dpw, const float* __restrict__ dpb) {
    int idx = blockIdx.x * blockDim.x + threadIdx.x;
    if (idx >= BZ * LZ) return;
    int t = idx & 1023, b = idx >> 10;
    float s = dpb[0];
#pragma unroll
    for (int c = 0; c < C7; c++) {
        float v = (t < 512) ? g_trend0[((size_t)(b * LZ + 512 + t)) * C7 + c]
                            : g_mean7[b * C7 + c];
        s += v * dpw[c];
    }
    g_trendbase[idx] = s;
}

__global__ void seasinit_kernel() {
    int idx = blockIdx.x * blockDim.x + threadIdx.x;
    if (idx >= BZ * LZ * C7) return;
    int c = idx % C7;
    int t = (idx / C7) & 1023;
    int b = idx / (C7 * LZ);
    g_seasinit[idx] = (t < 512) ? g_seas0[((size_t)(b * LZ + 512 + t)) * C7 + c] : 0.f;
}

// ------------------------------------------------------------------ embedding
__global__ void embed_kernel(const float* __restrict__ in, const float* __restrict__ w,
                             float* __restrict__ out) {
    int idx = blockIdx.x * blockDim.x + threadIdx.x;
    if (idx >= BZ * LZ * DZ) return;
    int o = idx & 63;
    int t = (idx >> 6) & 1023;
    int b = idx >> 16;
    float s = 0.f;
#pragma unroll
    for (int j = 0; j < 3; j++) {
        int ts = (t + j - 1 + LZ) & (LZ - 1);
        const float* ip = in + ((size_t)(b * LZ + ts)) * C7;
#pragma unroll
        for (int c = 0; c < C7; c++) s += ip[c] * w[(o * C7 + c) * 3 + j];
    }
    out[idx] = s + g_pe[(t << 6) + o];
}

// ------------------------------------------------------------------ tf32 helpers
__device__ __forceinline__ uint32_t to_tf32(float x) {
    uint32_t r;
    asm("cvt.rna.tf32.f32 %0, %1;" : "=r"(r) : "f"(x));
    return r;
}
__device__ __forceinline__ void cpa16(uint32_t s, const float* g) {
    asm volatile("cp.async.ca.shared.global [%0], [%1], 16;" :: "r"(s), "l"(g));
}
__device__ __forceinline__ void cpa_commit() {
    asm volatile("cp.async.commit_group;");
}
__device__ __forceinline__ void cpa_wait1() {
    asm volatile("cp.async.wait_group 1;");
}
__device__ __forceinline__ void mma_tf32(float* acc, const uint32_t* a, const uint32_t* bf) {
    asm volatile(
        "mma.sync.aligned.m16n8k8.row.col.f32.tf32.tf32.f32 "
        "{%0,%1,%2,%3}, {%4,%5,%6,%7}, {%8,%9}, {%0,%1,%2,%3};"
        : "+f"(acc[0]), "+f"(acc[1]), "+f"(acc[2]), "+f"(acc[3])
        : "r"(a[0]), "r"(a[1]), "r"(a[2]), "r"(a[3]), "r"(bf[0]), "r"(bf[1]));
}

// ------------------------------------------------------------------ tf32 GEMM
#define GT_ASTRIDE (128*36)
#define GT_BSTRIDE (64*36)
#define GT_SMEM ((2*GT_ASTRIDE + 2*GT_BSTRIDE) * 4)

template <int ACT>
__global__ __launch_bounds__(128) void gemm_tc(const float* __restrict__ A,
                                               const float* __restrict__ W,
                                               const float* __restrict__ bias,
                                               float* __restrict__ C,
                                               int N, int K, int O) {
    extern __shared__ float dsm[];
    float* As = dsm;
    float* Bs = dsm + 2 * GT_ASTRIDE;
    const int rb = blockIdx.x * 128;
    const int cb = blockIdx.y * 64;
    const int tid = threadIdx.x;
    const int lane = tid & 31;
    const int w = tid >> 5;
    const int wm = w & 1, wn = w >> 1;
    const int m0 = wm * 64, n0 = wn * 32;
    const int g = lane >> 2, tg = lane & 3;
    const int lrow = tid >> 3;
    const int lcol = (tid & 7) * 4;

    uint32_t sA = (uint32_t)__cvta_generic_to_shared(As);
    uint32_t sB = (uint32_t)__cvta_generic_to_shared(Bs);

    float acc[4][4][4];
#pragma unroll
    for (int mi = 0; mi < 4; mi++)
#pragma unroll
        for (int ni = 0; ni < 4; ni++)
#pragma unroll
            for (int r = 0; r < 4; r++) acc[mi][ni][r] = 0.f;

#pragma unroll
    for (int r = 0; r < 8; r++) {
        int row = lrow + r * 16;
        cpa16(sA + (uint32_t)((row * 36 + lcol) * 4), A + (size_t)(rb + row) * K + lcol);
    }
#pragma unroll
    for (int r = 0; r < 4; r++) {
        int row = lrow + r * 16;
        cpa16(sB + (uint32_t)((row * 36 + lcol) * 4), W + (size_t)(cb + row) * K + lcol);
    }
    cpa_commit();

    int st = 0;
    for (int k0 = 0; k0 < K; k0 += 32, st ^= 1) {
        if (k0 + 32 < K) {
            int nx = st ^ 1;
#pragma unroll
            for (int r = 0; r < 8; r++) {
                int row = lrow + r * 16;
                cpa16(sA + (uint32_t)((nx * GT_ASTRIDE + row * 36 + lcol) * 4),
                      A + (size_t)(rb + row) * K + k0 + 32 + lcol);
            }
#pragma unroll
            for (int r = 0; r < 4; r++) {
                int row = lrow + r * 16;
                cpa16(sB + (uint32_t)((nx * GT_BSTRIDE + row * 36 + lcol) * 4),
                      W + (size_t)(cb + row) * K + k0 + 32 + lcol);
            }
        }
        cpa_commit();
        cpa_wait1();
        __syncthreads();
        const float* Ast = As + st * GT_ASTRIDE;
        const float* Bst = Bs + st * GT_BSTRIDE;
#pragma unroll
        for (int kk = 0; kk < 32; kk += 8) {
            uint32_t a[4][4], bfr[4][2];
#pragma unroll
            for (int mi = 0; mi < 4; mi++) {
                int r = m0 + mi * 16 + g;
                a[mi][0] = to_tf32(Ast[r * 36 + kk + tg]);
                a[mi][1] = to_tf32(Ast[(r + 8) * 36 + kk + tg]);
                a[mi][2] = to_tf32(Ast[r * 36 + kk + tg + 4]);
                a[mi][3] = to_tf32(Ast[(r + 8) * 36 + kk + tg + 4]);
            }
#pragma unroll
            for (int ni = 0; ni < 4; ni++) {
                int c = n0 + ni * 8 + g;
                bfr[ni][0] = to_tf32(Bst[c * 36 + kk + tg]);
                bfr[ni][1] = to_tf32(Bst[c * 36 + kk + tg + 4]);
            }
#pragma unroll
            for (int mi = 0; mi < 4; mi++)
#pragma unroll
                for (int ni = 0; ni < 4; ni++)
                    mma_tf32(acc[mi][ni], a[mi], bfr[ni]);
        }
        __syncthreads();
    }
#pragma unroll
    for (int mi = 0; mi < 4; mi++) {
        int row0 = rb + m0 + mi * 16 + g;
#pragma unroll
        for (int ni = 0; ni < 4; ni++) {
            int col = cb + n0 + ni * 8 + 2 * tg;
#pragma unroll
            for (int half = 0; half < 2; half++) {
                int row = row0 + half * 8;
                float v0 = acc[mi][ni][half * 2 + 0];
                float v1 = acc[mi][ni][half * 2 + 1];
                if (bias) { v0 += bias[col]; v1 += bias[col + 1]; }
                if (ACT == 1) {
                    v0 = 0.5f * v0 * (1.f + erff(v0 * 0.70710678118654752f));
                    v1 = 0.5f * v1 * (1.f + erff(v1 * 0.70710678118654752f));
                }
                C[(size_t)row * O + col] = v0;
                C[(size_t)row * O + col + 1] = v1;
            }
        }
    }
}

// ------------------------------------------------------------------ fused FFN: C = gelu(A@W1^T)@W2^T
// A [N,64], W1 [256,64], W2 [64,256], C [N,64]. Block: 128 rows, 128 threads.
#define FFN_AS  (128*68)
#define FFN_WS  (64*68)
#define FFN_PS  (128*68)
#define FFN_SMEM ((FFN_AS + 2*FFN_WS + FFN_PS) * 4)

__global__ __launch_bounds__(128) void gemm_ffn(const float* __restrict__ A,
                                                const float* __restrict__ W1,
                                                const float* __restrict__ W2,
                                                float* __restrict__ C) {
    extern __shared__ float sm[];
    float* As  = sm;                        // [128][68]
    float* Ws1 = sm + FFN_AS;               // [64][68]
    float* Ws2 = sm + FFN_AS + FFN_WS;      // [64][68]
    float* Ps  = sm + FFN_AS + 2 * FFN_WS;  // [128][68]
    const int rb = blockIdx.x * 128;
    const int tid = threadIdx.x;
    const int lane = tid & 31;
    const int w = tid >> 5;
    const int wm = w & 1, wn = w >> 1;
    const int m0 = wm * 64, n0 = wn * 32;
    const int g = lane >> 2, tg = lane & 3;

    // load A tile 128x64
    for (int i = tid; i < 128 * 16; i += 128) {
        int row = i >> 4;
        int c4 = (i & 15) * 4;
        *reinterpret_cast<float4*>(&As[row * 68 + c4]) =
            *reinterpret_cast<const float4*>(A + (size_t)(rb + row) * 64 + c4);
    }

    float acc[4][4][4];
#pragma unroll
    for (int mi = 0; mi < 4; mi++)
#pragma unroll
        for (int ni = 0; ni < 4; ni++)
#pragma unroll
            for (int r = 0; r < 4; r++) acc[mi][ni][r] = 0.f;

    for (int ch = 0; ch < 4; ch++) {
        __syncthreads();   // Ws/Ps reuse safe
        // W1 chunk rows [ch*64, ch*64+64), W2 chunk cols [ch*64, ch*64+64)
        for (int i = tid; i < 64 * 16; i += 128) {
            int row = i >> 4;
            int c4 = (i & 15) * 4;
            *reinterpret_cast<float4*>(&Ws1[row * 68 + c4]) =
                *reinterpret_cast<const float4*>(W1 + (size_t)(ch * 64 + row) * 64 + c4);
            *reinterpret_cast<float4*>(&Ws2[row * 68 + c4]) =
                *reinterpret_cast<const float4*>(W2 + (size_t)row * 256 + ch * 64 + c4);
        }
        __syncthreads();
        // mma1: P = A @ W1c^T
        float p1[4][4][4];
#pragma unroll
        for (int mi = 0; mi < 4; mi++)
#pragma unroll
            for (int ni = 0; ni < 4; ni++)
#pragma unroll
                for (int r = 0; r < 4; r++) p1[mi][ni][r] = 0.f;
#pragma unroll
        for (int kk = 0; kk < 64; kk += 8) {
            uint32_t a[4][4], bfr[4][2];
#pragma unroll
            for (int mi = 0; mi < 4; mi++) {
                int r = m0 + mi * 16 + g;
                a[mi][0] = to_tf32(As[r * 68 + kk + tg]);
                a[mi][1] = to_tf32(As[(r + 8) * 68 + kk + tg]);
                a[mi][2] = to_tf32(As[r * 68 + kk + tg + 4]);
                a[mi][3] = to_tf32(As[(r + 8) * 68 + kk + tg + 4]);
            }
#pragma unroll
            for (int ni = 0; ni < 4; ni++) {
                int c = n0 + ni * 8 + g;
                bfr[ni][0] = to_tf32(Ws1[c * 68 + kk + tg]);
                bfr[ni][1] = to_tf32(Ws1[c * 68 + kk + tg + 4]);
            }
#pragma unroll
            for (int mi = 0; mi < 4; mi++)
#pragma unroll
                for (int ni = 0; ni < 4; ni++)
                    mma_tf32(p1[mi][ni], a[mi], bfr[ni]);
        }
        // gelu -> Ps
#pragma unroll
        for (int mi = 0; mi < 4; mi++) {
            int row0 = m0 + mi * 16 + g;
#pragma unroll
            for (int ni = 0; ni < 4; ni++) {
                int col = n0 + ni * 8 + 2 * tg;
#pragma unroll
                for (int half = 0; half < 2; half++) {
                    int row = row0 + half * 8;
                    float v0 = p1[mi][ni][half * 2 + 0];
                    float v1 = p1[mi][ni][half * 2 + 1];
                    v0 = 0.5f * v0 * (1.f + erff(v0 * 0.70710678118654752f));
                    v1 = 0.5f * v1 * (1.f + erff(v1 * 0.70710678118654752f));
                    Ps[row * 68 + col] = v0;
                    Ps[row * 68 + col + 1] = v1;
                }
            }
        }
        __syncthreads();
        // mma2: acc += P @ W2c^T
#pragma unroll
        for (int kk = 0; kk < 64; kk += 8) {
            uint32_t a[4][4], bfr[4][2];
#pragma unroll
            for (int mi = 0; mi < 4; mi++) {
                int r = m0 + mi * 16 + g;
                a[mi][0] = to_tf32(Ps[r * 68 + kk + tg]);
                a[mi][1] = to_tf32(Ps[(r + 8) * 68 + kk + tg]);
                a[mi][2] = to_tf32(Ps[r * 68 + kk + tg + 4]);
                a[mi][3] = to_tf32(Ps[(r + 8) * 68 + kk + tg + 4]);
            }
#pragma unroll
            for (int ni = 0; ni < 4; ni++) {
                int c = n0 + ni * 8 + g;
                bfr[ni][0] = to_tf32(Ws2[c * 68 + kk + tg]);
                bfr[ni][1] = to_tf32(Ws2[c * 68 + kk + tg + 4]);
            }
#pragma unroll
            for (int mi = 0; mi < 4; mi++)
#pragma unroll
                for (int ni = 0; ni < 4; ni++)
                    mma_tf32(acc[mi][ni], a[mi], bfr[ni]);
        }
    }
#pragma unroll
    for (int mi = 0; mi < 4; mi++) {
        int row0 = rb + m0 + mi * 16 + g;
#pragma unroll
        for (int ni = 0; ni < 4; ni++) {
            int col = n0 + ni * 8 + 2 * tg;
#pragma unroll
            for (int half = 0; half < 2; half++) {
                int row = row0 + half * 8;
                C[(size_t)row * 64 + col] = acc[mi][ni][half * 2 + 0];
                C[(size_t)row * 64 + col + 1] = acc[mi][ni][half * 2 + 1];
            }
        }
    }
}

// ------------------------------------------------------------------ DFT GEMM with fused transpose
__device__ __forceinline__ void dft_body(const float* __restrict__ Aq,
                                         const float* __restrict__ F,
                                         float* __restrict__ X,
                                         int b, int cb, int zz) {
    __shared__ float As[64][33];
    __shared__ float Bs[64][36];
    const int tbase = zz * 256;
    const int tid = threadIdx.x;
    const int lane = tid & 31;
    const int w = tid >> 5;
    const int wm = w & 1, wn = w >> 1;
    const int m0 = wm * 32, n0 = wn * 32;
    const int g = lane >> 2, tg = lane & 3;
    const int lrow = tid >> 3;
    const int lcol = (tid & 7) * 4;

    float acc[2][4][4];
#pragma unroll
    for (int mi = 0; mi < 2; mi++)
#pragma unroll
        for (int ni = 0; ni < 4; ni++)
#pragma unroll
            for (int r = 0; r < 4; r++) acc[mi][ni][r] = 0.f;

    for (int t0 = tbase; t0 < tbase + 256; t0 += 32) {
#pragma unroll
        for (int i = 0; i < 4; i++) {
            int f4 = i * 128 + tid;
            int tl = f4 >> 4;
            int he = (f4 & 15) * 4;
            float4 v = *reinterpret_cast<const float4*>(
                Aq + ((size_t)(b * LZ + t0 + tl)) * DZ + he);
            As[he + 0][tl] = v.x;
            As[he + 1][tl] = v.y;
            As[he + 2][tl] = v.z;
            As[he + 3][tl] = v.w;
        }
#pragma unroll
        for (int r = 0; r < 4; r++) {
            int row = lrow + r * 16;
            *reinterpret_cast<float4*>(&Bs[row][lcol]) =
                *reinterpret_cast<const float4*>(F + (size_t)(cb + row) * LZ + t0 + lcol);
        }
        __syncthreads();
#pragma unroll
        for (int kk = 0; kk < 32; kk += 8) {
            uint32_t a[2][4], bfr[4][2];
#pragma unroll
            for (int mi = 0; mi < 2; mi++) {
                int r = m0 + mi * 16 + g;
                a[mi][0] = to_tf32(As[r][kk + tg]);
                a[mi][1] = to_tf32(As[r + 8][kk + tg]);
                a[mi][2] = to_tf32(As[r][kk + tg + 4]);
                a[mi][3] = to_tf32(As[r + 8][kk + tg + 4]);
            }
#pragma unroll
            for (int ni = 0; ni < 4; ni++) {
                int c = n0 + ni * 8 + g;
                bfr[ni][0] = to_tf32(Bs[c][kk + tg]);
                bfr[ni][1] = to_tf32(Bs[c][kk + tg + 4]);
            }
#pragma unroll
            for (int mi = 0; mi < 2; mi++)
#pragma unroll
                for (int ni = 0; ni < 4; ni++)
                    mma_tf32(acc[mi][ni], a[mi], bfr[ni]);
        }
        __syncthreads();
    }
#pragma unroll
    for (int mi = 0; mi < 2; mi++) {
        int r0 = m0 + mi * 16 + g;
#pragma unroll
        for (int ni = 0; ni < 4; ni++) {
            int col = cb + n0 + ni * 8 + 2 * tg;
#pragma unroll
            for (int half = 0; half < 2; half++) {
                int row = r0 + half * 8;
                atomicAdd(&X[(size_t)(b * 64 + row) * M2 + col], acc[mi][ni][half * 2 + 0]);
                atomicAdd(&X[(size_t)(b * 64 + row) * M2 + col + 1], acc[mi][ni][half * 2 + 1]);
            }
        }
    }
}

__global__ __launch_bounds__(128) void gemm_dft(const float* __restrict__ Aq,
                                                const float* __restrict__ F,
                                                float* __restrict__ X) {
    dft_body(Aq, F, X, blockIdx.x, blockIdx.y * 64, blockIdx.z);
}

__global__ __launch_bounds__(128) void gemm_dft2(const float* __restrict__ Aq1,
                                                 float* __restrict__ X1,
                                                 const float* __restrict__ Aq2,
                                                 float* __restrict__ X2,
                                                 const float* __restrict__ F) {
    int z = blockIdx.z;
    if (z < 4) dft_body(Aq1, F, X1, blockIdx.x, blockIdx.y * 64, z);
    else       dft_body(Aq2, F, X2, blockIdx.x, blockIdx.y * 64, z - 4);
}

// ------------------------------------------------------------------ mode-space projection (cross path)
__global__ __launch_bounds__(256) void modeproj_kernel(const float* __restrict__ Hf,
                                                       const float* __restrict__ Wq,
                                                       const float* __restrict__ bq,
                                                       const float* __restrict__ cm,
                                                       float* __restrict__ Qf) {
    __shared__ float Hs[64][68];
    __shared__ float Ws[64][68];
    int b = blockIdx.x;
    int mh = blockIdx.y;
    int tid = threadIdx.x;
    for (int i = tid; i < 64 * 16; i += 256) {
        int d = i >> 4;
        int c4 = (i & 15) * 4;
        *reinterpret_cast<float4*>(&Hs[d][c4]) =
            *reinterpret_cast<const float4*>(Hf + ((size_t)(b * 64 + d)) * M2 + mh * 64 + c4);
    }
    for (int i = tid; i < 64 * 16; i += 256) {
        int he = i >> 4;
        int c4 = (i & 15) * 4;
        *reinterpret_cast<float4*>(&Ws[he][c4]) =
            *reinterpret_cast<const float4*>(Wq + he * 64 + c4);
    }
    __syncthreads();
    if (cm && mh == 0 && tid < 64) Hs[tid][0] -= cm[b * 64 + tid] * 1024.f;
    __syncthreads();
    int he = tid >> 2;
    int mg = tid & 3;
#pragma unroll
    for (int j = 0; j < 16; j++) {
        int ml = mg + 4 * j;
        float s = 0.f;
#pragma unroll
        for (int d = 0; d < 64; d++) s += Ws[he][d] * Hs[d][ml];
        int m2 = mh * 64 + ml;
        if (m2 == 0) s += bq[he] * 1024.f;
        Qf[((size_t)(b * 64 + he)) * M2 + m2] = s;
    }
}

// ------------------------------------------------------------------ fused modeproj + mode_mix (self-attn)
#define MPM_SMEM ((2*64*68 + 64*66) * 4)
__global__ __launch_bounds__(256) void modeproj_mix_kernel(const float* __restrict__ Hf,
                                                           const float* __restrict__ Wq,
                                                           const float* __restrict__ bq,
                                                           const float* __restrict__ wr,
                                                           const float* __restrict__ wi,
                                                           float* __restrict__ sel,
                                                           float scale) {
    extern __shared__ float sm[];
    float* Hs = sm;
    float* Ws = sm + 64 * 68;
    float* Qs = sm + 2 * 64 * 68;
    int b = blockIdx.x;
    int mh = blockIdx.y;
    int tid = threadIdx.x;
    for (int i = tid; i < 64 * 16; i += 256) {
        int d = i >> 4;
        int c4 = (i & 15) * 4;
        *reinterpret_cast<float4*>(&Hs[d * 68 + c4]) =
            *reinterpret_cast<const float4*>(Hf + ((size_t)(b * 64 + d)) * M2 + mh * 64 + c4);
    }
    for (int i = tid; i < 64 * 16; i += 256) {
        int he = i >> 4;
        int c4 = (i & 15) * 4;
        *reinterpret_cast<float4*>(&Ws[he * 68 + c4]) =
            *reinterpret_cast<const float4*>(Wq + he * 64 + c4);
    }
    __syncthreads();
    {
        int he = tid >> 2;
        int mg = tid & 3;
#pragma unroll
        for (int j = 0; j < 16; j++) {
            int ml = mg + 4 * j;
            float s = 0.f;
#pragma unroll
            for (int d = 0; d < 64; d++) s += Ws[he * 68 + d] * Hs[d * 68 + ml];
            if (mh == 0 && ml == 0) s += bq[he] * 1024.f;
            Qs[he * 66 + ml] = s;
        }
    }
    __syncthreads();
    {
        int lm = tid & 31;
        int hob = tid >> 5;
        int m = mh * 32 + lm;
#pragma unroll
        for (int j = 0; j < 8; j++) {
            int ho = hob * 8 + j;
            int h = ho >> 3, o = ho & 7;
            float ar = 0.f, ai = 0.f;
#pragma unroll
            for (int e = 0; e < 8; e++) {
                float xr = Qs[(h * 8 + e) * 66 + 2 * lm];
                float xi = Qs[(h * 8 + e) * 66 + 2 * lm + 1];
                int wix = ((h * 8 + e) * 8 + o) * MZ + m;
                float wrv = wr[wix], wiv = wi[wix];
                ar += xr * wrv - xi * wiv;
                ai += xr * wiv + xi * wrv;
            }
            size_t ro = ((size_t)(b * 64 + h * 8 + o)) * M2 + 2 * m;
            sel[ro] = ar * scale;
            sel[ro + 1] = ai * scale;
        }
    }
}

// ------------------------------------------------------------------ fused cross attention
__global__ __launch_bounds__(256) void qkattn_kernel(const float* __restrict__ Qf,
                                                     const float* __restrict__ Kf,
                                                     const float* __restrict__ wr,
                                                     const float* __restrict__ wi,
                                                     float* __restrict__ sel,
                                                     float scale) {
    __shared__ float Qs[8][128];
    __shared__ float Ks[8][128];
    __shared__ float qks[64][130];
    __shared__ float Vs[8][128];
    int bh = blockIdx.x;
    int h = bh & 7, b = bh >> 3;
    int tid = threadIdx.x;
    size_t tbase = (size_t)(b * 64 + h * 8) * M2;
#pragma unroll
    for (int i = 0; i < 4; i++) {
        int f = i * 256 + tid;
        int e = f >> 7, c = f & 127;
        Qs[e][c] = Qf[tbase + e * M2 + c];
        Ks[e][c] = Kf[tbase + e * M2 + c];
    }
    __syncthreads();
    {
        int x = tid >> 2;
        int ys = tid & 3;
#pragma unroll
        for (int j = 0; j < 16; j++) {
            int y = ys * 16 + j;
            float ar = 0.f, ai = 0.f;
#pragma unroll
            for (int e = 0; e < 8; e++) {
                float qr = Qs[e][2 * x], qi = Qs[e][2 * x + 1];
                float kr = Ks[e][2 * y], ki = Ks[e][2 * y + 1];
                ar += qr * kr - qi * ki;
                ai += qr * ki + qi * kr;
            }
            float a2 = 2.f * ar, b2 = 2.f * ai;
            float tr, ti;
            if (fabsf(a2) > 30.f) {
                tr = copysignf(1.f, ar);
                ti = 0.f;
            } else {
                float sn, cs;
                sincosf(b2, &sn, &cs);
                float ex = expf(a2);
                float exi = 1.f / ex;
                float den = 0.5f * (ex + exi) + cs;
                tr = 0.5f * (ex - exi) / den;
                ti = sn / den;
            }
            qks[x][2 * y] = tr;
            qks[x][2 * y + 1] = ti;
        }
    }
    __syncthreads();
    {
        int flat0 = tid * 2;
#pragma unroll
        for (int u = 0; u < 2; u++) {
            int flat = flat0 + u;
            int e = flat >> 6, x = flat & 63;
            float ar = 0.f, ai = 0.f;
#pragma unroll 16
            for (int y = 0; y < 64; y++) {
                float qr = qks[x][2 * y], qi = qks[x][2 * y + 1];
                float kr = Ks[e][2 * y], ki = Ks[e][2 * y + 1];
                ar += qr * kr - qi * ki;
                ai += qr * ki + qi * kr;
            }
            Vs[e][2 * x] = ar;
            Vs[e][2 * x + 1] = ai;
        }
    }
    __syncthreads();
    {
        int m = tid & 63;
        int og = tid >> 6;
#pragma unroll
        for (int j = 0; j < 2; j++) {
            int o = og * 2 + j;
            float ar = 0.f, ai = 0.f;
#pragma unroll
            for (int e = 0; e < 8; e++) {
                float xr = Vs[e][2 * m], xi = Vs[e][2 * m + 1];
                int wix = ((h * 8 + e) * 8 + o) * MZ + m;
                float wrv = wr[wix], wiv = wi[wix];
                ar += xr * wrv - xi * wiv;
                ai += xr * wiv + xi * wrv;
            }
            size_t ro = ((size_t)(b * 64 + h * 8 + o)) * M2 + 2 * m;
            sel[ro] = ar * scale;
            sel[ro + 1] = ai * scale;
        }
    }
}

// ------------------------------------------------------------------ layernorm family
__global__ void ln_row_kernel(const float* __restrict__ X, const float* __restrict__ g,
                              const float* __restrict__ be, float* __restrict__ out) {
    __shared__ float red[256];
    int tid = threadIdx.x;
    int sub = tid >> 6;
    int d = tid & 63;
    int row = blockIdx.x * 4 + sub;
    float v = X[(size_t)row * DZ + d];
    red[tid] = v;
    __syncthreads();
    for (int s = 32; s > 0; s >>= 1) {
        if (d < s) red[tid] += red[tid + s];
        __syncthreads();
    }
    float mu = red[sub * 64] * (1.f / 64.f);
    __syncthreads();
    float dv = v - mu;
    red[tid] = dv * dv;
    __syncthreads();
    for (int s = 32; s > 0; s >>= 1) {
        if (d < s) red[tid] += red[tid + s];
        __syncthreads();
    }
    float var = red[sub * 64] * (1.f / 64.f);
    out[(size_t)row * DZ + d] = dv * rsqrtf(var + 1e-5f) * g[d] + be[d];
}

__global__ void colmean_kernel(const float* __restrict__ X, float* __restrict__ cm) {
    __shared__ float r[256];
    int b = blockIdx.x / DZ, d = blockIdx.x % DZ;
    float s = 0.f;
    for (int t = threadIdx.x; t < LZ; t += 256) s += X[((size_t)(b * LZ + t)) * DZ + d];
    r[threadIdx.x] = s;
    __syncthreads();
    for (int o = 128; o > 0; o >>= 1) {
        if (threadIdx.x < o) r[threadIdx.x] += r[threadIdx.x + o];
        __syncthreads();
    }
    if (threadIdx.x == 0) cm[b * DZ + d] = r[0] * (1.f / LZ);
}

// ------------------------------------------------------------------ final epilogue
__global__ void final_kernel(const float* __restrict__ xln, const float* __restrict__ cm,
                             const float* __restrict__ tacc,
                             const float* __restrict__ tbase, const float* __restrict__ tw,
                             const float* __restrict__ pw, const float* __restrict__ pb,
                             float* __restrict__ out) {
    int idx = blockIdx.x * blockDim.x + threadIdx.x;
    if (idx >= BZ * 512) return;
    int t = idx & 511, b = idx >> 9;
    int tt = t + 512;
    float cv = 0.f;
#pragma unroll
    for (int j = 0; j < 3; j++) {
        int ts = (tt + j - 1) & (LZ - 1);
        const float* row = tacc + ((size_t)(b * LZ + ts)) * DZ;
#pragma unroll 4
        for (int d4 = 0; d4 < 16; d4++) {
            float4 rv = *reinterpret_cast<const float4*>(row + d4 * 4);
            cv += rv.x * tw[(d4 * 4 + 0) * 3 + j] + rv.y * tw[(d4 * 4 + 1) * 3 + j]
                + rv.z * tw[(d4 * 4 + 2) * 3 + j] + rv.w * tw[(d4 * 4 + 3) * 3 + j];
        }
    }
    float p = pb[0];
    const float* xr = xln + ((size_t)(b * LZ + tt)) * DZ;
    const float* cmr = cm + b * DZ;
#pragma unroll 4
    for (int d4 = 0; d4 < 16; d4++) {
        float4 xv = *reinterpret_cast<const float4*>(xr + d4 * 4);
        float4 cvv = *reinterpret_cast<const float4*>(cmr + d4 * 4);
        float4 pv = *reinterpret_cast<const float4*>(pw + d4 * 4);
        p += (xv.x - cvv.x) * pv.x + (xv.y - cvv.y) * pv.y
           + (xv.z - cvv.z) * pv.z + (xv.w - cvv.w) * pv.w;
    }
    out[idx] = p + cv + tbase[b * LZ + tt];
}

static float* symaddr_f(const void* sym) {
    void* p = nullptr;
    cudaGetSymbolAddress(&p, sym);
    return (float*)p;
}

extern "C" void kernel_launch(void* const* d_in, const int* in_sizes, int n_in,
                              void* d_out, int out_size) {
    const float* x_enc       = (const float*)d_in[0];
    const float* dp_w        = (const float*)d_in[1];
    const float* dp_b        = (const float*)d_in[2];
    const float* emb_enc_w   = (const float*)d_in[3];
    const float* emb_dec_w   = (const float*)d_in[4];
    const float* decomp_w    = (const float*)d_in[5];
    const float* decomp_b    = (const float*)d_in[6];
    const float* enc_attn_w  = (const float*)d_in[7];
    const float* enc_attn_b  = (const float*)d_in[8];
    const float* enc_four_wr = (const float*)d_in[9];
    const float* enc_four_wi = (const float*)d_in[10];
    const float* enc_c1      = (const float*)d_in[11];
    const float* enc_c2      = (const float*)d_in[12];
    const float* enc_ln_g    = (const float*)d_in[13];
    const float* enc_ln_b    = (const float*)d_in[14];
    const float* dec_self_w  = (const float*)d_in[15];
    const float* dec_self_b  = (const float*)d_in[16];
    const float* dec_four_wr = (const float*)d_in[17];
    const float* dec_four_wi = (const float*)d_in[18];
    const float* dec_cross_w = (const float*)d_in[19];
    const float* dec_cross_b = (const float*)d_in[20];
    const float* dec_cross_wr= (const float*)d_in[21];
    const float* dec_cross_wi= (const float*)d_in[22];
    const float* dec_c1      = (const float*)d_in[23];
    const float* dec_c2      = (const float*)d_in[24];
    const float* dec_trend_w = (const float*)d_in[25];
    const float* dec_ln_g    = (const float*)d_in[26];
    const float* dec_ln_b    = (const float*)d_in[27];
    const float* dec_proj_w  = (const float*)d_in[28];
    const float* dec_proj_b  = (const float*)d_in[29];
    float* out = (float*)d_out;

    float* px        = symaddr_f(g_x);
    float* pseas0    = symaddr_f(g_seas0);
    float* ptrend0   = symaddr_f(g_trend0);
    float* pseasinit = symaddr_f(g_seasinit);
    float* ph        = symaddr_f(g_h);
    float* py        = symaddr_f(g_y);
    float* pa        = symaddr_f(g_a);
    float* py2       = symaddr_f(g_y2);
    float* pa2       = symaddr_f(g_a2);
    float* pHf       = symaddr_f(g_Hf);
    float* pHf2      = pHf + (size_t)NHE * M2;
    float* pXf       = symaddr_f(g_Xf);
    float* pXk       = symaddr_f(g_Xk);
    float* psel      = symaddr_f(g_sel);
    float* psel2     = symaddr_f(g_sel2);
    float* pxd       = symaddr_f(g_xd);
    float* ptacc     = symaddr_f(g_tacc);
    float* pcm       = symaddr_f(g_cm);
    float* pcm2      = symaddr_f(g_cm2);
    float* pln       = symaddr_f(g_ln);
    float* pF        = symaddr_f(g_F);
    float* pFi       = symaddr_f(g_Fi);
    float* ptbase    = symaddr_f(g_trendbase);

    cudaFuncSetAttribute(gemm_tc<0>, cudaFuncAttributeMaxDynamicSharedMemorySize, GT_SMEM);
    cudaFuncSetAttribute(gemm_ffn, cudaFuncAttributeMaxDynamicSharedMemorySize, FFN_SMEM);
    cudaFuncSetAttribute(modeproj_mix_kernel, cudaFuncAttributeMaxDynamicSharedMemorySize, MPM_SMEM);

    static cudaStream_t s2 = nullptr;
    static cudaEvent_t evFork = nullptr, evJoin = nullptr;
    if (!s2) {
        cudaStreamCreateWithFlags(&s2, cudaStreamNonBlocking);
        cudaEventCreateWithFlags(&evFork, cudaEventDisableTiming);
        cudaEventCreateWithFlags(&evJoin, cudaEventDisableTiming);
    }

    dim3 dftg(BZ, 2, 4);
    dim3 dftg2(BZ, 2, 8);
    dim3 mpg(BZ, 2);

    // ---- shared prep (stream 0) ----
    build_tables_kernel<<<512, 256>>>();
    transpose_in_kernel<<<1792, 256>>>(x_enc);
    colmean7_kernel<<<BZ * C7, 256>>>(x_enc);
    decomp7_kernel<<<BZ * C7, LZ>>>(px, decomp_w + 0, decomp_b + 0, pseas0, ptrend0);
    trendbase_kernel<<<256, 256>>>(dp_w, dp_b);
    seasinit_kernel<<<1792, 256>>>();
    cudaEventRecord(evFork, 0);

    // ---- decoder prefix (stream s2) ----
    cudaStreamWaitEvent(s2, evFork, 0);
    embed_kernel<<<16384, 256, 0, s2>>>(pseasinit, emb_dec_w, pxd);
    cudaMemsetAsync(pHf2, 0, (size_t)NHE * M2 * sizeof(float), s2);
    gemm_dft<<<dftg, 128, 0, s2>>>(pxd, pF, pHf2);
    modeproj_mix_kernel<<<mpg, 256, MPM_SMEM, s2>>>(pHf2, dec_self_w + 0, dec_self_b + 0,
                                                    dec_four_wr, dec_four_wi, psel2, 1.0f);
    gemm_tc<0><<<dim3(32, 16), 128, GT_SMEM, s2>>>(psel2, pFi, nullptr, py2, NHE, 128, 1024);
    gemm_tc<0><<<dim3(512, 1), 128, GT_SMEM, s2>>>(py2, dec_self_w + 3 * 4096,
                                                   dec_self_b + 3 * 64, pa2, NROW, 64, 64);
    decomp64_kernel<<<1024, 256, 0, s2>>>(pxd, pa2, decomp_w + 5 * 4, decomp_b + 5 * 4,
                                          pxd, ptacc, 0);
    cudaEventRecord(evJoin, s2);

    // ---- encoder (stream 0) ----
    embed_kernel<<<16384, 256>>>(px, emb_enc_w, ph);
    for (int l = 0; l < 2; l++) {
        const float* wq = enc_attn_w + (size_t)(l * 4 + 0) * 4096;
        const float* bq = enc_attn_b + (size_t)(l * 4 + 0) * 64;
        const float* wo = enc_attn_w + (size_t)(l * 4 + 3) * 4096;
        const float* bo = enc_attn_b + (size_t)(l * 4 + 3) * 64;
        cudaMemsetAsync(pHf, 0, (size_t)NHE * M2 * sizeof(float));
        gemm_dft<<<dftg, 128>>>(ph, pF, pHf);
        modeproj_mix_kernel<<<mpg, 256, MPM_SMEM>>>(pHf, wq, bq,
                                                    enc_four_wr + (size_t)l * 32768,
                                                    enc_four_wi + (size_t)l * 32768, psel, 1.0f);
        gemm_tc<0><<<dim3(32, 16), 128, GT_SMEM>>>(psel, pFi, nullptr, py, NHE, 128, 1024);
        gemm_tc<0><<<dim3(512, 1), 128, GT_SMEM>>>(py, wo, bo, pa, NROW, 64, 64);
        decomp64_kernel<<<1024, 256>>>(ph, pa, decomp_w + (1 + 2 * l) * 4,
                                       decomp_b + (1 + 2 * l) * 4, ph, nullptr, 0);
        gemm_ffn<<<512, 128, FFN_SMEM>>>(ph, enc_c1 + (size_t)l * 16384,
                                         enc_c2 + (size_t)l * 16384, py);
        decomp64_kernel<<<1024, 256>>>(ph, py, decomp_w + (2 + 2 * l) * 4,
                                       decomp_b + (2 + 2 * l) * 4, ph, nullptr, 0);
    }
    ln_row_kernel<<<16384, 256>>>(ph, enc_ln_g, enc_ln_b, ph);
    colmean_kernel<<<BZ * DZ, 256>>>(ph, pcm2);

    // ---- join, then cross attention ----
    cudaStreamWaitEvent(0, evJoin, 0);
    cudaMemsetAsync(pHf, 0, (size_t)2 * NHE * M2 * sizeof(float));
    gemm_dft2<<<dftg2, 128>>>(pxd, pHf, ph, pHf2, pF);
    modeproj_kernel<<<mpg, 256>>>(pHf, dec_cross_w + 0, dec_cross_b + 0, nullptr, pXf);
    modeproj_kernel<<<mpg, 256>>>(pHf2, dec_cross_w + 1 * 4096, dec_cross_b + 1 * 64, pcm2, pXk);
    qkattn_kernel<<<512, 256>>>(pXf, pXk, dec_cross_wr, dec_cross_wi, psel, 1.0f / 4096.0f);
    gemm_tc<0><<<dim3(32, 16), 128, GT_SMEM>>>(psel, pFi, nullptr, py, NHE, 128, 1024);
    gemm_tc<0><<<dim3(512, 1), 128, GT_SMEM>>>(py, dec_cross_w + 3 * 4096, dec_cross_b + 3 * 64, pa,
                                               NROW, 64, 64);
    decomp64_kernel<<<1024, 256>>>(pxd, pa, decomp_w + 6 * 4, decomp_b + 6 * 4, pxd, ptacc, 1);

    gemm_ffn<<<512, 128, FFN_SMEM>>>(pxd, dec_c1, dec_c2, py);
    decomp64_kernel<<<1024, 256>>>(pxd, py, decomp_w + 7 * 4, decomp_b + 7 * 4, pxd, ptacc, 1);

    ln_row_kernel<<<16384, 256>>>(pxd, dec_ln_g, dec_ln_b, pln);
    colmean_kernel<<<BZ * DZ, 256>>>(pln, pcm);
    final_kernel<<<128, 256>>>(pln, pcm, ptacc, ptbase, dec_trend_w, dec_proj_w, dec_proj_b, out);
}